// round 1
// baseline (speedup 1.0000x reference)
#include <cuda_runtime.h>
#include <cstdint>

#define D_MODEL 1024
#define D_FF    4096
#define SEQ     2048
#define BATCH   4
#define NTOK    (BATCH*SEQ)   /* 8192 */
#define NHEAD   16
#define DK      64

// ---------------- scratch (static device globals; no allocation) ----------------
__device__ float g_xn [(size_t)NTOK*D_MODEL];
__device__ float g_q  [(size_t)NTOK*D_MODEL];
__device__ float g_k  [(size_t)NTOK*D_MODEL];
__device__ float g_v  [(size_t)NTOK*D_MODEL];
__device__ float g_ctx[(size_t)NTOK*D_MODEL];
__device__ float g_x1 [(size_t)NTOK*D_MODEL];
__device__ float g_ffh[(size_t)NTOK*D_FF];

// ---------------- LayerNorm: one block per row of 1024 ----------------
__global__ void ln_kernel(const float* __restrict__ x,
                          const float* __restrict__ gamma,
                          const float* __restrict__ beta,
                          float* __restrict__ y)
{
    __shared__ float sbuf[64];
    const int row = blockIdx.x;
    const int tid = threadIdx.x;            // 256 threads, 4 floats each
    const int lane = tid & 31, wid = tid >> 5;

    const float4 xv = ((const float4*)(x + (size_t)row * D_MODEL))[tid];
    float s  = xv.x + xv.y + xv.z + xv.w;
    float ss = xv.x*xv.x + xv.y*xv.y + xv.z*xv.z + xv.w*xv.w;
    #pragma unroll
    for (int off = 16; off; off >>= 1) {
        s  += __shfl_xor_sync(0xffffffffu, s,  off);
        ss += __shfl_xor_sync(0xffffffffu, ss, off);
    }
    if (lane == 0) { sbuf[wid] = s; sbuf[32 + wid] = ss; }
    __syncthreads();
    if (tid == 0) {
        float t = 0.f, t2 = 0.f;
        #pragma unroll
        for (int i = 0; i < 8; i++) { t += sbuf[i]; t2 += sbuf[32 + i]; }
        sbuf[16] = t; sbuf[48] = t2;
    }
    __syncthreads();
    const float mu   = sbuf[16] * (1.0f / D_MODEL);
    const float var  = sbuf[48] * (1.0f / D_MODEL) - mu * mu;
    const float rstd = rsqrtf(var + 1e-5f);

    const float4 g4 = ((const float4*)gamma)[tid];
    const float4 b4 = ((const float4*)beta)[tid];
    float4 o;
    o.x = (xv.x - mu) * rstd * g4.x + b4.x;
    o.y = (xv.y - mu) * rstd * g4.y + b4.y;
    o.z = (xv.z - mu) * rstd * g4.z + b4.z;
    o.w = (xv.w - mu) * rstd * g4.w + b4.w;
    ((float4*)(y + (size_t)row * D_MODEL))[tid] = o;
}

// ---------------- SGEMM: C = A[M,K] @ B[K,N] + bias (+R) (relu) ----------------
// BM=BN=128, BK=16, 256 threads, 8x8 per thread. M,N,K all multiples of 128/16.
template<bool RELU, bool RESID>
__global__ __launch_bounds__(256)
void gemm_kernel(const float* __restrict__ A, const float* __restrict__ B,
                 const float* __restrict__ bias, const float* __restrict__ R,
                 float* __restrict__ C, int M, int N, int K)
{
    __shared__ float As[16 * 132];   // A stored transposed [k][m], padded
    __shared__ float Bs[16 * 128];

    const int tid = threadIdx.x;
    const int tx = tid & 15;
    const int ty = tid >> 4;
    const int m0 = blockIdx.y << 7;
    const int n0 = blockIdx.x << 7;

    const int arow = tid >> 2;            // 0..63
    const int akk  = (tid & 3) << 2;      // 0,4,8,12
    const int bkk  = tid >> 5;            // 0..7
    const int bc   = (tid & 31) << 2;     // 0..124

    float acc[8][8];
    #pragma unroll
    for (int i = 0; i < 8; i++)
        #pragma unroll
        for (int j = 0; j < 8; j++) acc[i][j] = 0.f;

    const float* Aptr0 = A + (size_t)(m0 + arow) * K + akk;
    const float* Aptr1 = Aptr0 + (size_t)64 * K;
    const float* Bptr0 = B + (size_t)bkk * N + n0 + bc;
    const float* Bptr1 = Bptr0 + (size_t)8 * N;

    for (int k0 = 0; k0 < K; k0 += 16) {
        const float4 a0 = *(const float4*)(Aptr0 + k0);
        const float4 a1 = *(const float4*)(Aptr1 + k0);
        const float4 b0 = *(const float4*)(Bptr0 + (size_t)k0 * N);
        const float4 b1 = *(const float4*)(Bptr1 + (size_t)k0 * N);
        __syncthreads();
        As[(akk + 0) * 132 + arow] = a0.x;
        As[(akk + 1) * 132 + arow] = a0.y;
        As[(akk + 2) * 132 + arow] = a0.z;
        As[(akk + 3) * 132 + arow] = a0.w;
        As[(akk + 0) * 132 + arow + 64] = a1.x;
        As[(akk + 1) * 132 + arow + 64] = a1.y;
        As[(akk + 2) * 132 + arow + 64] = a1.z;
        As[(akk + 3) * 132 + arow + 64] = a1.w;
        *(float4*)&Bs[bkk * 128 + bc]       = b0;
        *(float4*)&Bs[(bkk + 8) * 128 + bc] = b1;
        __syncthreads();
        #pragma unroll
        for (int kk = 0; kk < 16; kk++) {
            float af[8], bf[8];
            *(float4*)(af)     = *(const float4*)&As[kk * 132 + ty * 8];
            *(float4*)(af + 4) = *(const float4*)&As[kk * 132 + ty * 8 + 4];
            *(float4*)(bf)     = *(const float4*)&Bs[kk * 128 + tx * 8];
            *(float4*)(bf + 4) = *(const float4*)&Bs[kk * 128 + tx * 8 + 4];
            #pragma unroll
            for (int i = 0; i < 8; i++)
                #pragma unroll
                for (int j = 0; j < 8; j++)
                    acc[i][j] += af[i] * bf[j];
        }
    }

    float bfr[8];
    *(float4*)(bfr)     = *(const float4*)&bias[n0 + tx * 8];
    *(float4*)(bfr + 4) = *(const float4*)&bias[n0 + tx * 8 + 4];

    #pragma unroll
    for (int i = 0; i < 8; i++) {
        const size_t row = (size_t)(m0 + ty * 8 + i) * N + n0 + tx * 8;
        #pragma unroll
        for (int j = 0; j < 8; j += 4) {
            float4 r;
            r.x = acc[i][j + 0] + bfr[j + 0];
            r.y = acc[i][j + 1] + bfr[j + 1];
            r.z = acc[i][j + 2] + bfr[j + 2];
            r.w = acc[i][j + 3] + bfr[j + 3];
            if (RELU) {
                r.x = fmaxf(r.x, 0.f); r.y = fmaxf(r.y, 0.f);
                r.z = fmaxf(r.z, 0.f); r.w = fmaxf(r.w, 0.f);
            }
            if (RESID) {
                const float4 rs = *(const float4*)&R[row + j];
                r.x += rs.x; r.y += rs.y; r.z += rs.z; r.w += rs.w;
            }
            *(float4*)&C[row + j] = r;
        }
    }
}

// ---------------- Flash attention ----------------
// Q/K/V layout: [b, s, h, dk] flattened into [tok, 1024], head offset h*64.
// Block: 256 threads (8 warps), 128 query rows per block (16 rows per warp).
// Lane owns score cols / out dims {lane, lane+32}.  grid = (S/128, B*H).
#define ATTN_SMEM ((128*64 + 64*68 + 64*64 + 8*16*64) * 4)   /* 99328 B */

__global__ __launch_bounds__(256)
void attn_kernel(const float* __restrict__ Q, const float* __restrict__ K,
                 const float* __restrict__ V, float* __restrict__ O)
{
    extern __shared__ float sm[];
    float* q_s = sm;                       // [128][64]
    float* k_s = q_s + 128 * 64;           // [64][68] padded
    float* v_s = k_s + 64 * 68;            // [64][64]
    float* p_s = v_s + 64 * 64;            // [8 warps][16 r][64 c]

    const int tid  = threadIdx.x;
    const int lane = tid & 31;
    const int wid  = tid >> 5;
    const int bh = blockIdx.y;             // 0..63
    const int b  = bh >> 4;
    const int h  = bh & 15;
    const int q0 = blockIdx.x << 7;

    const size_t base = (size_t)b * SEQ * D_MODEL + (size_t)h * DK;

    // load Q tile 128x64
    #pragma unroll
    for (int t = 0; t < 8; t++) {
        const int idx = tid + t * 256;
        const int r = idx >> 4, d4 = (idx & 15) << 2;
        *(float4*)&q_s[r * 64 + d4] =
            *(const float4*)&Q[base + (size_t)(q0 + r) * D_MODEL + d4];
    }

    float m[16], l[16], o0[16], o1[16];
    #pragma unroll
    for (int r = 0; r < 16; r++) { m[r] = -1e30f; l[r] = 0.f; o0[r] = 0.f; o1[r] = 0.f; }

    float* pw = p_s + wid * 16 * 64;
    const float scale = 0.125f;            // 1/sqrt(64)

    for (int kt = 0; kt < SEQ / 64; kt++) {
        const int k0 = kt * 64;
        __syncthreads();
        #pragma unroll
        for (int t = 0; t < 4; t++) {
            const int idx = tid + t * 256;
            const int c = idx >> 4, d4 = (idx & 15) << 2;
            *(float4*)&k_s[c * 68 + d4] =
                *(const float4*)&K[base + (size_t)(k0 + c) * D_MODEL + d4];
            *(float4*)&v_s[c * 64 + d4] =
                *(const float4*)&V[base + (size_t)(k0 + c) * D_MODEL + d4];
        }
        __syncthreads();

        // scores: s[r][{lane,lane+32}]
        float s0[16], s1[16];
        #pragma unroll
        for (int r = 0; r < 16; r++) { s0[r] = 0.f; s1[r] = 0.f; }
        #pragma unroll
        for (int d4 = 0; d4 < 64; d4 += 4) {
            const float4 ka = *(const float4*)&k_s[lane * 68 + d4];
            const float4 kb = *(const float4*)&k_s[(lane + 32) * 68 + d4];
            #pragma unroll
            for (int r = 0; r < 16; r++) {
                const float4 q4 = *(const float4*)&q_s[(wid * 16 + r) * 64 + d4];
                s0[r] += q4.x*ka.x + q4.y*ka.y + q4.z*ka.z + q4.w*ka.w;
                s1[r] += q4.x*kb.x + q4.y*kb.y + q4.z*kb.z + q4.w*kb.w;
            }
        }

        // online softmax per row
        #pragma unroll
        for (int r = 0; r < 16; r++) {
            const float a = s0[r] * scale;
            const float c = s1[r] * scale;
            float mx = fmaxf(a, c);
            #pragma unroll
            for (int off = 16; off; off >>= 1)
                mx = fmaxf(mx, __shfl_xor_sync(0xffffffffu, mx, off));
            const float mnew  = fmaxf(m[r], mx);
            const float alpha = __expf(m[r] - mnew);
            const float p0 = __expf(a - mnew);
            const float p1 = __expf(c - mnew);
            m[r] = mnew;
            pw[r * 64 + lane]      = p0;
            pw[r * 64 + lane + 32] = p1;
            float ps = p0 + p1;
            #pragma unroll
            for (int off = 16; off; off >>= 1)
                ps += __shfl_xor_sync(0xffffffffu, ps, off);
            l[r]  = l[r] * alpha + ps;
            o0[r] *= alpha;
            o1[r] *= alpha;
        }
        __syncwarp();

        // O += P @ V   (dims {lane, lane+32})
        #pragma unroll
        for (int c4 = 0; c4 < 64; c4 += 4) {
            float va[4], vb[4];
            #pragma unroll
            for (int u = 0; u < 4; u++) {
                va[u] = v_s[(c4 + u) * 64 + lane];
                vb[u] = v_s[(c4 + u) * 64 + lane + 32];
            }
            #pragma unroll
            for (int r = 0; r < 16; r++) {
                const float4 p4 = *(const float4*)&pw[r * 64 + c4];
                o0[r] += p4.x*va[0] + p4.y*va[1] + p4.z*va[2] + p4.w*va[3];
                o1[r] += p4.x*vb[0] + p4.y*vb[1] + p4.z*vb[2] + p4.w*vb[3];
            }
        }
    }

    #pragma unroll
    for (int r = 0; r < 16; r++) {
        const float inv = 1.f / l[r];
        const size_t orow = base + (size_t)(q0 + wid * 16 + r) * D_MODEL;
        O[orow + lane]      = o0[r] * inv;
        O[orow + lane + 32] = o1[r] * inv;
    }
}

// ---------------- launch ----------------
extern "C" void kernel_launch(void* const* d_in, const int* in_sizes, int n_in,
                              void* d_out, int out_size)
{
    const float* x    = (const float*)d_in[0];
    const float* ln1g = (const float*)d_in[1];
    const float* ln1b = (const float*)d_in[2];
    const float* ln2g = (const float*)d_in[3];
    const float* ln2b = (const float*)d_in[4];
    const float* Wq = (const float*)d_in[5];
    const float* bq = (const float*)d_in[6];
    const float* Wk = (const float*)d_in[7];
    const float* bk = (const float*)d_in[8];
    const float* Wv = (const float*)d_in[9];
    const float* bv = (const float*)d_in[10];
    const float* Wo = (const float*)d_in[11];
    const float* bo = (const float*)d_in[12];
    const float* W1 = (const float*)d_in[13];
    const float* b1 = (const float*)d_in[14];
    const float* W2 = (const float*)d_in[15];
    const float* b2 = (const float*)d_in[16];
    float* out = (float*)d_out;

    float *xn, *q, *k, *v, *ctx, *x1, *ffh;
    cudaGetSymbolAddress((void**)&xn,  g_xn);
    cudaGetSymbolAddress((void**)&q,   g_q);
    cudaGetSymbolAddress((void**)&k,   g_k);
    cudaGetSymbolAddress((void**)&v,   g_v);
    cudaGetSymbolAddress((void**)&ctx, g_ctx);
    cudaGetSymbolAddress((void**)&x1,  g_x1);
    cudaGetSymbolAddress((void**)&ffh, g_ffh);

    cudaFuncSetAttribute(attn_kernel,
                         cudaFuncAttributeMaxDynamicSharedMemorySize, ATTN_SMEM);

    const dim3 gD(D_MODEL / 128, NTOK / 128);     // 8 x 64
    const dim3 gF(D_FF / 128,    NTOK / 128);     // 32 x 64

    // 1) xn = LN1(x)
    ln_kernel<<<NTOK, 256>>>(x, ln1g, ln1b, xn);
    // 2) q,k,v = xn @ W{q,k,v} + b
    gemm_kernel<false,false><<<gD, 256>>>(xn, Wq, bq, nullptr, q,  NTOK, D_MODEL, D_MODEL);
    gemm_kernel<false,false><<<gD, 256>>>(xn, Wk, bk, nullptr, k,  NTOK, D_MODEL, D_MODEL);
    gemm_kernel<false,false><<<gD, 256>>>(xn, Wv, bv, nullptr, v,  NTOK, D_MODEL, D_MODEL);
    // 3) ctx = attention(q,k,v)
    attn_kernel<<<dim3(SEQ / 128, BATCH * NHEAD), 256, ATTN_SMEM>>>(q, k, v, ctx);
    // 4) x1 = x + ctx @ Wo + bo
    gemm_kernel<false,true><<<gD, 256>>>(ctx, Wo, bo, x, x1, NTOK, D_MODEL, D_MODEL);
    // 5) xn = LN2(x1)
    ln_kernel<<<NTOK, 256>>>(x1, ln2g, ln2b, xn);
    // 6) ffh = relu(xn @ W1 + b1)
    gemm_kernel<true,false><<<gF, 256>>>(xn, W1, b1, nullptr, ffh, NTOK, D_FF, D_MODEL);
    // 7) out = x1 + ffh @ W2 + b2
    gemm_kernel<false,true><<<gD, 256>>>(ffh, W2, b2, x1, out, NTOK, D_MODEL, D_FF);
}

// round 2
// speedup vs baseline: 3.2169x; 3.2169x over previous
#include <cuda_runtime.h>
#include <cstdint>

#define D_MODEL 1024
#define D_FF    4096
#define SEQ     2048
#define BATCH   4
#define NTOK    (BATCH*SEQ)   /* 8192 */
#define NHEAD   16
#define DK      64

// ---------------- scratch (static device globals; no allocation) ----------------
__device__ float g_xn [(size_t)NTOK*D_MODEL];
__device__ float g_q  [(size_t)NTOK*D_MODEL];
__device__ float g_k  [(size_t)NTOK*D_MODEL];
__device__ float g_v  [(size_t)NTOK*D_MODEL];
__device__ float g_ctx[(size_t)NTOK*D_MODEL];
__device__ float g_x1 [(size_t)NTOK*D_MODEL];
__device__ float g_ffh[(size_t)NTOK*D_FF];

// ---------------- helpers ----------------
__device__ __forceinline__ uint32_t f2tf(float x) {
    uint32_t u;
    asm("cvt.rna.tf32.f32 %0, %1;" : "=r"(u) : "f"(x));
    return u;
}
__device__ __forceinline__ uint4 cvt4(float4 v) {
    uint4 r;
    r.x = f2tf(v.x); r.y = f2tf(v.y); r.z = f2tf(v.z); r.w = f2tf(v.w);
    return r;
}
// D += A(16x8) @ B(8x8), tf32 inputs, f32 accum
__device__ __forceinline__ void mma_tf32(float& d0, float& d1, float& d2, float& d3,
                                         uint32_t a0, uint32_t a1, uint32_t a2, uint32_t a3,
                                         uint32_t b0, uint32_t b1) {
    asm volatile(
        "mma.sync.aligned.m16n8k8.row.col.f32.tf32.tf32.f32 "
        "{%0,%1,%2,%3}, {%4,%5,%6,%7}, {%8,%9}, {%0,%1,%2,%3};"
        : "+f"(d0), "+f"(d1), "+f"(d2), "+f"(d3)
        : "r"(a0), "r"(a1), "r"(a2), "r"(a3), "r"(b0), "r"(b1));
}

// ---------------- LayerNorm: one block per row of 1024 ----------------
__global__ void ln_kernel(const float* __restrict__ x,
                          const float* __restrict__ gamma,
                          const float* __restrict__ beta,
                          float* __restrict__ y)
{
    __shared__ float sbuf[64];
    const int row = blockIdx.x;
    const int tid = threadIdx.x;            // 256 threads, 4 floats each
    const int lane = tid & 31, wid = tid >> 5;

    const float4 xv = ((const float4*)(x + (size_t)row * D_MODEL))[tid];
    float s  = xv.x + xv.y + xv.z + xv.w;
    float ss = xv.x*xv.x + xv.y*xv.y + xv.z*xv.z + xv.w*xv.w;
    #pragma unroll
    for (int off = 16; off; off >>= 1) {
        s  += __shfl_xor_sync(0xffffffffu, s,  off);
        ss += __shfl_xor_sync(0xffffffffu, ss, off);
    }
    if (lane == 0) { sbuf[wid] = s; sbuf[32 + wid] = ss; }
    __syncthreads();
    if (tid == 0) {
        float t = 0.f, t2 = 0.f;
        #pragma unroll
        for (int i = 0; i < 8; i++) { t += sbuf[i]; t2 += sbuf[32 + i]; }
        sbuf[16] = t; sbuf[48] = t2;
    }
    __syncthreads();
    const float mu   = sbuf[16] * (1.0f / D_MODEL);
    const float var  = sbuf[48] * (1.0f / D_MODEL) - mu * mu;
    const float rstd = rsqrtf(var + 1e-5f);

    const float4 g4 = ((const float4*)gamma)[tid];
    const float4 b4 = ((const float4*)beta)[tid];
    float4 o;
    o.x = (xv.x - mu) * rstd * g4.x + b4.x;
    o.y = (xv.y - mu) * rstd * g4.y + b4.y;
    o.z = (xv.z - mu) * rstd * g4.z + b4.z;
    o.w = (xv.w - mu) * rstd * g4.w + b4.w;
    ((float4*)(y + (size_t)row * D_MODEL))[tid] = o;
}

// ---------------- TF32 tensor-core GEMM ----------------
// C = A[M,K] @ B[K,N] + bias (+R) (relu). BM=BN=128, BK=32, 256 thr (8 warps),
// warp grid 4(m) x 2(n), warp tile 32x64. Conflict-free strides: As 36, Bs 136.
#define SA 36
#define SB 136

template<bool RELU, bool RESID>
__global__ __launch_bounds__(256)
void gemm_tc(const float* __restrict__ A, const float* __restrict__ B,
             const float* __restrict__ bias, const float* __restrict__ R,
             float* __restrict__ C, int M, int N, int K)
{
    __shared__ uint32_t As[128 * SA];   // [m][k] tf32 bits
    __shared__ uint32_t Bs[32 * SB];    // [k][n] tf32 bits

    const int tid  = threadIdx.x;
    const int lane = tid & 31;
    const int wid  = tid >> 5;
    const int wm   = wid & 3;           // warp m index (0..3)
    const int wn   = wid >> 2;          // warp n index (0..1)
    const int g    = lane >> 2;         // groupID 0..7
    const int t    = lane & 3;          // threadID in group 0..3

    const int m0 = blockIdx.y << 7;
    const int n0 = blockIdx.x << 7;

    // gmem load indices
    const int ar = tid >> 3;            // A row within pass (0..31)
    const int ak = (tid & 7) << 2;      // A k offset (0,4,..28)
    const int br = tid >> 5;            // B k-row within pass (0..7)
    const int bc = (tid & 31) << 2;     // B col (0..124)

    float acc[2][8][4];
    #pragma unroll
    for (int mi = 0; mi < 2; mi++)
        #pragma unroll
        for (int ni = 0; ni < 8; ni++)
            #pragma unroll
            for (int c = 0; c < 4; c++) acc[mi][ni][c] = 0.f;

    for (int k0 = 0; k0 < K; k0 += 32) {
        float4 av[4], bv[4];
        #pragma unroll
        for (int p = 0; p < 4; p++) {
            av[p] = *(const float4*)&A[(size_t)(m0 + ar + p * 32) * K + k0 + ak];
            bv[p] = *(const float4*)&B[(size_t)(k0 + br + p * 8) * N + n0 + bc];
        }
        __syncthreads();
        #pragma unroll
        for (int p = 0; p < 4; p++) {
            *(uint4*)&As[(ar + p * 32) * SA + ak] = cvt4(av[p]);
            *(uint4*)&Bs[(br + p * 8) * SB + bc]  = cvt4(bv[p]);
        }
        __syncthreads();

        #pragma unroll
        for (int kk = 0; kk < 4; kk++) {
            const int k8 = kk * 8;
            uint32_t af[2][4], bf[8][2];
            #pragma unroll
            for (int mi = 0; mi < 2; mi++) {
                const int row = wm * 32 + mi * 16 + g;
                af[mi][0] = As[row * SA + k8 + t];
                af[mi][1] = As[(row + 8) * SA + k8 + t];
                af[mi][2] = As[row * SA + k8 + t + 4];
                af[mi][3] = As[(row + 8) * SA + k8 + t + 4];
            }
            #pragma unroll
            for (int ni = 0; ni < 8; ni++) {
                const int col = wn * 64 + ni * 8 + g;
                bf[ni][0] = Bs[(k8 + t) * SB + col];
                bf[ni][1] = Bs[(k8 + t + 4) * SB + col];
            }
            #pragma unroll
            for (int mi = 0; mi < 2; mi++)
                #pragma unroll
                for (int ni = 0; ni < 8; ni++)
                    mma_tf32(acc[mi][ni][0], acc[mi][ni][1], acc[mi][ni][2], acc[mi][ni][3],
                             af[mi][0], af[mi][1], af[mi][2], af[mi][3],
                             bf[ni][0], bf[ni][1]);
        }
    }

    // epilogue: rows (g, g+8), cols (2t, 2t+1) per tile
    #pragma unroll
    for (int ni = 0; ni < 8; ni++) {
        const int c = n0 + wn * 64 + ni * 8 + 2 * t;
        const float2 bi = *(const float2*)&bias[c];
        #pragma unroll
        for (int mi = 0; mi < 2; mi++) {
            const int r0 = m0 + wm * 32 + mi * 16 + g;
            #pragma unroll
            for (int h = 0; h < 2; h++) {
                const int rr = r0 + h * 8;
                float vx = acc[mi][ni][2 * h]     + bi.x;
                float vy = acc[mi][ni][2 * h + 1] + bi.y;
                if (RELU) { vx = fmaxf(vx, 0.f); vy = fmaxf(vy, 0.f); }
                const size_t idx = (size_t)rr * N + c;
                if (RESID) {
                    const float2 rs = *(const float2*)&R[idx];
                    vx += rs.x; vy += rs.y;
                }
                float2 o; o.x = vx; o.y = vy;
                *(float2*)&C[idx] = o;
            }
        }
    }
}

// ---------------- Flash attention, TF32 tensor cores ----------------
// 128 q-rows/block, 8 warps x 16 rows, key tiles of 64, dk=64.
// q_s[128][68], k_s[64][68], v_s[64][72], p_s[8][16][68] (tf32 bits).
#define QS 68
#define KS 68
#define VS 72
#define PS 68
#define ATTN_SMEM ((128*QS + 64*KS + 64*VS + 8*16*PS) * 4)

__global__ __launch_bounds__(256)
void attn_tc(const float* __restrict__ Q, const float* __restrict__ K,
             const float* __restrict__ V, float* __restrict__ O)
{
    extern __shared__ uint32_t sm[];
    uint32_t* q_s = sm;
    uint32_t* k_s = q_s + 128 * QS;
    uint32_t* v_s = k_s + 64 * KS;
    uint32_t* p_s = v_s + 64 * VS;

    const int tid  = threadIdx.x;
    const int lane = tid & 31;
    const int wid  = tid >> 5;
    const int g    = lane >> 2;
    const int t    = lane & 3;

    const int bh = blockIdx.y;             // 0..63
    const int b  = bh >> 4;
    const int h  = bh & 15;
    const int q0 = blockIdx.x << 7;

    const size_t base = (size_t)b * SEQ * D_MODEL + (size_t)h * DK;

    // load Q tile 128x64, pre-scaled by 1/sqrt(dk)
    #pragma unroll
    for (int p = 0; p < 8; p++) {
        const int idx = tid + p * 256;
        const int r = idx >> 4, d4 = (idx & 15) << 2;
        float4 qv = *(const float4*)&Q[base + (size_t)(q0 + r) * D_MODEL + d4];
        qv.x *= 0.125f; qv.y *= 0.125f; qv.z *= 0.125f; qv.w *= 0.125f;
        *(uint4*)&q_s[r * QS + d4] = cvt4(qv);
    }

    float m0v = -1e30f, m1v = -1e30f, l0 = 0.f, l1 = 0.f;
    float oacc[8][4];
    #pragma unroll
    for (int ni = 0; ni < 8; ni++)
        #pragma unroll
        for (int c = 0; c < 4; c++) oacc[ni][c] = 0.f;

    uint32_t* pw = p_s + wid * 16 * PS;
    const int qrow = wid * 16;

    for (int kt = 0; kt < SEQ / 64; kt++) {
        const int k0 = kt * 64;
        __syncthreads();
        #pragma unroll
        for (int p = 0; p < 4; p++) {
            const int idx = tid + p * 256;
            const int c = idx >> 4, d4 = (idx & 15) << 2;
            *(uint4*)&k_s[c * KS + d4] =
                cvt4(*(const float4*)&K[base + (size_t)(k0 + c) * D_MODEL + d4]);
            *(uint4*)&v_s[c * VS + d4] =
                cvt4(*(const float4*)&V[base + (size_t)(k0 + c) * D_MODEL + d4]);
        }
        __syncthreads();

        // S = Q @ K^T  (rows g/g+8, key cols ni*8 + 2t,2t+1)
        float sacc[8][4];
        #pragma unroll
        for (int ni = 0; ni < 8; ni++)
            #pragma unroll
            for (int c = 0; c < 4; c++) sacc[ni][c] = 0.f;

        #pragma unroll
        for (int d8 = 0; d8 < 8; d8++) {
            const int kb = d8 * 8;
            uint32_t a0 = q_s[(qrow + g) * QS + kb + t];
            uint32_t a1 = q_s[(qrow + g + 8) * QS + kb + t];
            uint32_t a2 = q_s[(qrow + g) * QS + kb + t + 4];
            uint32_t a3 = q_s[(qrow + g + 8) * QS + kb + t + 4];
            #pragma unroll
            for (int ni = 0; ni < 8; ni++) {
                uint32_t b0 = k_s[(ni * 8 + g) * KS + kb + t];
                uint32_t b1 = k_s[(ni * 8 + g) * KS + kb + t + 4];
                mma_tf32(sacc[ni][0], sacc[ni][1], sacc[ni][2], sacc[ni][3],
                         a0, a1, a2, a3, b0, b1);
            }
        }

        // online softmax (rows g and g+8; quad lanes hold a row's 64 keys)
        float mx0 = -1e30f, mx1 = -1e30f;
        #pragma unroll
        for (int ni = 0; ni < 8; ni++) {
            mx0 = fmaxf(mx0, fmaxf(sacc[ni][0], sacc[ni][1]));
            mx1 = fmaxf(mx1, fmaxf(sacc[ni][2], sacc[ni][3]));
        }
        mx0 = fmaxf(mx0, __shfl_xor_sync(0xffffffffu, mx0, 1));
        mx0 = fmaxf(mx0, __shfl_xor_sync(0xffffffffu, mx0, 2));
        mx1 = fmaxf(mx1, __shfl_xor_sync(0xffffffffu, mx1, 1));
        mx1 = fmaxf(mx1, __shfl_xor_sync(0xffffffffu, mx1, 2));

        const float mn0 = fmaxf(m0v, mx0);
        const float mn1 = fmaxf(m1v, mx1);
        const float al0 = __expf(m0v - mn0);
        const float al1 = __expf(m1v - mn1);
        m0v = mn0; m1v = mn1;

        float sum0 = 0.f, sum1 = 0.f;
        #pragma unroll
        for (int ni = 0; ni < 8; ni++) {
            const float p00 = __expf(sacc[ni][0] - mn0);
            const float p01 = __expf(sacc[ni][1] - mn0);
            const float p10 = __expf(sacc[ni][2] - mn1);
            const float p11 = __expf(sacc[ni][3] - mn1);
            sum0 += p00 + p01;
            sum1 += p10 + p11;
            uint2 u0; u0.x = f2tf(p00); u0.y = f2tf(p01);
            uint2 u1; u1.x = f2tf(p10); u1.y = f2tf(p11);
            *(uint2*)&pw[g * PS + ni * 8 + 2 * t]       = u0;
            *(uint2*)&pw[(g + 8) * PS + ni * 8 + 2 * t] = u1;
        }
        sum0 += __shfl_xor_sync(0xffffffffu, sum0, 1);
        sum0 += __shfl_xor_sync(0xffffffffu, sum0, 2);
        sum1 += __shfl_xor_sync(0xffffffffu, sum1, 1);
        sum1 += __shfl_xor_sync(0xffffffffu, sum1, 2);
        l0 = l0 * al0 + sum0;
        l1 = l1 * al1 + sum1;

        #pragma unroll
        for (int ni = 0; ni < 8; ni++) {
            oacc[ni][0] *= al0; oacc[ni][1] *= al0;
            oacc[ni][2] *= al1; oacc[ni][3] *= al1;
        }
        __syncwarp();

        // O += P @ V
        #pragma unroll
        for (int kk = 0; kk < 8; kk++) {
            const int kb = kk * 8;
            uint32_t a0 = pw[g * PS + kb + t];
            uint32_t a1 = pw[(g + 8) * PS + kb + t];
            uint32_t a2 = pw[g * PS + kb + t + 4];
            uint32_t a3 = pw[(g + 8) * PS + kb + t + 4];
            #pragma unroll
            for (int ni = 0; ni < 8; ni++) {
                uint32_t b0 = v_s[(kb + t) * VS + ni * 8 + g];
                uint32_t b1 = v_s[(kb + t + 4) * VS + ni * 8 + g];
                mma_tf32(oacc[ni][0], oacc[ni][1], oacc[ni][2], oacc[ni][3],
                         a0, a1, a2, a3, b0, b1);
            }
        }
        __syncwarp();
    }

    const float inv0 = 1.f / l0;
    const float inv1 = 1.f / l1;
    const size_t row0 = base + (size_t)(q0 + qrow + g) * D_MODEL;
    const size_t row1 = base + (size_t)(q0 + qrow + g + 8) * D_MODEL;
    #pragma unroll
    for (int ni = 0; ni < 8; ni++) {
        const int c = ni * 8 + 2 * t;
        float2 o0; o0.x = oacc[ni][0] * inv0; o0.y = oacc[ni][1] * inv0;
        float2 o1; o1.x = oacc[ni][2] * inv1; o1.y = oacc[ni][3] * inv1;
        *(float2*)&O[row0 + c] = o0;
        *(float2*)&O[row1 + c] = o1;
    }
}

// ---------------- launch ----------------
extern "C" void kernel_launch(void* const* d_in, const int* in_sizes, int n_in,
                              void* d_out, int out_size)
{
    const float* x    = (const float*)d_in[0];
    const float* ln1g = (const float*)d_in[1];
    const float* ln1b = (const float*)d_in[2];
    const float* ln2g = (const float*)d_in[3];
    const float* ln2b = (const float*)d_in[4];
    const float* Wq = (const float*)d_in[5];
    const float* bq = (const float*)d_in[6];
    const float* Wk = (const float*)d_in[7];
    const float* bk = (const float*)d_in[8];
    const float* Wv = (const float*)d_in[9];
    const float* bv = (const float*)d_in[10];
    const float* Wo = (const float*)d_in[11];
    const float* bo = (const float*)d_in[12];
    const float* W1 = (const float*)d_in[13];
    const float* b1 = (const float*)d_in[14];
    const float* W2 = (const float*)d_in[15];
    const float* b2 = (const float*)d_in[16];
    float* out = (float*)d_out;

    float *xn, *q, *k, *v, *ctx, *x1, *ffh;
    cudaGetSymbolAddress((void**)&xn,  g_xn);
    cudaGetSymbolAddress((void**)&q,   g_q);
    cudaGetSymbolAddress((void**)&k,   g_k);
    cudaGetSymbolAddress((void**)&v,   g_v);
    cudaGetSymbolAddress((void**)&ctx, g_ctx);
    cudaGetSymbolAddress((void**)&x1,  g_x1);
    cudaGetSymbolAddress((void**)&ffh, g_ffh);

    cudaFuncSetAttribute(attn_tc,
                         cudaFuncAttributeMaxDynamicSharedMemorySize, ATTN_SMEM);

    const dim3 gD(D_MODEL / 128, NTOK / 128);     // 8 x 64
    const dim3 gF(D_FF / 128,    NTOK / 128);     // 32 x 64

    // 1) xn = LN1(x)
    ln_kernel<<<NTOK, 256>>>(x, ln1g, ln1b, xn);
    // 2) q,k,v = xn @ W{q,k,v} + b
    gemm_tc<false,false><<<gD, 256>>>(xn, Wq, bq, nullptr, q,  NTOK, D_MODEL, D_MODEL);
    gemm_tc<false,false><<<gD, 256>>>(xn, Wk, bk, nullptr, k,  NTOK, D_MODEL, D_MODEL);
    gemm_tc<false,false><<<gD, 256>>>(xn, Wv, bv, nullptr, v,  NTOK, D_MODEL, D_MODEL);
    // 3) ctx = attention(q,k,v)
    attn_tc<<<dim3(SEQ / 128, BATCH * NHEAD), 256, ATTN_SMEM>>>(q, k, v, ctx);
    // 4) x1 = x + ctx @ Wo + bo
    gemm_tc<false,true><<<gD, 256>>>(ctx, Wo, bo, x, x1, NTOK, D_MODEL, D_MODEL);
    // 5) xn = LN2(x1)
    ln_kernel<<<NTOK, 256>>>(x1, ln2g, ln2b, xn);
    // 6) ffh = relu(xn @ W1 + b1)
    gemm_tc<true,false><<<gF, 256>>>(xn, W1, b1, nullptr, ffh, NTOK, D_FF, D_MODEL);
    // 7) out = x1 + ffh @ W2 + b2
    gemm_tc<false,true><<<gD, 256>>>(ffh, W2, b2, x1, out, NTOK, D_MODEL, D_FF);
}

// round 4
// speedup vs baseline: 5.1973x; 1.6156x over previous
#include <cuda_runtime.h>
#include <cuda_fp16.h>
#include <cstdint>

#define D_MODEL 1024
#define D_FF    4096
#define SEQ     2048
#define BATCH   4
#define NTOK    (BATCH*SEQ)   /* 8192 */
#define NHEAD   16
#define DK      64

// ---------------- scratch (static device globals; no allocation) ----------------
__device__ __half g_xnh [(size_t)NTOK*D_MODEL];
__device__ float  g_qkv [(size_t)NTOK*3*D_MODEL];
__device__ __half g_ctxh[(size_t)NTOK*D_MODEL];
__device__ float  g_x1  [(size_t)NTOK*D_MODEL];
__device__ __half g_ffh [(size_t)NTOK*D_FF];
__device__ __half g_wqkvt[(size_t)3*D_MODEL*D_MODEL];
__device__ __half g_wot  [(size_t)D_MODEL*D_MODEL];
__device__ __half g_w1t  [(size_t)D_FF*D_MODEL];
__device__ __half g_w2t  [(size_t)D_MODEL*D_FF];
__device__ float  g_bqkv [3*D_MODEL];

// ---------------- PTX helpers ----------------
__device__ __forceinline__ uint32_t f2tf(float x) {
    uint32_t u;
    asm("cvt.rna.tf32.f32 %0, %1;" : "=r"(u) : "f"(x));
    return u;
}
__device__ __forceinline__ uint4 cvt4(float4 v) {
    uint4 r;
    r.x = f2tf(v.x); r.y = f2tf(v.y); r.z = f2tf(v.z); r.w = f2tf(v.w);
    return r;
}
__device__ __forceinline__ uint32_t smem_u32(const void* p) {
    uint32_t a;
    asm("{ .reg .u64 t; cvta.to.shared.u64 t, %1; cvt.u32.u64 %0, t; }"
        : "=r"(a) : "l"(p));
    return a;
}

#define LDSM4(r0, r1, r2, r3, a) \
    asm volatile("ldmatrix.sync.aligned.m8n8.x4.shared.b16 {%0,%1,%2,%3}, [%4];" \
        : "=r"(r0), "=r"(r1), "=r"(r2), "=r"(r3) : "r"(a))

#define CP16(dst, src) \
    asm volatile("cp.async.cg.shared.global [%0], [%1], 16;" :: "r"(dst), "l"(src))
#define CP_COMMIT() asm volatile("cp.async.commit_group;" ::: "memory")
#define CP_WAIT1()  asm volatile("cp.async.wait_group 1;" ::: "memory")

// fp16 MMA, fp32 accum: D(16x8) += A(16x16) @ B(16x8)
__device__ __forceinline__ void mma16(float* d, const uint32_t* a, const uint32_t* b) {
    asm volatile(
        "mma.sync.aligned.m16n8k16.row.col.f32.f16.f16.f32 "
        "{%0,%1,%2,%3}, {%4,%5,%6,%7}, {%8,%9}, {%0,%1,%2,%3};"
        : "+f"(d[0]), "+f"(d[1]), "+f"(d[2]), "+f"(d[3])
        : "r"(a[0]), "r"(a[1]), "r"(a[2]), "r"(a[3]), "r"(b[0]), "r"(b[1]));
}

// ---------------- LayerNorm: f32 in, fp16 out ----------------
__global__ void ln_kernel(const float* __restrict__ x,
                          const float* __restrict__ gamma,
                          const float* __restrict__ beta,
                          __half* __restrict__ y)
{
    __shared__ float sbuf[64];
    const int row = blockIdx.x;
    const int tid = threadIdx.x;
    const int lane = tid & 31, wid = tid >> 5;

    const float4 xv = ((const float4*)(x + (size_t)row * D_MODEL))[tid];
    float s  = xv.x + xv.y + xv.z + xv.w;
    float ss = xv.x*xv.x + xv.y*xv.y + xv.z*xv.z + xv.w*xv.w;
    #pragma unroll
    for (int off = 16; off; off >>= 1) {
        s  += __shfl_xor_sync(0xffffffffu, s,  off);
        ss += __shfl_xor_sync(0xffffffffu, ss, off);
    }
    if (lane == 0) { sbuf[wid] = s; sbuf[32 + wid] = ss; }
    __syncthreads();
    if (tid == 0) {
        float t = 0.f, t2 = 0.f;
        #pragma unroll
        for (int i = 0; i < 8; i++) { t += sbuf[i]; t2 += sbuf[32 + i]; }
        sbuf[16] = t; sbuf[48] = t2;
    }
    __syncthreads();
    const float mu   = sbuf[16] * (1.0f / D_MODEL);
    const float var  = sbuf[48] * (1.0f / D_MODEL) - mu * mu;
    const float rstd = rsqrtf(var + 1e-5f);

    const float4 g4 = ((const float4*)gamma)[tid];
    const float4 b4 = ((const float4*)beta)[tid];
    const float ox = (xv.x - mu) * rstd * g4.x + b4.x;
    const float oy = (xv.y - mu) * rstd * g4.y + b4.y;
    const float oz = (xv.z - mu) * rstd * g4.z + b4.z;
    const float ow = (xv.w - mu) * rstd * g4.w + b4.w;
    __half2 h0 = __floats2half2_rn(ox, oy);
    __half2 h1 = __floats2half2_rn(oz, ow);
    uint2 o;
    o.x = *(uint32_t*)&h0; o.y = *(uint32_t*)&h1;
    *(uint2*)(y + (size_t)row * D_MODEL + tid * 4) = o;
}

// ---------------- weight transpose: f32 in[K,N] -> fp16 out[N,K] ----------------
__global__ void transpose_h(const float* __restrict__ in, __half* __restrict__ out,
                            int K, int N)
{
    __shared__ float s[32][33];
    const int tx = threadIdx.x, ty = threadIdx.y;     // 32 x 8
    const int n0 = blockIdx.x * 32, k0 = blockIdx.y * 32;
    #pragma unroll
    for (int i = 0; i < 4; i++)
        s[ty + 8 * i][tx] = in[(size_t)(k0 + ty + 8 * i) * N + n0 + tx];
    __syncthreads();
    #pragma unroll
    for (int i = 0; i < 4; i++)
        out[(size_t)(n0 + ty + 8 * i) * K + k0 + tx] = __float2half_rn(s[tx][ty + 8 * i]);
}

__global__ void concat_bias_kernel(const float* __restrict__ bq, const float* __restrict__ bk,
                                   const float* __restrict__ bv, float* __restrict__ o)
{
    const int i = threadIdx.x + blockIdx.x * 1024;
    const float* src = (blockIdx.x == 0) ? bq : (blockIdx.x == 1) ? bk : bv;
    o[i] = src[threadIdx.x];
}

// ---------------- fp16 tensor-core GEMM ----------------
// C[M,N] = Ah[M,K](f16) @ Bh[N,K](f16)^T + bias (+relu) (+R).
// CTA tile 128x256, 8 warps (2m x 4n), warp tile 64x64, k-stage 32, 3-stage cp.async.
// smem per stage: A 128x32 f16 (8KB, 64B rows) + B 256x32 f16 (16KB). chunk swizzle:
// phys16B = chunk ^ ((row>>1)&3)  -> conflict-free STS + ldmatrix.
#define STG_BYTES 24576
#define GSM_TOTAL (3 * STG_BYTES)     /* 73728 */

template<bool RELU, bool RESID, bool HOUT>
__global__ __launch_bounds__(256, 1)
void gemm_h(const __half* __restrict__ Ah, const __half* __restrict__ Bh,
            const float* __restrict__ bias, const float* __restrict__ R,
            float* __restrict__ Cf, __half* __restrict__ Ch, int M, int N, int K)
{
    extern __shared__ char smem[];
    const uint32_t sb = smem_u32(smem);
    const int tid  = threadIdx.x;
    const int lane = tid & 31;
    const int wid  = tid >> 5;
    const int wm   = wid & 1;
    const int wn   = wid >> 1;

    const int m0 = blockIdx.y << 7;
    const int n0 = blockIdx.x << 8;

    // ---- cp.async geometry ----
    const int lr = tid >> 1;                 // 0..127
    const int t1 = tid & 1;
    const __half* Asrc  = Ah + (size_t)(m0 + lr) * K + t1 * 16;
    const __half* Bsrc0 = Bh + (size_t)(n0 + lr) * K + t1 * 16;
    const __half* Bsrc1 = Bsrc0 + (size_t)128 * K;
    const int swr = (lr >> 1) & 3;
    uint32_t aoff[2], boff[2];
    #pragma unroll
    for (int j = 0; j < 2; j++) {
        aoff[j] = lr * 64 + (((t1 * 2 + j) ^ swr) << 4);
        boff[j] = aoff[j];                   // same formula; row+128 has same swizzle
    }

    // ---- ldmatrix addresses (byte offsets within stage) ----
    uint32_t aAddr[4][2], bAddr[4][2];
    {
        const int rlA = lane & 15, clA = lane >> 4;
        #pragma unroll
        for (int mi = 0; mi < 4; mi++) {
            const int row = wm * 64 + mi * 16 + rlA;
            const int sw = (row >> 1) & 3;
            aAddr[mi][0] = row * 64 + (((0 + clA) ^ sw) << 4);
            aAddr[mi][1] = row * 64 + (((2 + clA) ^ sw) << 4);
        }
        const int rlB = (lane & 7) + ((lane >> 4) << 3);
        const int clB = (lane >> 3) & 1;
        #pragma unroll
        for (int p = 0; p < 4; p++) {
            const int row = wn * 64 + p * 16 + rlB;
            const int sw = (row >> 1) & 3;
            bAddr[p][0] = 8192 + row * 64 + (((0 + clB) ^ sw) << 4);
            bAddr[p][1] = 8192 + row * 64 + (((2 + clB) ^ sw) << 4);
        }
    }

    float acc[4][8][4];
    #pragma unroll
    for (int mi = 0; mi < 4; mi++)
        #pragma unroll
        for (int ni = 0; ni < 8; ni++)
            #pragma unroll
            for (int c = 0; c < 4; c++) acc[mi][ni][c] = 0.f;

    const int T = K >> 5;

    // ---- issue helper (stage s into buffer buf) ----
    #define ISSUE_STAGE(s, buf) do { \
        const uint32_t ab = sb + (buf) * STG_BYTES; \
        const uint32_t bb = ab + 8192; \
        const __half* as_ = Asrc  + (s) * 32; \
        const __half* b0_ = Bsrc0 + (s) * 32; \
        const __half* b1_ = Bsrc1 + (s) * 32; \
        CP16(ab + aoff[0], as_);        CP16(ab + aoff[1], as_ + 8); \
        CP16(bb + boff[0], b0_);        CP16(bb + boff[1], b0_ + 8); \
        CP16(bb + boff[0] + 8192, b1_); CP16(bb + boff[1] + 8192, b1_ + 8); \
    } while (0)

    ISSUE_STAGE(0, 0); CP_COMMIT();
    if (T > 1) ISSUE_STAGE(1, 1);
    CP_COMMIT();

    int cur = 0;
    for (int kt = 0; kt < T; kt++) {
        CP_WAIT1();
        __syncthreads();
        {
            int nb = cur + 2; if (nb >= 3) nb -= 3;
            if (kt + 2 < T) ISSUE_STAGE(kt + 2, nb);
            CP_COMMIT();
        }
        const uint32_t sA = sb + cur * STG_BYTES;
        #pragma unroll
        for (int s = 0; s < 2; s++) {
            uint32_t af[4][4];
            #pragma unroll
            for (int mi = 0; mi < 4; mi++)
                LDSM4(af[mi][0], af[mi][1], af[mi][2], af[mi][3], sA + aAddr[mi][s]);
            uint32_t bf[8][2];
            #pragma unroll
            for (int p = 0; p < 4; p++)
                LDSM4(bf[2*p][0], bf[2*p][1], bf[2*p+1][0], bf[2*p+1][1], sA + bAddr[p][s]);
            #pragma unroll
            for (int mi = 0; mi < 4; mi++)
                #pragma unroll
                for (int ni = 0; ni < 8; ni++)
                    mma16(acc[mi][ni], af[mi], bf[ni]);
        }
        cur = (cur == 2) ? 0 : cur + 1;
    }
    #undef ISSUE_STAGE

    // ---- epilogue ----
    const int g  = lane >> 2;
    const int t2 = lane & 3;
    #pragma unroll
    for (int ni = 0; ni < 8; ni++) {
        const int c = n0 + wn * 64 + ni * 8 + 2 * t2;
        const float2 bi = *(const float2*)&bias[c];
        #pragma unroll
        for (int mi = 0; mi < 4; mi++) {
            const int r0 = m0 + wm * 64 + mi * 16 + g;
            #pragma unroll
            for (int h = 0; h < 2; h++) {
                const int rr = r0 + h * 8;
                float vx = acc[mi][ni][2 * h]     + bi.x;
                float vy = acc[mi][ni][2 * h + 1] + bi.y;
                if (RELU) { vx = fmaxf(vx, 0.f); vy = fmaxf(vy, 0.f); }
                const size_t idx = (size_t)rr * N + c;
                if (RESID) {
                    const float2 rs = *(const float2*)&R[idx];
                    vx += rs.x; vy += rs.y;
                }
                if (HOUT) {
                    __half2 hv = __floats2half2_rn(vx, vy);
                    *(uint32_t*)&Ch[idx] = *(uint32_t*)&hv;
                } else {
                    float2 o; o.x = vx; o.y = vy;
                    *(float2*)&Cf[idx] = o;
                }
            }
        }
    }
}

// ---------------- Flash attention, TF32 mma.sync (round-2 proven), fp16 out ----------------
#define QS 68
#define KS 68
#define VS 72
#define PS 68
#define ATTN_SMEM ((128*QS + 64*KS + 64*VS + 8*16*PS) * 4)

__device__ __forceinline__ void mma_tf32(float& d0, float& d1, float& d2, float& d3,
                                         uint32_t a0, uint32_t a1, uint32_t a2, uint32_t a3,
                                         uint32_t b0, uint32_t b1) {
    asm volatile(
        "mma.sync.aligned.m16n8k8.row.col.f32.tf32.tf32.f32 "
        "{%0,%1,%2,%3}, {%4,%5,%6,%7}, {%8,%9}, {%0,%1,%2,%3};"
        : "+f"(d0), "+f"(d1), "+f"(d2), "+f"(d3)
        : "r"(a0), "r"(a1), "r"(a2), "r"(a3), "r"(b0), "r"(b1));
}

__global__ __launch_bounds__(256)
void attn_tc(const float* __restrict__ Q, const float* __restrict__ K,
             const float* __restrict__ V, __half* __restrict__ O, int ld)
{
    extern __shared__ uint32_t sm[];
    uint32_t* q_s = sm;
    uint32_t* k_s = q_s + 128 * QS;
    uint32_t* v_s = k_s + 64 * KS;
    uint32_t* p_s = v_s + 64 * VS;

    const int tid  = threadIdx.x;
    const int lane = tid & 31;
    const int wid  = tid >> 5;
    const int g    = lane >> 2;
    const int t    = lane & 3;

    const int bh = blockIdx.y;
    const int b  = bh >> 4;
    const int h  = bh & 15;
    const int q0 = blockIdx.x << 7;

    const size_t base  = (size_t)b * SEQ * ld + (size_t)h * DK;
    const size_t obase = (size_t)b * SEQ * D_MODEL + (size_t)h * DK;

    #pragma unroll
    for (int p = 0; p < 8; p++) {
        const int idx = tid + p * 256;
        const int r = idx >> 4, d4 = (idx & 15) << 2;
        float4 qv = *(const float4*)&Q[base + (size_t)(q0 + r) * ld + d4];
        qv.x *= 0.125f; qv.y *= 0.125f; qv.z *= 0.125f; qv.w *= 0.125f;
        *(uint4*)&q_s[r * QS + d4] = cvt4(qv);
    }

    float m0v = -1e30f, m1v = -1e30f, l0 = 0.f, l1 = 0.f;
    float oacc[8][4];
    #pragma unroll
    for (int ni = 0; ni < 8; ni++)
        #pragma unroll
        for (int c = 0; c < 4; c++) oacc[ni][c] = 0.f;

    uint32_t* pw = p_s + wid * 16 * PS;
    const int qrow = wid * 16;

    for (int kt = 0; kt < SEQ / 64; kt++) {
        const int k0 = kt * 64;
        __syncthreads();
        #pragma unroll
        for (int p = 0; p < 4; p++) {
            const int idx = tid + p * 256;
            const int c = idx >> 4, d4 = (idx & 15) << 2;
            *(uint4*)&k_s[c * KS + d4] =
                cvt4(*(const float4*)&K[base + (size_t)(k0 + c) * ld + d4]);
            *(uint4*)&v_s[c * VS + d4] =
                cvt4(*(const float4*)&V[base + (size_t)(k0 + c) * ld + d4]);
        }
        __syncthreads();

        float sacc[8][4];
        #pragma unroll
        for (int ni = 0; ni < 8; ni++)
            #pragma unroll
            for (int c = 0; c < 4; c++) sacc[ni][c] = 0.f;

        #pragma unroll
        for (int d8 = 0; d8 < 8; d8++) {
            const int kb = d8 * 8;
            uint32_t a0 = q_s[(qrow + g) * QS + kb + t];
            uint32_t a1 = q_s[(qrow + g + 8) * QS + kb + t];
            uint32_t a2 = q_s[(qrow + g) * QS + kb + t + 4];
            uint32_t a3 = q_s[(qrow + g + 8) * QS + kb + t + 4];
            #pragma unroll
            for (int ni = 0; ni < 8; ni++) {
                uint32_t b0 = k_s[(ni * 8 + g) * KS + kb + t];
                uint32_t b1 = k_s[(ni * 8 + g) * KS + kb + t + 4];
                mma_tf32(sacc[ni][0], sacc[ni][1], sacc[ni][2], sacc[ni][3],
                         a0, a1, a2, a3, b0, b1);
            }
        }

        float mx0 = -1e30f, mx1 = -1e30f;
        #pragma unroll
        for (int ni = 0; ni < 8; ni++) {
            mx0 = fmaxf(mx0, fmaxf(sacc[ni][0], sacc[ni][1]));
            mx1 = fmaxf(mx1, fmaxf(sacc[ni][2], sacc[ni][3]));
        }
        mx0 = fmaxf(mx0, __shfl_xor_sync(0xffffffffu, mx0, 1));
        mx0 = fmaxf(mx0, __shfl_xor_sync(0xffffffffu, mx0, 2));
        mx1 = fmaxf(mx1, __shfl_xor_sync(0xffffffffu, mx1, 1));
        mx1 = fmaxf(mx1, __shfl_xor_sync(0xffffffffu, mx1, 2));

        const float mn0 = fmaxf(m0v, mx0);
        const float mn1 = fmaxf(m1v, mx1);
        const float al0 = __expf(m0v - mn0);
        const float al1 = __expf(m1v - mn1);
        m0v = mn0; m1v = mn1;

        float sum0 = 0.f, sum1 = 0.f;
        #pragma unroll
        for (int ni = 0; ni < 8; ni++) {
            const float p00 = __expf(sacc[ni][0] - mn0);
            const float p01 = __expf(sacc[ni][1] - mn0);
            const float p10 = __expf(sacc[ni][2] - mn1);
            const float p11 = __expf(sacc[ni][3] - mn1);
            sum0 += p00 + p01;
            sum1 += p10 + p11;
            uint2 u0; u0.x = f2tf(p00); u0.y = f2tf(p01);
            uint2 u1; u1.x = f2tf(p10); u1.y = f2tf(p11);
            *(uint2*)&pw[g * PS + ni * 8 + 2 * t]       = u0;
            *(uint2*)&pw[(g + 8) * PS + ni * 8 + 2 * t] = u1;
        }
        sum0 += __shfl_xor_sync(0xffffffffu, sum0, 1);
        sum0 += __shfl_xor_sync(0xffffffffu, sum0, 2);
        sum1 += __shfl_xor_sync(0xffffffffu, sum1, 1);
        sum1 += __shfl_xor_sync(0xffffffffu, sum1, 2);
        l0 = l0 * al0 + sum0;
        l1 = l1 * al1 + sum1;

        #pragma unroll
        for (int ni = 0; ni < 8; ni++) {
            oacc[ni][0] *= al0; oacc[ni][1] *= al0;
            oacc[ni][2] *= al1; oacc[ni][3] *= al1;
        }
        __syncwarp();

        #pragma unroll
        for (int kk = 0; kk < 8; kk++) {
            const int kb = kk * 8;
            uint32_t a0 = pw[g * PS + kb + t];
            uint32_t a1 = pw[(g + 8) * PS + kb + t];
            uint32_t a2 = pw[g * PS + kb + t + 4];
            uint32_t a3 = pw[(g + 8) * PS + kb + t + 4];
            #pragma unroll
            for (int ni = 0; ni < 8; ni++) {
                uint32_t b0 = v_s[(kb + t) * VS + ni * 8 + g];
                uint32_t b1 = v_s[(kb + t + 4) * VS + ni * 8 + g];
                mma_tf32(oacc[ni][0], oacc[ni][1], oacc[ni][2], oacc[ni][3],
                         a0, a1, a2, a3, b0, b1);
            }
        }
        __syncwarp();
    }

    const float inv0 = 1.f / l0;
    const float inv1 = 1.f / l1;
    const size_t row0 = obase + (size_t)(q0 + qrow + g) * D_MODEL;
    const size_t row1 = obase + (size_t)(q0 + qrow + g + 8) * D_MODEL;
    #pragma unroll
    for (int ni = 0; ni < 8; ni++) {
        const int c = ni * 8 + 2 * t;
        __half2 h0 = __floats2half2_rn(oacc[ni][0] * inv0, oacc[ni][1] * inv0);
        __half2 h1 = __floats2half2_rn(oacc[ni][2] * inv1, oacc[ni][3] * inv1);
        *(uint32_t*)&O[row0 + c] = *(uint32_t*)&h0;
        *(uint32_t*)&O[row1 + c] = *(uint32_t*)&h1;
    }
}

// ---------------- launch ----------------
extern "C" void kernel_launch(void* const* d_in, const int* in_sizes, int n_in,
                              void* d_out, int out_size)
{
    const float* x    = (const float*)d_in[0];
    const float* ln1g = (const float*)d_in[1];
    const float* ln1b = (const float*)d_in[2];
    const float* ln2g = (const float*)d_in[3];
    const float* ln2b = (const float*)d_in[4];
    const float* Wq = (const float*)d_in[5];
    const float* bq = (const float*)d_in[6];
    const float* Wk = (const float*)d_in[7];
    const float* bk = (const float*)d_in[8];
    const float* Wv = (const float*)d_in[9];
    const float* bv = (const float*)d_in[10];
    const float* Wo = (const float*)d_in[11];
    const float* bo = (const float*)d_in[12];
    const float* W1 = (const float*)d_in[13];
    const float* b1 = (const float*)d_in[14];
    const float* W2 = (const float*)d_in[15];
    const float* b2 = (const float*)d_in[16];
    float* out = (float*)d_out;

    __half *xnh, *ctxh, *ffh, *wqkvt, *wot, *w1t, *w2t;
    float *qkv, *x1, *bqkv;
    cudaGetSymbolAddress((void**)&xnh,   g_xnh);
    cudaGetSymbolAddress((void**)&qkv,   g_qkv);
    cudaGetSymbolAddress((void**)&ctxh,  g_ctxh);
    cudaGetSymbolAddress((void**)&x1,    g_x1);
    cudaGetSymbolAddress((void**)&ffh,   g_ffh);
    cudaGetSymbolAddress((void**)&wqkvt, g_wqkvt);
    cudaGetSymbolAddress((void**)&wot,   g_wot);
    cudaGetSymbolAddress((void**)&w1t,   g_w1t);
    cudaGetSymbolAddress((void**)&w2t,   g_w2t);
    cudaGetSymbolAddress((void**)&bqkv,  g_bqkv);

    cudaFuncSetAttribute(attn_tc, cudaFuncAttributeMaxDynamicSharedMemorySize, ATTN_SMEM);
    cudaFuncSetAttribute(gemm_h<false,false,false>, cudaFuncAttributeMaxDynamicSharedMemorySize, GSM_TOTAL);
    cudaFuncSetAttribute(gemm_h<false,true,false>,  cudaFuncAttributeMaxDynamicSharedMemorySize, GSM_TOTAL);
    cudaFuncSetAttribute(gemm_h<true,false,true>,   cudaFuncAttributeMaxDynamicSharedMemorySize, GSM_TOTAL);

    const dim3 tb(32, 8);

    // weight transposes (f32 W[K,N] -> f16 Wt[N,K]) + bias concat
    transpose_h<<<dim3(32, 32), tb>>>(Wq, wqkvt,                             D_MODEL, D_MODEL);
    transpose_h<<<dim3(32, 32), tb>>>(Wk, wqkvt + (size_t)D_MODEL*D_MODEL,   D_MODEL, D_MODEL);
    transpose_h<<<dim3(32, 32), tb>>>(Wv, wqkvt + (size_t)2*D_MODEL*D_MODEL, D_MODEL, D_MODEL);
    transpose_h<<<dim3(32, 32), tb>>>(Wo, wot, D_MODEL, D_MODEL);
    transpose_h<<<dim3(128, 32), tb>>>(W1, w1t, D_MODEL, D_FF);
    transpose_h<<<dim3(32, 128), tb>>>(W2, w2t, D_FF, D_MODEL);
    concat_bias_kernel<<<3, 1024>>>(bq, bk, bv, bqkv);

    // 1) xn = LN1(x)  (fp16 out)
    ln_kernel<<<NTOK, 256>>>(x, ln1g, ln1b, xnh);
    // 2) qkv = xn @ [Wq|Wk|Wv] + [bq|bk|bv]   (fused, N=3072, f32 out)
    gemm_h<false,false,false><<<dim3(3*D_MODEL/256, NTOK/128), 256, GSM_TOTAL>>>(
        xnh, wqkvt, bqkv, nullptr, qkv, nullptr, NTOK, 3*D_MODEL, D_MODEL);
    // 3) ctx = attention(q,k,v)  (fp16 out)
    attn_tc<<<dim3(SEQ/128, BATCH*NHEAD), 256, ATTN_SMEM>>>(
        qkv, qkv + D_MODEL, qkv + 2*D_MODEL, ctxh, 3*D_MODEL);
    // 4) x1 = x + ctx @ Wo + bo  (f32 out)
    gemm_h<false,true,false><<<dim3(D_MODEL/256, NTOK/128), 256, GSM_TOTAL>>>(
        ctxh, wot, bo, x, x1, nullptr, NTOK, D_MODEL, D_MODEL);
    // 5) xn = LN2(x1)  (fp16 out)
    ln_kernel<<<NTOK, 256>>>(x1, ln2g, ln2b, xnh);
    // 6) ffh = relu(xn @ W1 + b1)  (fp16 out)
    gemm_h<true,false,true><<<dim3(D_FF/256, NTOK/128), 256, GSM_TOTAL>>>(
        xnh, w1t, b1, nullptr, nullptr, ffh, NTOK, D_FF, D_MODEL);
    // 7) out = x1 + ffh @ W2 + b2  (f32 out)
    gemm_h<false,true,false><<<dim3(D_MODEL/256, NTOK/128), 256, GSM_TOTAL>>>(
        ffh, w2t, b2, x1, out, nullptr, NTOK, D_MODEL, D_FF);
}

// round 5
// speedup vs baseline: 7.6995x; 1.4815x over previous
#include <cuda_runtime.h>
#include <cuda_fp16.h>
#include <cstdint>

#define D_MODEL 1024
#define D_FF    4096
#define SEQ     2048
#define BATCH   4
#define NTOK    (BATCH*SEQ)   /* 8192 */
#define NHEAD   16
#define DK      64

// ---------------- scratch (static device globals; no allocation) ----------------
__device__ __half g_xnh  [(size_t)NTOK*D_MODEL];
__device__ __half g_qkvh [(size_t)NTOK*3*D_MODEL];
__device__ __half g_ctxh [(size_t)NTOK*D_MODEL];
__device__ float  g_x1   [(size_t)NTOK*D_MODEL];
__device__ __half g_ffh  [(size_t)NTOK*D_FF];
__device__ __half g_wqkvt[(size_t)3*D_MODEL*D_MODEL];
__device__ __half g_wot  [(size_t)D_MODEL*D_MODEL];
__device__ __half g_w1t  [(size_t)D_FF*D_MODEL];
__device__ __half g_w2t  [(size_t)D_MODEL*D_FF];
__device__ float  g_bqkv [3*D_MODEL];

// ---------------- PTX helpers ----------------
__device__ __forceinline__ uint32_t smem_u32(const void* p) {
    uint32_t a;
    asm("{ .reg .u64 t; cvta.to.shared.u64 t, %1; cvt.u32.u64 %0, t; }"
        : "=r"(a) : "l"(p));
    return a;
}

#define LDSM4(r0, r1, r2, r3, a) \
    asm volatile("ldmatrix.sync.aligned.m8n8.x4.shared.b16 {%0,%1,%2,%3}, [%4];" \
        : "=r"(r0), "=r"(r1), "=r"(r2), "=r"(r3) : "r"(a))
#define LDSM4T(r0, r1, r2, r3, a) \
    asm volatile("ldmatrix.sync.aligned.m8n8.x4.trans.shared.b16 {%0,%1,%2,%3}, [%4];" \
        : "=r"(r0), "=r"(r1), "=r"(r2), "=r"(r3) : "r"(a))

#define CP16(dst, src) \
    asm volatile("cp.async.cg.shared.global [%0], [%1], 16;" :: "r"(dst), "l"(src))
#define CP_COMMIT() asm volatile("cp.async.commit_group;" ::: "memory")
#define CP_WAIT1()  asm volatile("cp.async.wait_group 1;" ::: "memory")

// fp16 MMA, fp32 accum: D(16x8) += A(16x16) @ B(16x8)
__device__ __forceinline__ void mma16(float* d, const uint32_t* a, const uint32_t* b) {
    asm volatile(
        "mma.sync.aligned.m16n8k16.row.col.f32.f16.f16.f32 "
        "{%0,%1,%2,%3}, {%4,%5,%6,%7}, {%8,%9}, {%0,%1,%2,%3};"
        : "+f"(d[0]), "+f"(d[1]), "+f"(d[2]), "+f"(d[3])
        : "r"(a[0]), "r"(a[1]), "r"(a[2]), "r"(a[3]), "r"(b[0]), "r"(b[1]));
}

// ---------------- LayerNorm: f32 in, fp16 out ----------------
__global__ void ln_kernel(const float* __restrict__ x,
                          const float* __restrict__ gamma,
                          const float* __restrict__ beta,
                          __half* __restrict__ y)
{
    __shared__ float sbuf[64];
    const int row = blockIdx.x;
    const int tid = threadIdx.x;
    const int lane = tid & 31, wid = tid >> 5;

    const float4 xv = ((const float4*)(x + (size_t)row * D_MODEL))[tid];
    float s  = xv.x + xv.y + xv.z + xv.w;
    float ss = xv.x*xv.x + xv.y*xv.y + xv.z*xv.z + xv.w*xv.w;
    #pragma unroll
    for (int off = 16; off; off >>= 1) {
        s  += __shfl_xor_sync(0xffffffffu, s,  off);
        ss += __shfl_xor_sync(0xffffffffu, ss, off);
    }
    if (lane == 0) { sbuf[wid] = s; sbuf[32 + wid] = ss; }
    __syncthreads();
    if (tid == 0) {
        float t = 0.f, t2 = 0.f;
        #pragma unroll
        for (int i = 0; i < 8; i++) { t += sbuf[i]; t2 += sbuf[32 + i]; }
        sbuf[16] = t; sbuf[48] = t2;
    }
    __syncthreads();
    const float mu   = sbuf[16] * (1.0f / D_MODEL);
    const float var  = sbuf[48] * (1.0f / D_MODEL) - mu * mu;
    const float rstd = rsqrtf(var + 1e-5f);

    const float4 g4 = ((const float4*)gamma)[tid];
    const float4 b4 = ((const float4*)beta)[tid];
    const float ox = (xv.x - mu) * rstd * g4.x + b4.x;
    const float oy = (xv.y - mu) * rstd * g4.y + b4.y;
    const float oz = (xv.z - mu) * rstd * g4.z + b4.z;
    const float ow = (xv.w - mu) * rstd * g4.w + b4.w;
    __half2 h0 = __floats2half2_rn(ox, oy);
    __half2 h1 = __floats2half2_rn(oz, ow);
    uint2 o;
    o.x = *(uint32_t*)&h0; o.y = *(uint32_t*)&h1;
    *(uint2*)(y + (size_t)row * D_MODEL + tid * 4) = o;
}

// ---------------- weight transpose: f32 in[K,N] -> fp16 out[N,K] ----------------
__global__ void transpose_h(const float* __restrict__ in, __half* __restrict__ out,
                            int K, int N)
{
    __shared__ float s[32][33];
    const int tx = threadIdx.x, ty = threadIdx.y;     // 32 x 8
    const int n0 = blockIdx.x * 32, k0 = blockIdx.y * 32;
    #pragma unroll
    for (int i = 0; i < 4; i++)
        s[ty + 8 * i][tx] = in[(size_t)(k0 + ty + 8 * i) * N + n0 + tx];
    __syncthreads();
    #pragma unroll
    for (int i = 0; i < 4; i++)
        out[(size_t)(n0 + ty + 8 * i) * K + k0 + tx] = __float2half_rn(s[tx][ty + 8 * i]);
}

__global__ void concat_bias_kernel(const float* __restrict__ bq, const float* __restrict__ bk,
                                   const float* __restrict__ bv, float* __restrict__ o)
{
    const int i = threadIdx.x + blockIdx.x * 1024;
    const float* src = (blockIdx.x == 0) ? bq : (blockIdx.x == 1) ? bk : bv;
    o[i] = src[threadIdx.x];
}

// ---------------- fp16 tensor-core GEMM, k-stage 64 ----------------
// C[M,N] = Ah[M,K](f16) @ Bh[N,K](f16)^T + bias (+relu) (+R).
// CTA 128x256, 8 warps (2m x 4n), warp 64x64, 3-stage cp.async, 128B rows SW128.
#define STG_BYTES 49152
#define GSM_TOTAL (3 * STG_BYTES)     /* 147456 */

template<bool RELU, bool RESID, bool HOUT>
__global__ __launch_bounds__(256, 1)
void gemm_h(const __half* __restrict__ Ah, const __half* __restrict__ Bh,
            const float* __restrict__ bias, const float* __restrict__ R,
            float* __restrict__ Cf, __half* __restrict__ Ch, int M, int N, int K)
{
    extern __shared__ char smem[];
    const uint32_t sb = smem_u32(smem);
    const int tid  = threadIdx.x;
    const int lane = tid & 31;
    const int wid  = tid >> 5;
    const int wm   = wid & 1;
    const int wn   = wid >> 1;
    const int swz  = lane & 7;

    const int m0 = blockIdx.y << 7;
    const int n0 = blockIdx.x << 8;

    // ldmatrix geometry
    const int rlA = lane & 15, clA = lane >> 4;
    const int rlB = (lane & 7) + ((lane >> 4) << 3);
    const int clB = (lane >> 3) & 1;

    float acc[4][8][4];
    #pragma unroll
    for (int mi = 0; mi < 4; mi++)
        #pragma unroll
        for (int ni = 0; ni < 8; ni++)
            #pragma unroll
            for (int c = 0; c < 4; c++) acc[mi][ni][c] = 0.f;

    const int T = K >> 6;

    #define ISSUE_STAGE(s, buf) do { \
        const uint32_t b0_ = sb + (buf) * STG_BYTES; \
        _Pragma("unroll") \
        for (int j = 0; j < 4; j++) { \
            const int c_ = tid + j * 256, row_ = c_ >> 3, ch_ = c_ & 7; \
            CP16(b0_ + row_ * 128 + ((ch_ ^ (row_ & 7)) << 4), \
                 Ah + (size_t)(m0 + row_) * K + (s) * 64 + ch_ * 8); \
        } \
        _Pragma("unroll") \
        for (int j = 0; j < 8; j++) { \
            const int c_ = tid + j * 256, row_ = c_ >> 3, ch_ = c_ & 7; \
            CP16(b0_ + 16384 + row_ * 128 + ((ch_ ^ (row_ & 7)) << 4), \
                 Bh + (size_t)(n0 + row_) * K + (s) * 64 + ch_ * 8); \
        } \
    } while (0)

    ISSUE_STAGE(0, 0); CP_COMMIT();
    if (T > 1) ISSUE_STAGE(1, 1);
    CP_COMMIT();

    int cur = 0;
    for (int kt = 0; kt < T; kt++) {
        CP_WAIT1();
        __syncthreads();
        {
            int nb = cur + 2; if (nb >= 3) nb -= 3;
            if (kt + 2 < T) ISSUE_STAGE(kt + 2, nb);
            CP_COMMIT();
        }
        const uint32_t sA = sb + cur * STG_BYTES;
        #pragma unroll
        for (int s = 0; s < 4; s++) {
            uint32_t af[4][4];
            #pragma unroll
            for (int mi = 0; mi < 4; mi++) {
                const int row = wm * 64 + mi * 16 + rlA;
                LDSM4(af[mi][0], af[mi][1], af[mi][2], af[mi][3],
                      sA + row * 128 + (((2 * s + clA) ^ swz) << 4));
            }
            uint32_t bf[8][2];
            #pragma unroll
            for (int p = 0; p < 4; p++) {
                const int row = wn * 64 + p * 16 + rlB;
                LDSM4(bf[2*p][0], bf[2*p][1], bf[2*p+1][0], bf[2*p+1][1],
                      sA + 16384 + row * 128 + (((2 * s + clB) ^ swz) << 4));
            }
            #pragma unroll
            for (int mi = 0; mi < 4; mi++)
                #pragma unroll
                for (int ni = 0; ni < 8; ni++)
                    mma16(acc[mi][ni], af[mi], bf[ni]);
        }
        cur = (cur == 2) ? 0 : cur + 1;
    }
    #undef ISSUE_STAGE

    // ---- epilogue ----
    const int g  = lane >> 2;
    const int t2 = lane & 3;
    #pragma unroll
    for (int ni = 0; ni < 8; ni++) {
        const int c = n0 + wn * 64 + ni * 8 + 2 * t2;
        const float2 bi = *(const float2*)&bias[c];
        #pragma unroll
        for (int mi = 0; mi < 4; mi++) {
            const int r0 = m0 + wm * 64 + mi * 16 + g;
            #pragma unroll
            for (int h = 0; h < 2; h++) {
                const int rr = r0 + h * 8;
                float vx = acc[mi][ni][2 * h]     + bi.x;
                float vy = acc[mi][ni][2 * h + 1] + bi.y;
                if (RELU) { vx = fmaxf(vx, 0.f); vy = fmaxf(vy, 0.f); }
                const size_t idx = (size_t)rr * N + c;
                if (RESID) {
                    const float2 rs = *(const float2*)&R[idx];
                    vx += rs.x; vy += rs.y;
                }
                if (HOUT) {
                    __half2 hv = __floats2half2_rn(vx, vy);
                    *(uint32_t*)&Ch[idx] = *(uint32_t*)&hv;
                } else {
                    float2 o; o.x = vx; o.y = vy;
                    *(float2*)&Cf[idx] = o;
                }
            }
        }
    }
}

// ---------------- fp16 flash attention, register-resident P ----------------
// 128 q-rows/block, 8 warps x 16 rows, 64-key tiles, dk=64.
// smem: q 16KB + 3 x (K 8KB | V 8KB) cp.async stages = 64KB. 128B rows, SW128.
#define ATT_STG  16384
#define ATT_SMEM (16384 + 3 * ATT_STG)   /* 65536 */

__global__ __launch_bounds__(256, 1)
void attn_h(const __half* __restrict__ Qg, const __half* __restrict__ Kg,
            const __half* __restrict__ Vg, __half* __restrict__ O, int ld)
{
    extern __shared__ char smem[];
    const uint32_t sb = smem_u32(smem);
    const int tid  = threadIdx.x;
    const int lane = tid & 31;
    const int wid  = tid >> 5;
    const int g    = lane >> 2;
    const int t    = lane & 3;
    const int swz  = lane & 7;

    const int bh = blockIdx.y;
    const int b  = bh >> 4;
    const int h  = bh & 15;
    const int q0 = blockIdx.x << 7;

    const size_t base  = (size_t)b * SEQ * ld + (size_t)h * DK;
    const size_t obase = (size_t)b * SEQ * D_MODEL + (size_t)h * DK;

    // ---- load Q tile (128 x 64 half, swizzled) ----
    #pragma unroll
    for (int p = 0; p < 4; p++) {
        const int c = tid + p * 256, row = c >> 3, ch = c & 7;
        *(uint4*)(smem + row * 128 + ((ch ^ (row & 7)) << 4)) =
            *(const uint4*)(Qg + base + (size_t)(q0 + row) * ld + ch * 8);
    }
    __syncthreads();

    // ---- Q fragments (held in registers for the whole loop) ----
    uint32_t aq[4][4];
    {
        const int rowA = wid * 16 + (lane & 15);
        const int clA  = lane >> 4;
        #pragma unroll
        for (int kb = 0; kb < 4; kb++)
            LDSM4(aq[kb][0], aq[kb][1], aq[kb][2], aq[kb][3],
                  sb + rowA * 128 + (((2 * kb + clA) ^ swz) << 4));
    }

    const int rlB = (lane & 7) + ((lane >> 4) << 3);   // QK B-frag row-in-16
    const int clB = (lane >> 3) & 1;
    const int kV  = (lane & 7) + ((lane & 8) ? 8 : 0); // V trans row-in-16
    const int cV  = (lane >> 4) & 1;

    float m0v = -1e30f, m1v = -1e30f, l0 = 0.f, l1 = 0.f;
    float oacc[8][4];
    #pragma unroll
    for (int ni = 0; ni < 8; ni++)
        #pragma unroll
        for (int c = 0; c < 4; c++) oacc[ni][c] = 0.f;

    #define ISSUE_KV(s, buf) do { \
        const uint32_t kb_ = sb + 16384 + (buf) * ATT_STG; \
        _Pragma("unroll") \
        for (int j = 0; j < 2; j++) { \
            const int c_ = tid + j * 256, row_ = c_ >> 3, ch_ = c_ & 7; \
            const uint32_t off_ = row_ * 128 + ((ch_ ^ (row_ & 7)) << 4); \
            const size_t gsrc = base + (size_t)((s) * 64 + row_) * ld + ch_ * 8; \
            CP16(kb_ + off_,        Kg + gsrc); \
            CP16(kb_ + 8192 + off_, Vg + gsrc); \
        } \
    } while (0)

    ISSUE_KV(0, 0); CP_COMMIT();
    ISSUE_KV(1, 1); CP_COMMIT();

    int cur = 0;
    const int T = SEQ / 64;
    for (int kt = 0; kt < T; kt++) {
        CP_WAIT1();
        __syncthreads();
        {
            int nb = cur + 2; if (nb >= 3) nb -= 3;
            if (kt + 2 < T) ISSUE_KV(kt + 2, nb);
            CP_COMMIT();
        }
        const uint32_t kbuf = sb + 16384 + cur * ATT_STG;
        const uint32_t vbuf = kbuf + 8192;

        // ---- S = Q @ K^T ----
        float sacc[8][4];
        #pragma unroll
        for (int ni = 0; ni < 8; ni++)
            #pragma unroll
            for (int c = 0; c < 4; c++) sacc[ni][c] = 0.f;

        #pragma unroll
        for (int kb = 0; kb < 4; kb++) {
            uint32_t bf[8][2];
            #pragma unroll
            for (int a = 0; a < 4; a++) {
                const int row = 16 * a + rlB;
                LDSM4(bf[2*a][0], bf[2*a][1], bf[2*a+1][0], bf[2*a+1][1],
                      kbuf + row * 128 + (((2 * kb + clB) ^ swz) << 4));
            }
            #pragma unroll
            for (int ni = 0; ni < 8; ni++)
                mma16(sacc[ni], aq[kb], bf[ni]);
        }

        // ---- online softmax (rows g, g+8; quad lanes own a row's keys) ----
        #pragma unroll
        for (int ni = 0; ni < 8; ni++) {
            sacc[ni][0] *= 0.125f; sacc[ni][1] *= 0.125f;
            sacc[ni][2] *= 0.125f; sacc[ni][3] *= 0.125f;
        }
        float mx0 = -1e30f, mx1 = -1e30f;
        #pragma unroll
        for (int ni = 0; ni < 8; ni++) {
            mx0 = fmaxf(mx0, fmaxf(sacc[ni][0], sacc[ni][1]));
            mx1 = fmaxf(mx1, fmaxf(sacc[ni][2], sacc[ni][3]));
        }
        mx0 = fmaxf(mx0, __shfl_xor_sync(0xffffffffu, mx0, 1));
        mx0 = fmaxf(mx0, __shfl_xor_sync(0xffffffffu, mx0, 2));
        mx1 = fmaxf(mx1, __shfl_xor_sync(0xffffffffu, mx1, 1));
        mx1 = fmaxf(mx1, __shfl_xor_sync(0xffffffffu, mx1, 2));

        const float mn0 = fmaxf(m0v, mx0);
        const float mn1 = fmaxf(m1v, mx1);
        const float al0 = __expf(m0v - mn0);
        const float al1 = __expf(m1v - mn1);
        m0v = mn0; m1v = mn1;

        uint32_t pa[8][2];
        float sum0 = 0.f, sum1 = 0.f;
        #pragma unroll
        for (int ni = 0; ni < 8; ni++) {
            const float p0 = __expf(sacc[ni][0] - mn0);
            const float p1 = __expf(sacc[ni][1] - mn0);
            const float p2 = __expf(sacc[ni][2] - mn1);
            const float p3 = __expf(sacc[ni][3] - mn1);
            sum0 += p0 + p1; sum1 += p2 + p3;
            __half2 h0 = __floats2half2_rn(p0, p1);
            __half2 h1 = __floats2half2_rn(p2, p3);
            pa[ni][0] = *(uint32_t*)&h0;
            pa[ni][1] = *(uint32_t*)&h1;
        }
        sum0 += __shfl_xor_sync(0xffffffffu, sum0, 1);
        sum0 += __shfl_xor_sync(0xffffffffu, sum0, 2);
        sum1 += __shfl_xor_sync(0xffffffffu, sum1, 1);
        sum1 += __shfl_xor_sync(0xffffffffu, sum1, 2);
        l0 = l0 * al0 + sum0;
        l1 = l1 * al1 + sum1;

        #pragma unroll
        for (int ni = 0; ni < 8; ni++) {
            oacc[ni][0] *= al0; oacc[ni][1] *= al0;
            oacc[ni][2] *= al1; oacc[ni][3] *= al1;
        }

        // ---- O += P @ V (P stays in registers as A-fragments) ----
        #pragma unroll
        for (int kk = 0; kk < 4; kk++) {
            uint32_t bv[8][2];
            #pragma unroll
            for (int bb = 0; bb < 4; bb++) {
                const int key = 16 * kk + kV;
                LDSM4T(bv[2*bb][0], bv[2*bb][1], bv[2*bb+1][0], bv[2*bb+1][1],
                       vbuf + key * 128 + (((2 * bb + cV) ^ swz) << 4));
            }
            uint32_t ap[4] = { pa[2*kk][0], pa[2*kk][1], pa[2*kk+1][0], pa[2*kk+1][1] };
            #pragma unroll
            for (int ni = 0; ni < 8; ni++)
                mma16(oacc[ni], ap, bv[ni]);
        }

        cur = (cur == 2) ? 0 : cur + 1;
    }
    #undef ISSUE_KV

    // ---- epilogue ----
    const float inv0 = 1.f / l0;
    const float inv1 = 1.f / l1;
    const size_t row0 = obase + (size_t)(q0 + wid * 16 + g) * D_MODEL;
    const size_t row1 = row0 + (size_t)8 * D_MODEL;
    #pragma unroll
    for (int ni = 0; ni < 8; ni++) {
        const int c = ni * 8 + 2 * t;
        __half2 h0 = __floats2half2_rn(oacc[ni][0] * inv0, oacc[ni][1] * inv0);
        __half2 h1 = __floats2half2_rn(oacc[ni][2] * inv1, oacc[ni][3] * inv1);
        *(uint32_t*)&O[row0 + c] = *(uint32_t*)&h0;
        *(uint32_t*)&O[row1 + c] = *(uint32_t*)&h1;
    }
}

// ---------------- launch ----------------
extern "C" void kernel_launch(void* const* d_in, const int* in_sizes, int n_in,
                              void* d_out, int out_size)
{
    const float* x    = (const float*)d_in[0];
    const float* ln1g = (const float*)d_in[1];
    const float* ln1b = (const float*)d_in[2];
    const float* ln2g = (const float*)d_in[3];
    const float* ln2b = (const float*)d_in[4];
    const float* Wq = (const float*)d_in[5];
    const float* bq = (const float*)d_in[6];
    const float* Wk = (const float*)d_in[7];
    const float* bk = (const float*)d_in[8];
    const float* Wv = (const float*)d_in[9];
    const float* bv = (const float*)d_in[10];
    const float* Wo = (const float*)d_in[11];
    const float* bo = (const float*)d_in[12];
    const float* W1 = (const float*)d_in[13];
    const float* b1 = (const float*)d_in[14];
    const float* W2 = (const float*)d_in[15];
    const float* b2 = (const float*)d_in[16];
    float* out = (float*)d_out;

    __half *xnh, *qkvh, *ctxh, *ffh, *wqkvt, *wot, *w1t, *w2t;
    float *x1, *bqkv;
    cudaGetSymbolAddress((void**)&xnh,   g_xnh);
    cudaGetSymbolAddress((void**)&qkvh,  g_qkvh);
    cudaGetSymbolAddress((void**)&ctxh,  g_ctxh);
    cudaGetSymbolAddress((void**)&x1,    g_x1);
    cudaGetSymbolAddress((void**)&ffh,   g_ffh);
    cudaGetSymbolAddress((void**)&wqkvt, g_wqkvt);
    cudaGetSymbolAddress((void**)&wot,   g_wot);
    cudaGetSymbolAddress((void**)&w1t,   g_w1t);
    cudaGetSymbolAddress((void**)&w2t,   g_w2t);
    cudaGetSymbolAddress((void**)&bqkv,  g_bqkv);

    cudaFuncSetAttribute(attn_h, cudaFuncAttributeMaxDynamicSharedMemorySize, ATT_SMEM);
    cudaFuncSetAttribute(gemm_h<false,false,true>,  cudaFuncAttributeMaxDynamicSharedMemorySize, GSM_TOTAL);
    cudaFuncSetAttribute(gemm_h<false,true,false>,  cudaFuncAttributeMaxDynamicSharedMemorySize, GSM_TOTAL);
    cudaFuncSetAttribute(gemm_h<true,false,true>,   cudaFuncAttributeMaxDynamicSharedMemorySize, GSM_TOTAL);

    const dim3 tb(32, 8);

    // weight transposes (f32 W[K,N] -> f16 Wt[N,K]) + bias concat
    transpose_h<<<dim3(32, 32), tb>>>(Wq, wqkvt,                             D_MODEL, D_MODEL);
    transpose_h<<<dim3(32, 32), tb>>>(Wk, wqkvt + (size_t)D_MODEL*D_MODEL,   D_MODEL, D_MODEL);
    transpose_h<<<dim3(32, 32), tb>>>(Wv, wqkvt + (size_t)2*D_MODEL*D_MODEL, D_MODEL, D_MODEL);
    transpose_h<<<dim3(32, 32), tb>>>(Wo, wot, D_MODEL, D_MODEL);
    transpose_h<<<dim3(128, 32), tb>>>(W1, w1t, D_MODEL, D_FF);
    transpose_h<<<dim3(32, 128), tb>>>(W2, w2t, D_FF, D_MODEL);
    concat_bias_kernel<<<3, 1024>>>(bq, bk, bv, bqkv);

    // 1) xn = LN1(x)  (fp16 out)
    ln_kernel<<<NTOK, 256>>>(x, ln1g, ln1b, xnh);
    // 2) qkv = xn @ [Wq|Wk|Wv] + [bq|bk|bv]   (fused, N=3072, fp16 out)
    gemm_h<false,false,true><<<dim3(3*D_MODEL/256, NTOK/128), 256, GSM_TOTAL>>>(
        xnh, wqkvt, bqkv, nullptr, nullptr, qkvh, NTOK, 3*D_MODEL, D_MODEL);
    // 3) ctx = attention(q,k,v)  (fp16 in/out)
    attn_h<<<dim3(SEQ/128, BATCH*NHEAD), 256, ATT_SMEM>>>(
        qkvh, qkvh + D_MODEL, qkvh + 2*D_MODEL, ctxh, 3*D_MODEL);
    // 4) x1 = x + ctx @ Wo + bo  (f32 out)
    gemm_h<false,true,false><<<dim3(D_MODEL/256, NTOK/128), 256, GSM_TOTAL>>>(
        ctxh, wot, bo, x, x1, nullptr, NTOK, D_MODEL, D_MODEL);
    // 5) xn = LN2(x1)  (fp16 out)
    ln_kernel<<<NTOK, 256>>>(x1, ln2g, ln2b, xnh);
    // 6) ffh = relu(xn @ W1 + b1)  (fp16 out)
    gemm_h<true,false,true><<<dim3(D_FF/256, NTOK/128), 256, GSM_TOTAL>>>(
        xnh, w1t, b1, nullptr, nullptr, ffh, NTOK, D_FF, D_MODEL);
    // 7) out = x1 + ffh @ W2 + b2  (f32 out)
    gemm_h<false,true,false><<<dim3(D_MODEL/256, NTOK/128), 256, GSM_TOTAL>>>(
        ffh, w2t, b2, x1, out, nullptr, NTOK, D_MODEL, D_FF);
}

// round 6
// speedup vs baseline: 7.7807x; 1.0105x over previous
#include <cuda_runtime.h>
#include <cuda_fp16.h>
#include <cstdint>

#define D_MODEL 1024
#define D_FF    4096
#define SEQ     2048
#define BATCH   4
#define NTOK    (BATCH*SEQ)   /* 8192 */
#define NHEAD   16
#define DK      64

// ---------------- scratch (static device globals; no allocation) ----------------
__device__ __half g_xnh  [(size_t)NTOK*D_MODEL];
__device__ __half g_qkvh [(size_t)NTOK*3*D_MODEL];
__device__ __half g_ctxh [(size_t)NTOK*D_MODEL];
__device__ float  g_x1   [(size_t)NTOK*D_MODEL];
__device__ __half g_ffh  [(size_t)NTOK*D_FF];
__device__ __half g_wqkvh[(size_t)D_MODEL*3*D_MODEL];   // [K=1024][N=3072]
__device__ __half g_woh  [(size_t)D_MODEL*D_MODEL];     // [K][N]
__device__ __half g_w1h  [(size_t)D_MODEL*D_FF];        // [1024][4096]
__device__ __half g_w2h  [(size_t)D_FF*D_MODEL];        // [4096][1024]
__device__ float  g_bqkv [3*D_MODEL];

// ---------------- PTX helpers ----------------
__device__ __forceinline__ uint32_t smem_u32(const void* p) {
    uint32_t a;
    asm("{ .reg .u64 t; cvta.to.shared.u64 t, %1; cvt.u32.u64 %0, t; }"
        : "=r"(a) : "l"(p));
    return a;
}

#define LDSM4(r0, r1, r2, r3, a) \
    asm volatile("ldmatrix.sync.aligned.m8n8.x4.shared.b16 {%0,%1,%2,%3}, [%4];" \
        : "=r"(r0), "=r"(r1), "=r"(r2), "=r"(r3) : "r"(a))
#define LDSM4T(r0, r1, r2, r3, a) \
    asm volatile("ldmatrix.sync.aligned.m8n8.x4.trans.shared.b16 {%0,%1,%2,%3}, [%4];" \
        : "=r"(r0), "=r"(r1), "=r"(r2), "=r"(r3) : "r"(a))

#define CP16(dst, src) \
    asm volatile("cp.async.cg.shared.global [%0], [%1], 16;" :: "r"(dst), "l"(src))
#define CP_COMMIT() asm volatile("cp.async.commit_group;" ::: "memory")
#define CP_WAIT1()  asm volatile("cp.async.wait_group 1;" ::: "memory")

// fp16 MMA, fp32 accum: D(16x8) += A(16x16) @ B(16x8)
__device__ __forceinline__ void mma16(float* d, const uint32_t* a, const uint32_t* b) {
    asm volatile(
        "mma.sync.aligned.m16n8k16.row.col.f32.f16.f16.f32 "
        "{%0,%1,%2,%3}, {%4,%5,%6,%7}, {%8,%9}, {%0,%1,%2,%3};"
        : "+f"(d[0]), "+f"(d[1]), "+f"(d[2]), "+f"(d[3])
        : "r"(a[0]), "r"(a[1]), "r"(a[2]), "r"(a[3]), "r"(b[0]), "r"(b[1]));
}

// ---------------- LayerNorm: f32 in, fp16 out ----------------
__global__ void ln_kernel(const float* __restrict__ x,
                          const float* __restrict__ gamma,
                          const float* __restrict__ beta,
                          __half* __restrict__ y)
{
    __shared__ float sbuf[64];
    const int row = blockIdx.x;
    const int tid = threadIdx.x;
    const int lane = tid & 31, wid = tid >> 5;

    const float4 xv = ((const float4*)(x + (size_t)row * D_MODEL))[tid];
    float s  = xv.x + xv.y + xv.z + xv.w;
    float ss = xv.x*xv.x + xv.y*xv.y + xv.z*xv.z + xv.w*xv.w;
    #pragma unroll
    for (int off = 16; off; off >>= 1) {
        s  += __shfl_xor_sync(0xffffffffu, s,  off);
        ss += __shfl_xor_sync(0xffffffffu, ss, off);
    }
    if (lane == 0) { sbuf[wid] = s; sbuf[32 + wid] = ss; }
    __syncthreads();
    if (tid == 0) {
        float t = 0.f, t2 = 0.f;
        #pragma unroll
        for (int i = 0; i < 8; i++) { t += sbuf[i]; t2 += sbuf[32 + i]; }
        sbuf[16] = t; sbuf[48] = t2;
    }
    __syncthreads();
    const float mu   = sbuf[16] * (1.0f / D_MODEL);
    const float var  = sbuf[48] * (1.0f / D_MODEL) - mu * mu;
    const float rstd = rsqrtf(var + 1e-5f);

    const float4 g4 = ((const float4*)gamma)[tid];
    const float4 b4 = ((const float4*)beta)[tid];
    const float ox = (xv.x - mu) * rstd * g4.x + b4.x;
    const float oy = (xv.y - mu) * rstd * g4.y + b4.y;
    const float oz = (xv.z - mu) * rstd * g4.z + b4.z;
    const float ow = (xv.w - mu) * rstd * g4.w + b4.w;
    __half2 h0 = __floats2half2_rn(ox, oy);
    __half2 h1 = __floats2half2_rn(oz, ow);
    uint2 o;
    o.x = *(uint32_t*)&h0; o.y = *(uint32_t*)&h1;
    *(uint2*)(y + (size_t)row * D_MODEL + tid * 4) = o;
}

// ---------------- weight convert (no transpose): f32 -> f16, same layout ----------------
__global__ void convert_h(const float* __restrict__ in, __half* __restrict__ out)
{
    const size_t i = ((size_t)blockIdx.x * 256 + threadIdx.x) * 4;
    const float4 v = *(const float4*)(in + i);
    __half2 a = __floats2half2_rn(v.x, v.y);
    __half2 b = __floats2half2_rn(v.z, v.w);
    uint2 o; o.x = *(uint32_t*)&a; o.y = *(uint32_t*)&b;
    *(uint2*)(out + i) = o;
}

// qkv merge-convert: out[k][j*1024 + n] = Wj[k][n], f32 -> f16
__global__ void convert_qkv(const float* __restrict__ Wq, const float* __restrict__ Wk,
                            const float* __restrict__ Wv, __half* __restrict__ out)
{
    const int k = blockIdx.x;           // 0..1023
    const int c = threadIdx.x;          // 0..255 (float4 index within row)
    const float* srcs[3] = { Wq, Wk, Wv };
    #pragma unroll
    for (int j = 0; j < 3; j++) {
        const float4 v = ((const float4*)(srcs[j] + (size_t)k * D_MODEL))[c];
        __half2 a = __floats2half2_rn(v.x, v.y);
        __half2 b = __floats2half2_rn(v.z, v.w);
        uint2 o; o.x = *(uint32_t*)&a; o.y = *(uint32_t*)&b;
        *(uint2*)(out + (size_t)k * 3 * D_MODEL + j * D_MODEL + c * 4) = o;
    }
}

__global__ void concat_bias_kernel(const float* __restrict__ bq, const float* __restrict__ bk,
                                   const float* __restrict__ bv, float* __restrict__ o)
{
    const int i = threadIdx.x + blockIdx.x * 1024;
    const float* src = (blockIdx.x == 0) ? bq : (blockIdx.x == 1) ? bk : bv;
    o[i] = src[threadIdx.x];
}

// ---------------- fp16 tensor-core GEMM, 512 threads, direct [K,N] B ----------------
// C[M,N] = Ah[M,K](f16) @ Bh[K,N](f16) + bias (+relu) (+R).
// CTA 128x256, 16 warps (2m x 8n), warp tile 64x32, k-stage 64, 3-stage cp.async.
// A smem: [128m][64k] 128B rows, chunk-xor swizzle.
// B smem: [64k][256n] 512B rows, per-8-chunk xor swizzle; frags via ldmatrix.trans.
#define STG_BYTES 49152
#define GSM_TOTAL (3 * STG_BYTES)     /* 147456 */

template<bool RELU, bool RESID, bool HOUT>
__global__ __launch_bounds__(512, 1)
void gemm_h(const __half* __restrict__ Ah, const __half* __restrict__ Bh,
            const float* __restrict__ bias, const float* __restrict__ R,
            float* __restrict__ Cf, __half* __restrict__ Ch, int M, int N, int K)
{
    extern __shared__ char smem[];
    const uint32_t sb = smem_u32(smem);
    const int tid  = threadIdx.x;
    const int lane = tid & 31;
    const int wid  = tid >> 5;          // 0..15
    const int wm   = wid & 1;
    const int wn   = wid >> 1;          // 0..7
    const int swz  = lane & 7;

    const int m0 = blockIdx.y << 7;
    const int n0 = blockIdx.x << 8;

    // A ldmatrix geometry
    const int rlA = lane & 15, clA = lane >> 4;
    // B trans-ldmatrix geometry (same as attention V path)
    const int kV = (lane & 7) + ((lane & 8) ? 8 : 0);
    const int cV = (lane >> 4) & 1;

    float acc[4][4][4];
    #pragma unroll
    for (int mi = 0; mi < 4; mi++)
        #pragma unroll
        for (int ni = 0; ni < 4; ni++)
            #pragma unroll
            for (int c = 0; c < 4; c++) acc[mi][ni][c] = 0.f;

    const int T = K >> 6;

    #define ISSUE_STAGE(s, buf) do { \
        const uint32_t b0_ = sb + (buf) * STG_BYTES; \
        _Pragma("unroll") \
        for (int j = 0; j < 2; j++) { \
            const int c_ = tid + j * 512, row_ = c_ >> 3, ch_ = c_ & 7; \
            CP16(b0_ + row_ * 128 + ((ch_ ^ (row_ & 7)) << 4), \
                 Ah + (size_t)(m0 + row_) * K + (s) * 64 + ch_ * 8); \
        } \
        _Pragma("unroll") \
        for (int j = 0; j < 4; j++) { \
            const int c_ = tid + j * 512, row_ = c_ >> 5, ch_ = c_ & 31; \
            const int ph_ = (ch_ & 24) | ((ch_ & 7) ^ (row_ & 7)); \
            CP16(b0_ + 16384 + row_ * 512 + (ph_ << 4), \
                 Bh + (size_t)((s) * 64 + row_) * N + n0 + ch_ * 8); \
        } \
    } while (0)

    ISSUE_STAGE(0, 0); CP_COMMIT();
    if (T > 1) ISSUE_STAGE(1, 1);
    CP_COMMIT();

    int cur = 0;
    for (int kt = 0; kt < T; kt++) {
        CP_WAIT1();
        __syncthreads();
        {
            int nb = cur + 2; if (nb >= 3) nb -= 3;
            if (kt + 2 < T) ISSUE_STAGE(kt + 2, nb);
            CP_COMMIT();
        }
        const uint32_t sA = sb + cur * STG_BYTES;
        const uint32_t sB = sA + 16384;
        #pragma unroll
        for (int s = 0; s < 4; s++) {
            uint32_t af[4][4];
            #pragma unroll
            for (int mi = 0; mi < 4; mi++) {
                const int row = wm * 64 + mi * 16 + rlA;
                LDSM4(af[mi][0], af[mi][1], af[mi][2], af[mi][3],
                      sA + row * 128 + (((2 * s + clA) ^ swz) << 4));
            }
            uint32_t bf[4][2];
            #pragma unroll
            for (int bb = 0; bb < 2; bb++) {
                const int c = wn * 4 + 2 * bb + cV;
                const int ph = (c & 24) | ((c & 7) ^ (kV & 7));
                LDSM4T(bf[2*bb][0], bf[2*bb][1], bf[2*bb+1][0], bf[2*bb+1][1],
                       sB + (16 * s + kV) * 512 + (ph << 4));
            }
            #pragma unroll
            for (int mi = 0; mi < 4; mi++)
                #pragma unroll
                for (int ni = 0; ni < 4; ni++)
                    mma16(acc[mi][ni], af[mi], bf[ni]);
        }
        cur = (cur == 2) ? 0 : cur + 1;
    }
    #undef ISSUE_STAGE

    // ---- epilogue ----
    const int g  = lane >> 2;
    const int t2 = lane & 3;
    #pragma unroll
    for (int ni = 0; ni < 4; ni++) {
        const int c = n0 + wn * 32 + ni * 8 + 2 * t2;
        const float2 bi = *(const float2*)&bias[c];
        #pragma unroll
        for (int mi = 0; mi < 4; mi++) {
            const int r0 = m0 + wm * 64 + mi * 16 + g;
            #pragma unroll
            for (int h = 0; h < 2; h++) {
                const int rr = r0 + h * 8;
                float vx = acc[mi][ni][2 * h]     + bi.x;
                float vy = acc[mi][ni][2 * h + 1] + bi.y;
                if (RELU) { vx = fmaxf(vx, 0.f); vy = fmaxf(vy, 0.f); }
                const size_t idx = (size_t)rr * N + c;
                if (RESID) {
                    const float2 rs = *(const float2*)&R[idx];
                    vx += rs.x; vy += rs.y;
                }
                if (HOUT) {
                    __half2 hv = __floats2half2_rn(vx, vy);
                    *(uint32_t*)&Ch[idx] = *(uint32_t*)&hv;
                } else {
                    float2 o; o.x = vx; o.y = vy;
                    *(float2*)&Cf[idx] = o;
                }
            }
        }
    }
}

// ---------------- fp16 flash attention, register-resident P (round-5 proven) ----------------
#define ATT_STG  16384
#define ATT_SMEM (16384 + 3 * ATT_STG)   /* 65536 */

__global__ __launch_bounds__(256, 1)
void attn_h(const __half* __restrict__ Qg, const __half* __restrict__ Kg,
            const __half* __restrict__ Vg, __half* __restrict__ O, int ld)
{
    extern __shared__ char smem[];
    const uint32_t sb = smem_u32(smem);
    const int tid  = threadIdx.x;
    const int lane = tid & 31;
    const int wid  = tid >> 5;
    const int g    = lane >> 2;
    const int t    = lane & 3;
    const int swz  = lane & 7;

    const int bh = blockIdx.y;
    const int b  = bh >> 4;
    const int h  = bh & 15;
    const int q0 = blockIdx.x << 7;

    const size_t base  = (size_t)b * SEQ * ld + (size_t)h * DK;
    const size_t obase = (size_t)b * SEQ * D_MODEL + (size_t)h * DK;

    #pragma unroll
    for (int p = 0; p < 4; p++) {
        const int c = tid + p * 256, row = c >> 3, ch = c & 7;
        *(uint4*)(smem + row * 128 + ((ch ^ (row & 7)) << 4)) =
            *(const uint4*)(Qg + base + (size_t)(q0 + row) * ld + ch * 8);
    }
    __syncthreads();

    uint32_t aq[4][4];
    {
        const int rowA = wid * 16 + (lane & 15);
        const int clA  = lane >> 4;
        #pragma unroll
        for (int kb = 0; kb < 4; kb++)
            LDSM4(aq[kb][0], aq[kb][1], aq[kb][2], aq[kb][3],
                  sb + rowA * 128 + (((2 * kb + clA) ^ swz) << 4));
    }

    const int rlB = (lane & 7) + ((lane >> 4) << 3);
    const int clB = (lane >> 3) & 1;
    const int kV  = (lane & 7) + ((lane & 8) ? 8 : 0);
    const int cV  = (lane >> 4) & 1;

    float m0v = -1e30f, m1v = -1e30f, l0 = 0.f, l1 = 0.f;
    float oacc[8][4];
    #pragma unroll
    for (int ni = 0; ni < 8; ni++)
        #pragma unroll
        for (int c = 0; c < 4; c++) oacc[ni][c] = 0.f;

    #define ISSUE_KV(s, buf) do { \
        const uint32_t kb_ = sb + 16384 + (buf) * ATT_STG; \
        _Pragma("unroll") \
        for (int j = 0; j < 2; j++) { \
            const int c_ = tid + j * 256, row_ = c_ >> 3, ch_ = c_ & 7; \
            const uint32_t off_ = row_ * 128 + ((ch_ ^ (row_ & 7)) << 4); \
            const size_t gsrc = base + (size_t)((s) * 64 + row_) * ld + ch_ * 8; \
            CP16(kb_ + off_,        Kg + gsrc); \
            CP16(kb_ + 8192 + off_, Vg + gsrc); \
        } \
    } while (0)

    ISSUE_KV(0, 0); CP_COMMIT();
    ISSUE_KV(1, 1); CP_COMMIT();

    int cur = 0;
    const int T = SEQ / 64;
    for (int kt = 0; kt < T; kt++) {
        CP_WAIT1();
        __syncthreads();
        {
            int nb = cur + 2; if (nb >= 3) nb -= 3;
            if (kt + 2 < T) ISSUE_KV(kt + 2, nb);
            CP_COMMIT();
        }
        const uint32_t kbuf = sb + 16384 + cur * ATT_STG;
        const uint32_t vbuf = kbuf + 8192;

        float sacc[8][4];
        #pragma unroll
        for (int ni = 0; ni < 8; ni++)
            #pragma unroll
            for (int c = 0; c < 4; c++) sacc[ni][c] = 0.f;

        #pragma unroll
        for (int kb = 0; kb < 4; kb++) {
            uint32_t bf[8][2];
            #pragma unroll
            for (int a = 0; a < 4; a++) {
                const int row = 16 * a + rlB;
                LDSM4(bf[2*a][0], bf[2*a][1], bf[2*a+1][0], bf[2*a+1][1],
                      kbuf + row * 128 + (((2 * kb + clB) ^ swz) << 4));
            }
            #pragma unroll
            for (int ni = 0; ni < 8; ni++)
                mma16(sacc[ni], aq[kb], bf[ni]);
        }

        #pragma unroll
        for (int ni = 0; ni < 8; ni++) {
            sacc[ni][0] *= 0.125f; sacc[ni][1] *= 0.125f;
            sacc[ni][2] *= 0.125f; sacc[ni][3] *= 0.125f;
        }
        float mx0 = -1e30f, mx1 = -1e30f;
        #pragma unroll
        for (int ni = 0; ni < 8; ni++) {
            mx0 = fmaxf(mx0, fmaxf(sacc[ni][0], sacc[ni][1]));
            mx1 = fmaxf(mx1, fmaxf(sacc[ni][2], sacc[ni][3]));
        }
        mx0 = fmaxf(mx0, __shfl_xor_sync(0xffffffffu, mx0, 1));
        mx0 = fmaxf(mx0, __shfl_xor_sync(0xffffffffu, mx0, 2));
        mx1 = fmaxf(mx1, __shfl_xor_sync(0xffffffffu, mx1, 1));
        mx1 = fmaxf(mx1, __shfl_xor_sync(0xffffffffu, mx1, 2));

        const float mn0 = fmaxf(m0v, mx0);
        const float mn1 = fmaxf(m1v, mx1);
        const float al0 = __expf(m0v - mn0);
        const float al1 = __expf(m1v - mn1);
        m0v = mn0; m1v = mn1;

        uint32_t pa[8][2];
        float sum0 = 0.f, sum1 = 0.f;
        #pragma unroll
        for (int ni = 0; ni < 8; ni++) {
            const float p0 = __expf(sacc[ni][0] - mn0);
            const float p1 = __expf(sacc[ni][1] - mn0);
            const float p2 = __expf(sacc[ni][2] - mn1);
            const float p3 = __expf(sacc[ni][3] - mn1);
            sum0 += p0 + p1; sum1 += p2 + p3;
            __half2 h0 = __floats2half2_rn(p0, p1);
            __half2 h1 = __floats2half2_rn(p2, p3);
            pa[ni][0] = *(uint32_t*)&h0;
            pa[ni][1] = *(uint32_t*)&h1;
        }
        sum0 += __shfl_xor_sync(0xffffffffu, sum0, 1);
        sum0 += __shfl_xor_sync(0xffffffffu, sum0, 2);
        sum1 += __shfl_xor_sync(0xffffffffu, sum1, 1);
        sum1 += __shfl_xor_sync(0xffffffffu, sum1, 2);
        l0 = l0 * al0 + sum0;
        l1 = l1 * al1 + sum1;

        #pragma unroll
        for (int ni = 0; ni < 8; ni++) {
            oacc[ni][0] *= al0; oacc[ni][1] *= al0;
            oacc[ni][2] *= al1; oacc[ni][3] *= al1;
        }

        #pragma unroll
        for (int kk = 0; kk < 4; kk++) {
            uint32_t bv[8][2];
            #pragma unroll
            for (int bb = 0; bb < 4; bb++) {
                const int key = 16 * kk + kV;
                LDSM4T(bv[2*bb][0], bv[2*bb][1], bv[2*bb+1][0], bv[2*bb+1][1],
                       vbuf + key * 128 + (((2 * bb + cV) ^ swz) << 4));
            }
            uint32_t ap[4] = { pa[2*kk][0], pa[2*kk][1], pa[2*kk+1][0], pa[2*kk+1][1] };
            #pragma unroll
            for (int ni = 0; ni < 8; ni++)
                mma16(oacc[ni], ap, bv[ni]);
        }

        cur = (cur == 2) ? 0 : cur + 1;
    }
    #undef ISSUE_KV

    const float inv0 = 1.f / l0;
    const float inv1 = 1.f / l1;
    const size_t row0 = obase + (size_t)(q0 + wid * 16 + g) * D_MODEL;
    const size_t row1 = row0 + (size_t)8 * D_MODEL;
    #pragma unroll
    for (int ni = 0; ni < 8; ni++) {
        const int c = ni * 8 + 2 * t;
        __half2 h0 = __floats2half2_rn(oacc[ni][0] * inv0, oacc[ni][1] * inv0);
        __half2 h1 = __floats2half2_rn(oacc[ni][2] * inv1, oacc[ni][3] * inv1);
        *(uint32_t*)&O[row0 + c] = *(uint32_t*)&h0;
        *(uint32_t*)&O[row1 + c] = *(uint32_t*)&h1;
    }
}

// ---------------- launch ----------------
extern "C" void kernel_launch(void* const* d_in, const int* in_sizes, int n_in,
                              void* d_out, int out_size)
{
    const float* x    = (const float*)d_in[0];
    const float* ln1g = (const float*)d_in[1];
    const float* ln1b = (const float*)d_in[2];
    const float* ln2g = (const float*)d_in[3];
    const float* ln2b = (const float*)d_in[4];
    const float* Wq = (const float*)d_in[5];
    const float* bq = (const float*)d_in[6];
    const float* Wk = (const float*)d_in[7];
    const float* bk = (const float*)d_in[8];
    const float* Wv = (const float*)d_in[9];
    const float* bv = (const float*)d_in[10];
    const float* Wo = (const float*)d_in[11];
    const float* bo = (const float*)d_in[12];
    const float* W1 = (const float*)d_in[13];
    const float* b1 = (const float*)d_in[14];
    const float* W2 = (const float*)d_in[15];
    const float* b2 = (const float*)d_in[16];
    float* out = (float*)d_out;

    __half *xnh, *qkvh, *ctxh, *ffh, *wqkvh, *woh, *w1h, *w2h;
    float *x1, *bqkv;
    cudaGetSymbolAddress((void**)&xnh,   g_xnh);
    cudaGetSymbolAddress((void**)&qkvh,  g_qkvh);
    cudaGetSymbolAddress((void**)&ctxh,  g_ctxh);
    cudaGetSymbolAddress((void**)&x1,    g_x1);
    cudaGetSymbolAddress((void**)&ffh,   g_ffh);
    cudaGetSymbolAddress((void**)&wqkvh, g_wqkvh);
    cudaGetSymbolAddress((void**)&woh,   g_woh);
    cudaGetSymbolAddress((void**)&w1h,   g_w1h);
    cudaGetSymbolAddress((void**)&w2h,   g_w2h);
    cudaGetSymbolAddress((void**)&bqkv,  g_bqkv);

    cudaFuncSetAttribute(attn_h, cudaFuncAttributeMaxDynamicSharedMemorySize, ATT_SMEM);
    cudaFuncSetAttribute(gemm_h<false,false,true>,  cudaFuncAttributeMaxDynamicSharedMemorySize, GSM_TOTAL);
    cudaFuncSetAttribute(gemm_h<false,true,false>,  cudaFuncAttributeMaxDynamicSharedMemorySize, GSM_TOTAL);
    cudaFuncSetAttribute(gemm_h<true,false,true>,   cudaFuncAttributeMaxDynamicSharedMemorySize, GSM_TOTAL);

    // weight converts (f32 -> f16, layout preserved [K,N]) + bias concat
    convert_qkv<<<D_MODEL, 256>>>(Wq, Wk, Wv, wqkvh);
    convert_h<<<(D_MODEL*D_MODEL)/1024, 256>>>(Wo, woh);
    convert_h<<<(D_MODEL*D_FF)/1024, 256>>>(W1, w1h);
    convert_h<<<(D_FF*D_MODEL)/1024, 256>>>(W2, w2h);
    concat_bias_kernel<<<3, 1024>>>(bq, bk, bv, bqkv);

    // 1) xn = LN1(x)  (fp16 out)
    ln_kernel<<<NTOK, 256>>>(x, ln1g, ln1b, xnh);
    // 2) qkv = xn @ [Wq|Wk|Wv] + [bq|bk|bv]   (fused, N=3072, fp16 out)
    gemm_h<false,false,true><<<dim3(3*D_MODEL/256, NTOK/128), 512, GSM_TOTAL>>>(
        xnh, wqkvh, bqkv, nullptr, nullptr, qkvh, NTOK, 3*D_MODEL, D_MODEL);
    // 3) ctx = attention(q,k,v)  (fp16 in/out)
    attn_h<<<dim3(SEQ/128, BATCH*NHEAD), 256, ATT_SMEM>>>(
        qkvh, qkvh + D_MODEL, qkvh + 2*D_MODEL, ctxh, 3*D_MODEL);
    // 4) x1 = x + ctx @ Wo + bo  (f32 out)
    gemm_h<false,true,false><<<dim3(D_MODEL/256, NTOK/128), 512, GSM_TOTAL>>>(
        ctxh, woh, bo, x, x1, nullptr, NTOK, D_MODEL, D_MODEL);
    // 5) xn = LN2(x1)  (fp16 out)
    ln_kernel<<<NTOK, 256>>>(x1, ln2g, ln2b, xnh);
    // 6) ffh = relu(xn @ W1 + b1)  (fp16 out)
    gemm_h<true,false,true><<<dim3(D_FF/256, NTOK/128), 512, GSM_TOTAL>>>(
        xnh, w1h, b1, nullptr, nullptr, ffh, NTOK, D_FF, D_MODEL);
    // 7) out = x1 + ffh @ W2 + b2  (f32 out)
    gemm_h<false,true,false><<<dim3(D_MODEL/256, NTOK/128), 512, GSM_TOTAL>>>(
        ffh, w2h, b2, x1, out, nullptr, NTOK, D_MODEL, D_FF);
}

// round 7
// speedup vs baseline: 8.3745x; 1.0763x over previous
#include <cuda_runtime.h>
#include <cuda_fp16.h>
#include <cstdint>

#define D_MODEL 1024
#define D_FF    4096
#define SEQ     2048
#define BATCH   4
#define NTOK    (BATCH*SEQ)   /* 8192 */
#define NHEAD   16
#define DK      64

// ---------------- scratch (static device globals; no allocation) ----------------
__device__ __half g_xnh  [(size_t)NTOK*D_MODEL];
__device__ __half g_qkvh [(size_t)NTOK*3*D_MODEL];
__device__ __half g_ctxh [(size_t)NTOK*D_MODEL];
__device__ float  g_x1   [(size_t)NTOK*D_MODEL];
__device__ __half g_ffh  [(size_t)NTOK*D_FF];
__device__ __half g_wqkvh[(size_t)D_MODEL*3*D_MODEL];   // [K=1024][N=3072]
__device__ __half g_woh  [(size_t)D_MODEL*D_MODEL];     // [K][N]
__device__ __half g_w1h  [(size_t)D_MODEL*D_FF];        // [1024][4096]
__device__ __half g_w2h  [(size_t)D_FF*D_MODEL];        // [4096][1024]
__device__ float  g_bqkv [3*D_MODEL];

// ---------------- PTX helpers ----------------
__device__ __forceinline__ uint32_t smem_u32(const void* p) {
    uint32_t a;
    asm("{ .reg .u64 t; cvta.to.shared.u64 t, %1; cvt.u32.u64 %0, t; }"
        : "=r"(a) : "l"(p));
    return a;
}

#define LDSM4(r0, r1, r2, r3, a) \
    asm volatile("ldmatrix.sync.aligned.m8n8.x4.shared.b16 {%0,%1,%2,%3}, [%4];" \
        : "=r"(r0), "=r"(r1), "=r"(r2), "=r"(r3) : "r"(a))
#define LDSM4T(r0, r1, r2, r3, a) \
    asm volatile("ldmatrix.sync.aligned.m8n8.x4.trans.shared.b16 {%0,%1,%2,%3}, [%4];" \
        : "=r"(r0), "=r"(r1), "=r"(r2), "=r"(r3) : "r"(a))

#define CP16(dst, src) \
    asm volatile("cp.async.cg.shared.global [%0], [%1], 16;" :: "r"(dst), "l"(src))
#define CP_COMMIT() asm volatile("cp.async.commit_group;" ::: "memory")
#define CP_WAIT1()  asm volatile("cp.async.wait_group 1;" ::: "memory")

// fp16 MMA, fp32 accum: D(16x8) += A(16x16) @ B(16x8)
__device__ __forceinline__ void mma16(float* d, const uint32_t* a, const uint32_t* b) {
    asm volatile(
        "mma.sync.aligned.m16n8k16.row.col.f32.f16.f16.f32 "
        "{%0,%1,%2,%3}, {%4,%5,%6,%7}, {%8,%9}, {%0,%1,%2,%3};"
        : "+f"(d[0]), "+f"(d[1]), "+f"(d[2]), "+f"(d[3])
        : "r"(a[0]), "r"(a[1]), "r"(a[2]), "r"(a[3]), "r"(b[0]), "r"(b[1]));
}

// ---------------- LayerNorm: f32 in, fp16 out ----------------
__global__ void ln_kernel(const float* __restrict__ x,
                          const float* __restrict__ gamma,
                          const float* __restrict__ beta,
                          __half* __restrict__ y)
{
    __shared__ float sbuf[64];
    const int row = blockIdx.x;
    const int tid = threadIdx.x;
    const int lane = tid & 31, wid = tid >> 5;

    const float4 xv = ((const float4*)(x + (size_t)row * D_MODEL))[tid];
    float s  = xv.x + xv.y + xv.z + xv.w;
    float ss = xv.x*xv.x + xv.y*xv.y + xv.z*xv.z + xv.w*xv.w;
    #pragma unroll
    for (int off = 16; off; off >>= 1) {
        s  += __shfl_xor_sync(0xffffffffu, s,  off);
        ss += __shfl_xor_sync(0xffffffffu, ss, off);
    }
    if (lane == 0) { sbuf[wid] = s; sbuf[32 + wid] = ss; }
    __syncthreads();
    if (tid == 0) {
        float t = 0.f, t2 = 0.f;
        #pragma unroll
        for (int i = 0; i < 8; i++) { t += sbuf[i]; t2 += sbuf[32 + i]; }
        sbuf[16] = t; sbuf[48] = t2;
    }
    __syncthreads();
    const float mu   = sbuf[16] * (1.0f / D_MODEL);
    const float var  = sbuf[48] * (1.0f / D_MODEL) - mu * mu;
    const float rstd = rsqrtf(var + 1e-5f);

    const float4 g4 = ((const float4*)gamma)[tid];
    const float4 b4 = ((const float4*)beta)[tid];
    const float ox = (xv.x - mu) * rstd * g4.x + b4.x;
    const float oy = (xv.y - mu) * rstd * g4.y + b4.y;
    const float oz = (xv.z - mu) * rstd * g4.z + b4.z;
    const float ow = (xv.w - mu) * rstd * g4.w + b4.w;
    __half2 h0 = __floats2half2_rn(ox, oy);
    __half2 h1 = __floats2half2_rn(oz, ow);
    uint2 o;
    o.x = *(uint32_t*)&h0; o.y = *(uint32_t*)&h1;
    *(uint2*)(y + (size_t)row * D_MODEL + tid * 4) = o;
}

// ---------------- weight convert (no transpose): f32 -> f16, same layout ----------------
__global__ void convert_h(const float* __restrict__ in, __half* __restrict__ out)
{
    const size_t i = ((size_t)blockIdx.x * 256 + threadIdx.x) * 4;
    const float4 v = *(const float4*)(in + i);
    __half2 a = __floats2half2_rn(v.x, v.y);
    __half2 b = __floats2half2_rn(v.z, v.w);
    uint2 o; o.x = *(uint32_t*)&a; o.y = *(uint32_t*)&b;
    *(uint2*)(out + i) = o;
}

// qkv merge-convert: out[k][j*1024 + n] = Wj[k][n], f32 -> f16
__global__ void convert_qkv(const float* __restrict__ Wq, const float* __restrict__ Wk,
                            const float* __restrict__ Wv, __half* __restrict__ out)
{
    const int k = blockIdx.x;           // 0..1023
    const int c = threadIdx.x;          // 0..255 (float4 index within row)
    const float* srcs[3] = { Wq, Wk, Wv };
    #pragma unroll
    for (int j = 0; j < 3; j++) {
        const float4 v = ((const float4*)(srcs[j] + (size_t)k * D_MODEL))[c];
        __half2 a = __floats2half2_rn(v.x, v.y);
        __half2 b = __floats2half2_rn(v.z, v.w);
        uint2 o; o.x = *(uint32_t*)&a; o.y = *(uint32_t*)&b;
        *(uint2*)(out + (size_t)k * 3 * D_MODEL + j * D_MODEL + c * 4) = o;
    }
}

__global__ void concat_bias_kernel(const float* __restrict__ bq, const float* __restrict__ bk,
                                   const float* __restrict__ bv, float* __restrict__ o)
{
    const int i = threadIdx.x + blockIdx.x * 1024;
    const float* src = (blockIdx.x == 0) ? bq : (blockIdx.x == 1) ? bk : bv;
    o[i] = src[threadIdx.x];
}

// ---------------- fp16 tensor-core GEMM, 2 CTAs/SM ----------------
// C[M,N] = Ah[M,K](f16) @ Bh[K,N](f16) + bias (+relu) (+R).
// CTA 128x128, 4 warps (2m x 2n), warp tile 64x64, k-stage 64, 3-stage cp.async.
// smem/stage: A [128m][64k] 128B rows (16KB) + B [64k][128n] 256B rows (16KB) = 32KB.
// 3 stages = 96KB -> 2 CTAs resident per SM; sync shadows cross-covered.
#define STG_BYTES 32768
#define GSM_TOTAL (3 * STG_BYTES)     /* 98304 */

template<bool RELU, bool RESID, bool HOUT>
__global__ __launch_bounds__(128, 2)
void gemm_h(const __half* __restrict__ Ah, const __half* __restrict__ Bh,
            const float* __restrict__ bias, const float* __restrict__ R,
            float* __restrict__ Cf, __half* __restrict__ Ch, int M, int N, int K)
{
    extern __shared__ char smem[];
    const uint32_t sb = smem_u32(smem);
    const int tid  = threadIdx.x;        // 0..127
    const int lane = tid & 31;
    const int wid  = tid >> 5;           // 0..3
    const int wm   = wid & 1;
    const int wn   = wid >> 1;           // 0..1
    const int swz  = lane & 7;

    const int m0 = blockIdx.y << 7;
    const int n0 = blockIdx.x << 7;

    // A ldmatrix geometry
    const int rlA = lane & 15, clA = lane >> 4;
    // B trans-ldmatrix geometry (proven in R6 / attention-V path)
    const int kV = (lane & 7) + ((lane & 8) ? 8 : 0);
    const int cV = (lane >> 4) & 1;

    float acc[4][8][4];
    #pragma unroll
    for (int mi = 0; mi < 4; mi++)
        #pragma unroll
        for (int ni = 0; ni < 8; ni++)
            #pragma unroll
            for (int c = 0; c < 4; c++) acc[mi][ni][c] = 0.f;

    const int T = K >> 6;

    #define ISSUE_STAGE(s, buf) do { \
        const uint32_t b0_ = sb + (buf) * STG_BYTES; \
        _Pragma("unroll") \
        for (int j = 0; j < 8; j++) { \
            const int c_ = tid + j * 128, row_ = c_ >> 3, ch_ = c_ & 7; \
            CP16(b0_ + row_ * 128 + ((ch_ ^ (row_ & 7)) << 4), \
                 Ah + (size_t)(m0 + row_) * K + (s) * 64 + ch_ * 8); \
        } \
        _Pragma("unroll") \
        for (int j = 0; j < 8; j++) { \
            const int c_ = tid + j * 128, row_ = c_ >> 4, ch_ = c_ & 15; \
            const int ph_ = (ch_ & 8) | ((ch_ & 7) ^ (row_ & 7)); \
            CP16(b0_ + 16384 + row_ * 256 + (ph_ << 4), \
                 Bh + (size_t)((s) * 64 + row_) * N + n0 + ch_ * 8); \
        } \
    } while (0)

    ISSUE_STAGE(0, 0); CP_COMMIT();
    if (T > 1) ISSUE_STAGE(1, 1);
    CP_COMMIT();

    int cur = 0;
    for (int kt = 0; kt < T; kt++) {
        CP_WAIT1();
        __syncthreads();
        {
            int nb = cur + 2; if (nb >= 3) nb -= 3;
            if (kt + 2 < T) ISSUE_STAGE(kt + 2, nb);
            CP_COMMIT();
        }
        const uint32_t sA = sb + cur * STG_BYTES;
        const uint32_t sB = sA + 16384;
        #pragma unroll
        for (int s = 0; s < 4; s++) {
            uint32_t af[4][4];
            #pragma unroll
            for (int mi = 0; mi < 4; mi++) {
                const int row = wm * 64 + mi * 16 + rlA;
                LDSM4(af[mi][0], af[mi][1], af[mi][2], af[mi][3],
                      sA + row * 128 + (((2 * s + clA) ^ swz) << 4));
            }
            uint32_t bf[8][2];
            #pragma unroll
            for (int bb = 0; bb < 4; bb++) {
                const int c = wn * 8 + 2 * bb + cV;
                const int ph = (c & 8) | ((c & 7) ^ (kV & 7));
                LDSM4T(bf[2*bb][0], bf[2*bb][1], bf[2*bb+1][0], bf[2*bb+1][1],
                       sB + (16 * s + kV) * 256 + (ph << 4));
            }
            #pragma unroll
            for (int mi = 0; mi < 4; mi++)
                #pragma unroll
                for (int ni = 0; ni < 8; ni++)
                    mma16(acc[mi][ni], af[mi], bf[ni]);
        }
        cur = (cur == 2) ? 0 : cur + 1;
    }
    #undef ISSUE_STAGE

    // ---- epilogue ----
    const int g  = lane >> 2;
    const int t2 = lane & 3;
    #pragma unroll
    for (int ni = 0; ni < 8; ni++) {
        const int c = n0 + wn * 64 + ni * 8 + 2 * t2;
        const float2 bi = *(const float2*)&bias[c];
        #pragma unroll
        for (int mi = 0; mi < 4; mi++) {
            const int r0 = m0 + wm * 64 + mi * 16 + g;
            #pragma unroll
            for (int h = 0; h < 2; h++) {
                const int rr = r0 + h * 8;
                float vx = acc[mi][ni][2 * h]     + bi.x;
                float vy = acc[mi][ni][2 * h + 1] + bi.y;
                if (RELU) { vx = fmaxf(vx, 0.f); vy = fmaxf(vy, 0.f); }
                const size_t idx = (size_t)rr * N + c;
                if (RESID) {
                    const float2 rs = *(const float2*)&R[idx];
                    vx += rs.x; vy += rs.y;
                }
                if (HOUT) {
                    __half2 hv = __floats2half2_rn(vx, vy);
                    *(uint32_t*)&Ch[idx] = *(uint32_t*)&hv;
                } else {
                    float2 o; o.x = vx; o.y = vy;
                    *(float2*)&Cf[idx] = o;
                }
            }
        }
    }
}

// ---------------- fp16 flash attention, register-resident P (round-5 proven) ----------------
#define ATT_STG  16384
#define ATT_SMEM (16384 + 3 * ATT_STG)   /* 65536 */

__global__ __launch_bounds__(256, 1)
void attn_h(const __half* __restrict__ Qg, const __half* __restrict__ Kg,
            const __half* __restrict__ Vg, __half* __restrict__ O, int ld)
{
    extern __shared__ char smem[];
    const uint32_t sb = smem_u32(smem);
    const int tid  = threadIdx.x;
    const int lane = tid & 31;
    const int wid  = tid >> 5;
    const int g    = lane >> 2;
    const int t    = lane & 3;
    const int swz  = lane & 7;

    const int bh = blockIdx.y;
    const int b  = bh >> 4;
    const int h  = bh & 15;
    const int q0 = blockIdx.x << 7;

    const size_t base  = (size_t)b * SEQ * ld + (size_t)h * DK;
    const size_t obase = (size_t)b * SEQ * D_MODEL + (size_t)h * DK;

    #pragma unroll
    for (int p = 0; p < 4; p++) {
        const int c = tid + p * 256, row = c >> 3, ch = c & 7;
        *(uint4*)(smem + row * 128 + ((ch ^ (row & 7)) << 4)) =
            *(const uint4*)(Qg + base + (size_t)(q0 + row) * ld + ch * 8);
    }
    __syncthreads();

    uint32_t aq[4][4];
    {
        const int rowA = wid * 16 + (lane & 15);
        const int clA  = lane >> 4;
        #pragma unroll
        for (int kb = 0; kb < 4; kb++)
            LDSM4(aq[kb][0], aq[kb][1], aq[kb][2], aq[kb][3],
                  sb + rowA * 128 + (((2 * kb + clA) ^ swz) << 4));
    }

    const int rlB = (lane & 7) + ((lane >> 4) << 3);
    const int clB = (lane >> 3) & 1;
    const int kV  = (lane & 7) + ((lane & 8) ? 8 : 0);
    const int cV  = (lane >> 4) & 1;

    float m0v = -1e30f, m1v = -1e30f, l0 = 0.f, l1 = 0.f;
    float oacc[8][4];
    #pragma unroll
    for (int ni = 0; ni < 8; ni++)
        #pragma unroll
        for (int c = 0; c < 4; c++) oacc[ni][c] = 0.f;

    #define ISSUE_KV(s, buf) do { \
        const uint32_t kb_ = sb + 16384 + (buf) * ATT_STG; \
        _Pragma("unroll") \
        for (int j = 0; j < 2; j++) { \
            const int c_ = tid + j * 256, row_ = c_ >> 3, ch_ = c_ & 7; \
            const uint32_t off_ = row_ * 128 + ((ch_ ^ (row_ & 7)) << 4); \
            const size_t gsrc = base + (size_t)((s) * 64 + row_) * ld + ch_ * 8; \
            CP16(kb_ + off_,        Kg + gsrc); \
            CP16(kb_ + 8192 + off_, Vg + gsrc); \
        } \
    } while (0)

    ISSUE_KV(0, 0); CP_COMMIT();
    ISSUE_KV(1, 1); CP_COMMIT();

    int cur = 0;
    const int T = SEQ / 64;
    for (int kt = 0; kt < T; kt++) {
        CP_WAIT1();
        __syncthreads();
        {
            int nb = cur + 2; if (nb >= 3) nb -= 3;
            if (kt + 2 < T) ISSUE_KV(kt + 2, nb);
            CP_COMMIT();
        }
        const uint32_t kbuf = sb + 16384 + cur * ATT_STG;
        const uint32_t vbuf = kbuf + 8192;

        float sacc[8][4];
        #pragma unroll
        for (int ni = 0; ni < 8; ni++)
            #pragma unroll
            for (int c = 0; c < 4; c++) sacc[ni][c] = 0.f;

        #pragma unroll
        for (int kb = 0; kb < 4; kb++) {
            uint32_t bf[8][2];
            #pragma unroll
            for (int a = 0; a < 4; a++) {
                const int row = 16 * a + rlB;
                LDSM4(bf[2*a][0], bf[2*a][1], bf[2*a+1][0], bf[2*a+1][1],
                      kbuf + row * 128 + (((2 * kb + clB) ^ swz) << 4));
            }
            #pragma unroll
            for (int ni = 0; ni < 8; ni++)
                mma16(sacc[ni], aq[kb], bf[ni]);
        }

        #pragma unroll
        for (int ni = 0; ni < 8; ni++) {
            sacc[ni][0] *= 0.125f; sacc[ni][1] *= 0.125f;
            sacc[ni][2] *= 0.125f; sacc[ni][3] *= 0.125f;
        }
        float mx0 = -1e30f, mx1 = -1e30f;
        #pragma unroll
        for (int ni = 0; ni < 8; ni++) {
            mx0 = fmaxf(mx0, fmaxf(sacc[ni][0], sacc[ni][1]));
            mx1 = fmaxf(mx1, fmaxf(sacc[ni][2], sacc[ni][3]));
        }
        mx0 = fmaxf(mx0, __shfl_xor_sync(0xffffffffu, mx0, 1));
        mx0 = fmaxf(mx0, __shfl_xor_sync(0xffffffffu, mx0, 2));
        mx1 = fmaxf(mx1, __shfl_xor_sync(0xffffffffu, mx1, 1));
        mx1 = fmaxf(mx1, __shfl_xor_sync(0xffffffffu, mx1, 2));

        const float mn0 = fmaxf(m0v, mx0);
        const float mn1 = fmaxf(m1v, mx1);
        const float al0 = __expf(m0v - mn0);
        const float al1 = __expf(m1v - mn1);
        m0v = mn0; m1v = mn1;

        uint32_t pa[8][2];
        float sum0 = 0.f, sum1 = 0.f;
        #pragma unroll
        for (int ni = 0; ni < 8; ni++) {
            const float p0 = __expf(sacc[ni][0] - mn0);
            const float p1 = __expf(sacc[ni][1] - mn0);
            const float p2 = __expf(sacc[ni][2] - mn1);
            const float p3 = __expf(sacc[ni][3] - mn1);
            sum0 += p0 + p1; sum1 += p2 + p3;
            __half2 h0 = __floats2half2_rn(p0, p1);
            __half2 h1 = __floats2half2_rn(p2, p3);
            pa[ni][0] = *(uint32_t*)&h0;
            pa[ni][1] = *(uint32_t*)&h1;
        }
        sum0 += __shfl_xor_sync(0xffffffffu, sum0, 1);
        sum0 += __shfl_xor_sync(0xffffffffu, sum0, 2);
        sum1 += __shfl_xor_sync(0xffffffffu, sum1, 1);
        sum1 += __shfl_xor_sync(0xffffffffu, sum1, 2);
        l0 = l0 * al0 + sum0;
        l1 = l1 * al1 + sum1;

        #pragma unroll
        for (int ni = 0; ni < 8; ni++) {
            oacc[ni][0] *= al0; oacc[ni][1] *= al0;
            oacc[ni][2] *= al1; oacc[ni][3] *= al1;
        }

        #pragma unroll
        for (int kk = 0; kk < 4; kk++) {
            uint32_t bv[8][2];
            #pragma unroll
            for (int bb = 0; bb < 4; bb++) {
                const int key = 16 * kk + kV;
                LDSM4T(bv[2*bb][0], bv[2*bb][1], bv[2*bb+1][0], bv[2*bb+1][1],
                       vbuf + key * 128 + (((2 * bb + cV) ^ swz) << 4));
            }
            uint32_t ap[4] = { pa[2*kk][0], pa[2*kk][1], pa[2*kk+1][0], pa[2*kk+1][1] };
            #pragma unroll
            for (int ni = 0; ni < 8; ni++)
                mma16(oacc[ni], ap, bv[ni]);
        }

        cur = (cur == 2) ? 0 : cur + 1;
    }
    #undef ISSUE_KV

    const float inv0 = 1.f / l0;
    const float inv1 = 1.f / l1;
    const size_t row0 = obase + (size_t)(q0 + wid * 16 + g) * D_MODEL;
    const size_t row1 = row0 + (size_t)8 * D_MODEL;
    #pragma unroll
    for (int ni = 0; ni < 8; ni++) {
        const int c = ni * 8 + 2 * t;
        __half2 h0 = __floats2half2_rn(oacc[ni][0] * inv0, oacc[ni][1] * inv0);
        __half2 h1 = __floats2half2_rn(oacc[ni][2] * inv1, oacc[ni][3] * inv1);
        *(uint32_t*)&O[row0 + c] = *(uint32_t*)&h0;
        *(uint32_t*)&O[row1 + c] = *(uint32_t*)&h1;
    }
}

// ---------------- launch ----------------
extern "C" void kernel_launch(void* const* d_in, const int* in_sizes, int n_in,
                              void* d_out, int out_size)
{
    const float* x    = (const float*)d_in[0];
    const float* ln1g = (const float*)d_in[1];
    const float* ln1b = (const float*)d_in[2];
    const float* ln2g = (const float*)d_in[3];
    const float* ln2b = (const float*)d_in[4];
    const float* Wq = (const float*)d_in[5];
    const float* bq = (const float*)d_in[6];
    const float* Wk = (const float*)d_in[7];
    const float* bk = (const float*)d_in[8];
    const float* Wv = (const float*)d_in[9];
    const float* bv = (const float*)d_in[10];
    const float* Wo = (const float*)d_in[11];
    const float* bo = (const float*)d_in[12];
    const float* W1 = (const float*)d_in[13];
    const float* b1 = (const float*)d_in[14];
    const float* W2 = (const float*)d_in[15];
    const float* b2 = (const float*)d_in[16];
    float* out = (float*)d_out;

    __half *xnh, *qkvh, *ctxh, *ffh, *wqkvh, *woh, *w1h, *w2h;
    float *x1, *bqkv;
    cudaGetSymbolAddress((void**)&xnh,   g_xnh);
    cudaGetSymbolAddress((void**)&qkvh,  g_qkvh);
    cudaGetSymbolAddress((void**)&ctxh,  g_ctxh);
    cudaGetSymbolAddress((void**)&x1,    g_x1);
    cudaGetSymbolAddress((void**)&ffh,   g_ffh);
    cudaGetSymbolAddress((void**)&wqkvh, g_wqkvh);
    cudaGetSymbolAddress((void**)&woh,   g_woh);
    cudaGetSymbolAddress((void**)&w1h,   g_w1h);
    cudaGetSymbolAddress((void**)&w2h,   g_w2h);
    cudaGetSymbolAddress((void**)&bqkv,  g_bqkv);

    cudaFuncSetAttribute(attn_h, cudaFuncAttributeMaxDynamicSharedMemorySize, ATT_SMEM);
    cudaFuncSetAttribute(gemm_h<false,false,true>,  cudaFuncAttributeMaxDynamicSharedMemorySize, GSM_TOTAL);
    cudaFuncSetAttribute(gemm_h<false,true,false>,  cudaFuncAttributeMaxDynamicSharedMemorySize, GSM_TOTAL);
    cudaFuncSetAttribute(gemm_h<true,false,true>,   cudaFuncAttributeMaxDynamicSharedMemorySize, GSM_TOTAL);

    // weight converts (f32 -> f16, layout preserved [K,N]) + bias concat
    convert_qkv<<<D_MODEL, 256>>>(Wq, Wk, Wv, wqkvh);
    convert_h<<<(D_MODEL*D_MODEL)/1024, 256>>>(Wo, woh);
    convert_h<<<(D_MODEL*D_FF)/1024, 256>>>(W1, w1h);
    convert_h<<<(D_FF*D_MODEL)/1024, 256>>>(W2, w2h);
    concat_bias_kernel<<<3, 1024>>>(bq, bk, bv, bqkv);

    // 1) xn = LN1(x)  (fp16 out)
    ln_kernel<<<NTOK, 256>>>(x, ln1g, ln1b, xnh);
    // 2) qkv = xn @ [Wq|Wk|Wv] + [bq|bk|bv]   (fused, N=3072, fp16 out)
    gemm_h<false,false,true><<<dim3(3*D_MODEL/128, NTOK/128), 128, GSM_TOTAL>>>(
        xnh, wqkvh, bqkv, nullptr, nullptr, qkvh, NTOK, 3*D_MODEL, D_MODEL);
    // 3) ctx = attention(q,k,v)  (fp16 in/out)
    attn_h<<<dim3(SEQ/128, BATCH*NHEAD), 256, ATT_SMEM>>>(
        qkvh, qkvh + D_MODEL, qkvh + 2*D_MODEL, ctxh, 3*D_MODEL);
    // 4) x1 = x + ctx @ Wo + bo  (f32 out)
    gemm_h<false,true,false><<<dim3(D_MODEL/128, NTOK/128), 128, GSM_TOTAL>>>(
        ctxh, woh, bo, x, x1, nullptr, NTOK, D_MODEL, D_MODEL);
    // 5) xn = LN2(x1)  (fp16 out)
    ln_kernel<<<NTOK, 256>>>(x1, ln2g, ln2b, xnh);
    // 6) ffh = relu(xn @ W1 + b1)  (fp16 out)
    gemm_h<true,false,true><<<dim3(D_FF/128, NTOK/128), 128, GSM_TOTAL>>>(
        xnh, w1h, b1, nullptr, nullptr, ffh, NTOK, D_FF, D_MODEL);
    // 7) out = x1 + ffh @ W2 + b2  (f32 out)
    gemm_h<false,true,false><<<dim3(D_MODEL/128, NTOK/128), 128, GSM_TOTAL>>>(
        ffh, w2h, b2, x1, out, nullptr, NTOK, D_MODEL, D_FF);
}

// round 8
// speedup vs baseline: 8.4024x; 1.0033x over previous
#include <cuda_runtime.h>
#include <cuda_fp16.h>
#include <cstdint>

#define D_MODEL 1024
#define D_FF    4096
#define SEQ     2048
#define BATCH   4
#define NTOK    (BATCH*SEQ)   /* 8192 */
#define NHEAD   16
#define DK      64

// ---------------- scratch (static device globals; no allocation) ----------------
__device__ __half g_xnh  [(size_t)NTOK*D_MODEL];
__device__ __half g_qkvh [(size_t)NTOK*3*D_MODEL];
__device__ __half g_ctxh [(size_t)NTOK*D_MODEL];
__device__ float  g_x1   [(size_t)NTOK*D_MODEL];
__device__ __half g_ffh  [(size_t)NTOK*D_FF];
__device__ __half g_wqkvh[(size_t)D_MODEL*3*D_MODEL];   // [K=1024][N=3072]
__device__ __half g_woh  [(size_t)D_MODEL*D_MODEL];     // [K][N]
__device__ __half g_w1h  [(size_t)D_MODEL*D_FF];        // [1024][4096]
__device__ __half g_w2h  [(size_t)D_FF*D_MODEL];        // [4096][1024]
__device__ float  g_bqkv [3*D_MODEL];

// ---------------- PTX helpers ----------------
__device__ __forceinline__ uint32_t smem_u32(const void* p) {
    uint32_t a;
    asm("{ .reg .u64 t; cvta.to.shared.u64 t, %1; cvt.u32.u64 %0, t; }"
        : "=r"(a) : "l"(p));
    return a;
}

#define LDSM4(r0, r1, r2, r3, a) \
    asm volatile("ldmatrix.sync.aligned.m8n8.x4.shared.b16 {%0,%1,%2,%3}, [%4];" \
        : "=r"(r0), "=r"(r1), "=r"(r2), "=r"(r3) : "r"(a))
#define LDSM4T(r0, r1, r2, r3, a) \
    asm volatile("ldmatrix.sync.aligned.m8n8.x4.trans.shared.b16 {%0,%1,%2,%3}, [%4];" \
        : "=r"(r0), "=r"(r1), "=r"(r2), "=r"(r3) : "r"(a))

#define CP16(dst, src) \
    asm volatile("cp.async.cg.shared.global [%0], [%1], 16;" :: "r"(dst), "l"(src))
#define CP_COMMIT() asm volatile("cp.async.commit_group;" ::: "memory")
#define CP_WAIT1()  asm volatile("cp.async.wait_group 1;" ::: "memory")

// fp16 MMA, fp32 accum: D(16x8) += A(16x16) @ B(16x8)
__device__ __forceinline__ void mma16(float* d, const uint32_t* a, const uint32_t* b) {
    asm volatile(
        "mma.sync.aligned.m16n8k16.row.col.f32.f16.f16.f32 "
        "{%0,%1,%2,%3}, {%4,%5,%6,%7}, {%8,%9}, {%0,%1,%2,%3};"
        : "+f"(d[0]), "+f"(d[1]), "+f"(d[2]), "+f"(d[3])
        : "r"(a[0]), "r"(a[1]), "r"(a[2]), "r"(a[3]), "r"(b[0]), "r"(b[1]));
}

// ---------------- LayerNorm: f32 in, fp16 out ----------------
__global__ void ln_kernel(const float* __restrict__ x,
                          const float* __restrict__ gamma,
                          const float* __restrict__ beta,
                          __half* __restrict__ y)
{
    __shared__ float sbuf[64];
    const int row = blockIdx.x;
    const int tid = threadIdx.x;
    const int lane = tid & 31, wid = tid >> 5;

    const float4 xv = ((const float4*)(x + (size_t)row * D_MODEL))[tid];
    float s  = xv.x + xv.y + xv.z + xv.w;
    float ss = xv.x*xv.x + xv.y*xv.y + xv.z*xv.z + xv.w*xv.w;
    #pragma unroll
    for (int off = 16; off; off >>= 1) {
        s  += __shfl_xor_sync(0xffffffffu, s,  off);
        ss += __shfl_xor_sync(0xffffffffu, ss, off);
    }
    if (lane == 0) { sbuf[wid] = s; sbuf[32 + wid] = ss; }
    __syncthreads();
    if (tid == 0) {
        float t = 0.f, t2 = 0.f;
        #pragma unroll
        for (int i = 0; i < 8; i++) { t += sbuf[i]; t2 += sbuf[32 + i]; }
        sbuf[16] = t; sbuf[48] = t2;
    }
    __syncthreads();
    const float mu   = sbuf[16] * (1.0f / D_MODEL);
    const float var  = sbuf[48] * (1.0f / D_MODEL) - mu * mu;
    const float rstd = rsqrtf(var + 1e-5f);

    const float4 g4 = ((const float4*)gamma)[tid];
    const float4 b4 = ((const float4*)beta)[tid];
    const float ox = (xv.x - mu) * rstd * g4.x + b4.x;
    const float oy = (xv.y - mu) * rstd * g4.y + b4.y;
    const float oz = (xv.z - mu) * rstd * g4.z + b4.z;
    const float ow = (xv.w - mu) * rstd * g4.w + b4.w;
    __half2 h0 = __floats2half2_rn(ox, oy);
    __half2 h1 = __floats2half2_rn(oz, ow);
    uint2 o;
    o.x = *(uint32_t*)&h0; o.y = *(uint32_t*)&h1;
    *(uint2*)(y + (size_t)row * D_MODEL + tid * 4) = o;
}

// ---------------- weight convert (no transpose): f32 -> f16, same layout ----------------
__global__ void convert_h(const float* __restrict__ in, __half* __restrict__ out)
{
    const size_t i = ((size_t)blockIdx.x * 256 + threadIdx.x) * 4;
    const float4 v = *(const float4*)(in + i);
    __half2 a = __floats2half2_rn(v.x, v.y);
    __half2 b = __floats2half2_rn(v.z, v.w);
    uint2 o; o.x = *(uint32_t*)&a; o.y = *(uint32_t*)&b;
    *(uint2*)(out + i) = o;
}

// qkv merge-convert: out[k][j*1024 + n] = Wj[k][n], f32 -> f16
__global__ void convert_qkv(const float* __restrict__ Wq, const float* __restrict__ Wk,
                            const float* __restrict__ Wv, __half* __restrict__ out)
{
    const int k = blockIdx.x;           // 0..1023
    const int c = threadIdx.x;          // 0..255 (float4 index within row)
    const float* srcs[3] = { Wq, Wk, Wv };
    #pragma unroll
    for (int j = 0; j < 3; j++) {
        const float4 v = ((const float4*)(srcs[j] + (size_t)k * D_MODEL))[c];
        __half2 a = __floats2half2_rn(v.x, v.y);
        __half2 b = __floats2half2_rn(v.z, v.w);
        uint2 o; o.x = *(uint32_t*)&a; o.y = *(uint32_t*)&b;
        *(uint2*)(out + (size_t)k * 3 * D_MODEL + j * D_MODEL + c * 4) = o;
    }
}

__global__ void concat_bias_kernel(const float* __restrict__ bq, const float* __restrict__ bk,
                                   const float* __restrict__ bv, float* __restrict__ o)
{
    const int i = threadIdx.x + blockIdx.x * 1024;
    const float* src = (blockIdx.x == 0) ? bq : (blockIdx.x == 1) ? bk : bv;
    o[i] = src[threadIdx.x];
}

// ---------------- fp16 tensor-core GEMM, 2 CTAs/SM, reg double-buffered ----------------
// C[M,N] = Ah[M,K](f16) @ Bh[K,N](f16) + bias (+relu) (+R).
// CTA 128x128, 4 warps (2m x 2n), warp tile 64x64, k-stage 64, 3-stage cp.async.
// Fragment registers double-buffered: LDSM for s+1 overlaps MMAs of s.
#define STG_BYTES 32768
#define GSM_TOTAL (3 * STG_BYTES)     /* 98304 */

template<bool RELU, bool RESID, bool HOUT>
__global__ __launch_bounds__(128, 2)
void gemm_h(const __half* __restrict__ Ah, const __half* __restrict__ Bh,
            const float* __restrict__ bias, const float* __restrict__ R,
            float* __restrict__ Cf, __half* __restrict__ Ch, int M, int N, int K)
{
    extern __shared__ char smem[];
    const uint32_t sb = smem_u32(smem);
    const int tid  = threadIdx.x;        // 0..127
    const int lane = tid & 31;
    const int wid  = tid >> 5;           // 0..3
    const int wm   = wid & 1;
    const int wn   = wid >> 1;           // 0..1
    const int swz  = lane & 7;

    const int m0 = blockIdx.y << 7;
    const int n0 = blockIdx.x << 7;

    // A ldmatrix geometry
    const int rlA = lane & 15, clA = lane >> 4;
    // B trans-ldmatrix geometry
    const int kV = (lane & 7) + ((lane & 8) ? 8 : 0);
    const int cV = (lane >> 4) & 1;

    float acc[4][8][4];
    #pragma unroll
    for (int mi = 0; mi < 4; mi++)
        #pragma unroll
        for (int ni = 0; ni < 8; ni++)
            #pragma unroll
            for (int c = 0; c < 4; c++) acc[mi][ni][c] = 0.f;

    const int T = K >> 6;

    #define ISSUE_STAGE(s, buf) do { \
        const uint32_t b0_ = sb + (buf) * STG_BYTES; \
        _Pragma("unroll") \
        for (int j = 0; j < 8; j++) { \
            const int c_ = tid + j * 128, row_ = c_ >> 3, ch_ = c_ & 7; \
            CP16(b0_ + row_ * 128 + ((ch_ ^ (row_ & 7)) << 4), \
                 Ah + (size_t)(m0 + row_) * K + (s) * 64 + ch_ * 8); \
        } \
        _Pragma("unroll") \
        for (int j = 0; j < 8; j++) { \
            const int c_ = tid + j * 128, row_ = c_ >> 4, ch_ = c_ & 15; \
            const int ph_ = (ch_ & 8) | ((ch_ & 7) ^ (row_ & 7)); \
            CP16(b0_ + 16384 + row_ * 256 + (ph_ << 4), \
                 Bh + (size_t)((s) * 64 + row_) * N + n0 + ch_ * 8); \
        } \
    } while (0)

    // Load fragments for k8-step s_ of the current k-tile into buffers a_/b_
    #define LOAD_FRAGS(a_, b_, s_) do { \
        _Pragma("unroll") \
        for (int mi = 0; mi < 4; mi++) { \
            const int row = wm * 64 + mi * 16 + rlA; \
            LDSM4((a_)[mi][0], (a_)[mi][1], (a_)[mi][2], (a_)[mi][3], \
                  sA + row * 128 + (((2 * (s_) + clA) ^ swz) << 4)); \
        } \
        _Pragma("unroll") \
        for (int bb = 0; bb < 4; bb++) { \
            const int c = wn * 8 + 2 * bb + cV; \
            const int ph = (c & 8) | ((c & 7) ^ (kV & 7)); \
            LDSM4T((b_)[2*bb][0], (b_)[2*bb][1], (b_)[2*bb+1][0], (b_)[2*bb+1][1], \
                   sB + (16 * (s_) + kV) * 256 + (ph << 4)); \
        } \
    } while (0)

    ISSUE_STAGE(0, 0); CP_COMMIT();
    if (T > 1) ISSUE_STAGE(1, 1);
    CP_COMMIT();

    uint32_t af[2][4][4], bf[2][8][2];

    int cur = 0;
    for (int kt = 0; kt < T; kt++) {
        CP_WAIT1();
        __syncthreads();
        {
            int nb = cur + 2; if (nb >= 3) nb -= 3;
            if (kt + 2 < T) ISSUE_STAGE(kt + 2, nb);
            CP_COMMIT();
        }
        const uint32_t sA = sb + cur * STG_BYTES;
        const uint32_t sB = sA + 16384;

        LOAD_FRAGS(af[0], bf[0], 0);
        #pragma unroll
        for (int s = 0; s < 4; s++) {
            const int cb = s & 1;
            if (s < 3) LOAD_FRAGS(af[cb ^ 1], bf[cb ^ 1], s + 1);
            #pragma unroll
            for (int mi = 0; mi < 4; mi++)
                #pragma unroll
                for (int ni = 0; ni < 8; ni++)
                    mma16(acc[mi][ni], af[cb][mi], bf[cb][ni]);
        }
        cur = (cur == 2) ? 0 : cur + 1;
    }
    #undef ISSUE_STAGE
    #undef LOAD_FRAGS

    // ---- epilogue ----
    const int g  = lane >> 2;
    const int t2 = lane & 3;
    #pragma unroll
    for (int ni = 0; ni < 8; ni++) {
        const int c = n0 + wn * 64 + ni * 8 + 2 * t2;
        const float2 bi = *(const float2*)&bias[c];
        #pragma unroll
        for (int mi = 0; mi < 4; mi++) {
            const int r0 = m0 + wm * 64 + mi * 16 + g;
            #pragma unroll
            for (int h = 0; h < 2; h++) {
                const int rr = r0 + h * 8;
                float vx = acc[mi][ni][2 * h]     + bi.x;
                float vy = acc[mi][ni][2 * h + 1] + bi.y;
                if (RELU) { vx = fmaxf(vx, 0.f); vy = fmaxf(vy, 0.f); }
                const size_t idx = (size_t)rr * N + c;
                if (RESID) {
                    const float2 rs = *(const float2*)&R[idx];
                    vx += rs.x; vy += rs.y;
                }
                if (HOUT) {
                    __half2 hv = __floats2half2_rn(vx, vy);
                    *(uint32_t*)&Ch[idx] = *(uint32_t*)&hv;
                } else {
                    float2 o; o.x = vx; o.y = vy;
                    *(float2*)&Cf[idx] = o;
                }
            }
        }
    }
}

// ---------------- fp16 flash attention, register-resident P (round-5 proven) ----------------
#define ATT_STG  16384
#define ATT_SMEM (16384 + 3 * ATT_STG)   /* 65536 */

__global__ __launch_bounds__(256, 1)
void attn_h(const __half* __restrict__ Qg, const __half* __restrict__ Kg,
            const __half* __restrict__ Vg, __half* __restrict__ O, int ld)
{
    extern __shared__ char smem[];
    const uint32_t sb = smem_u32(smem);
    const int tid  = threadIdx.x;
    const int lane = tid & 31;
    const int wid  = tid >> 5;
    const int g    = lane >> 2;
    const int t    = lane & 3;
    const int swz  = lane & 7;

    const int bh = blockIdx.y;
    const int b  = bh >> 4;
    const int h  = bh & 15;
    const int q0 = blockIdx.x << 7;

    const size_t base  = (size_t)b * SEQ * ld + (size_t)h * DK;
    const size_t obase = (size_t)b * SEQ * D_MODEL + (size_t)h * DK;

    #pragma unroll
    for (int p = 0; p < 4; p++) {
        const int c = tid + p * 256, row = c >> 3, ch = c & 7;
        *(uint4*)(smem + row * 128 + ((ch ^ (row & 7)) << 4)) =
            *(const uint4*)(Qg + base + (size_t)(q0 + row) * ld + ch * 8);
    }
    __syncthreads();

    uint32_t aq[4][4];
    {
        const int rowA = wid * 16 + (lane & 15);
        const int clA  = lane >> 4;
        #pragma unroll
        for (int kb = 0; kb < 4; kb++)
            LDSM4(aq[kb][0], aq[kb][1], aq[kb][2], aq[kb][3],
                  sb + rowA * 128 + (((2 * kb + clA) ^ swz) << 4));
    }

    const int rlB = (lane & 7) + ((lane >> 4) << 3);
    const int clB = (lane >> 3) & 1;
    const int kV  = (lane & 7) + ((lane & 8) ? 8 : 0);
    const int cV  = (lane >> 4) & 1;

    float m0v = -1e30f, m1v = -1e30f, l0 = 0.f, l1 = 0.f;
    float oacc[8][4];
    #pragma unroll
    for (int ni = 0; ni < 8; ni++)
        #pragma unroll
        for (int c = 0; c < 4; c++) oacc[ni][c] = 0.f;

    #define ISSUE_KV(s, buf) do { \
        const uint32_t kb_ = sb + 16384 + (buf) * ATT_STG; \
        _Pragma("unroll") \
        for (int j = 0; j < 2; j++) { \
            const int c_ = tid + j * 256, row_ = c_ >> 3, ch_ = c_ & 7; \
            const uint32_t off_ = row_ * 128 + ((ch_ ^ (row_ & 7)) << 4); \
            const size_t gsrc = base + (size_t)((s) * 64 + row_) * ld + ch_ * 8; \
            CP16(kb_ + off_,        Kg + gsrc); \
            CP16(kb_ + 8192 + off_, Vg + gsrc); \
        } \
    } while (0)

    ISSUE_KV(0, 0); CP_COMMIT();
    ISSUE_KV(1, 1); CP_COMMIT();

    int cur = 0;
    const int T = SEQ / 64;
    for (int kt = 0; kt < T; kt++) {
        CP_WAIT1();
        __syncthreads();
        {
            int nb = cur + 2; if (nb >= 3) nb -= 3;
            if (kt + 2 < T) ISSUE_KV(kt + 2, nb);
            CP_COMMIT();
        }
        const uint32_t kbuf = sb + 16384 + cur * ATT_STG;
        const uint32_t vbuf = kbuf + 8192;

        float sacc[8][4];
        #pragma unroll
        for (int ni = 0; ni < 8; ni++)
            #pragma unroll
            for (int c = 0; c < 4; c++) sacc[ni][c] = 0.f;

        #pragma unroll
        for (int kb = 0; kb < 4; kb++) {
            uint32_t bf[8][2];
            #pragma unroll
            for (int a = 0; a < 4; a++) {
                const int row = 16 * a + rlB;
                LDSM4(bf[2*a][0], bf[2*a][1], bf[2*a+1][0], bf[2*a+1][1],
                      kbuf + row * 128 + (((2 * kb + clB) ^ swz) << 4));
            }
            #pragma unroll
            for (int ni = 0; ni < 8; ni++)
                mma16(sacc[ni], aq[kb], bf[ni]);
        }

        #pragma unroll
        for (int ni = 0; ni < 8; ni++) {
            sacc[ni][0] *= 0.125f; sacc[ni][1] *= 0.125f;
            sacc[ni][2] *= 0.125f; sacc[ni][3] *= 0.125f;
        }
        float mx0 = -1e30f, mx1 = -1e30f;
        #pragma unroll
        for (int ni = 0; ni < 8; ni++) {
            mx0 = fmaxf(mx0, fmaxf(sacc[ni][0], sacc[ni][1]));
            mx1 = fmaxf(mx1, fmaxf(sacc[ni][2], sacc[ni][3]));
        }
        mx0 = fmaxf(mx0, __shfl_xor_sync(0xffffffffu, mx0, 1));
        mx0 = fmaxf(mx0, __shfl_xor_sync(0xffffffffu, mx0, 2));
        mx1 = fmaxf(mx1, __shfl_xor_sync(0xffffffffu, mx1, 1));
        mx1 = fmaxf(mx1, __shfl_xor_sync(0xffffffffu, mx1, 2));

        const float mn0 = fmaxf(m0v, mx0);
        const float mn1 = fmaxf(m1v, mx1);
        const float al0 = __expf(m0v - mn0);
        const float al1 = __expf(m1v - mn1);
        m0v = mn0; m1v = mn1;

        uint32_t pa[8][2];
        float sum0 = 0.f, sum1 = 0.f;
        #pragma unroll
        for (int ni = 0; ni < 8; ni++) {
            const float p0 = __expf(sacc[ni][0] - mn0);
            const float p1 = __expf(sacc[ni][1] - mn0);
            const float p2 = __expf(sacc[ni][2] - mn1);
            const float p3 = __expf(sacc[ni][3] - mn1);
            sum0 += p0 + p1; sum1 += p2 + p3;
            __half2 h0 = __floats2half2_rn(p0, p1);
            __half2 h1 = __floats2half2_rn(p2, p3);
            pa[ni][0] = *(uint32_t*)&h0;
            pa[ni][1] = *(uint32_t*)&h1;
        }
        sum0 += __shfl_xor_sync(0xffffffffu, sum0, 1);
        sum0 += __shfl_xor_sync(0xffffffffu, sum0, 2);
        sum1 += __shfl_xor_sync(0xffffffffu, sum1, 1);
        sum1 += __shfl_xor_sync(0xffffffffu, sum1, 2);
        l0 = l0 * al0 + sum0;
        l1 = l1 * al1 + sum1;

        #pragma unroll
        for (int ni = 0; ni < 8; ni++) {
            oacc[ni][0] *= al0; oacc[ni][1] *= al0;
            oacc[ni][2] *= al1; oacc[ni][3] *= al1;
        }

        #pragma unroll
        for (int kk = 0; kk < 4; kk++) {
            uint32_t bv[8][2];
            #pragma unroll
            for (int bb = 0; bb < 4; bb++) {
                const int key = 16 * kk + kV;
                LDSM4T(bv[2*bb][0], bv[2*bb][1], bv[2*bb+1][0], bv[2*bb+1][1],
                       vbuf + key * 128 + (((2 * bb + cV) ^ swz) << 4));
            }
            uint32_t ap[4] = { pa[2*kk][0], pa[2*kk][1], pa[2*kk+1][0], pa[2*kk+1][1] };
            #pragma unroll
            for (int ni = 0; ni < 8; ni++)
                mma16(oacc[ni], ap, bv[ni]);
        }

        cur = (cur == 2) ? 0 : cur + 1;
    }
    #undef ISSUE_KV

    const float inv0 = 1.f / l0;
    const float inv1 = 1.f / l1;
    const size_t row0 = obase + (size_t)(q0 + wid * 16 + g) * D_MODEL;
    const size_t row1 = row0 + (size_t)8 * D_MODEL;
    #pragma unroll
    for (int ni = 0; ni < 8; ni++) {
        const int c = ni * 8 + 2 * t;
        __half2 h0 = __floats2half2_rn(oacc[ni][0] * inv0, oacc[ni][1] * inv0);
        __half2 h1 = __floats2half2_rn(oacc[ni][2] * inv1, oacc[ni][3] * inv1);
        *(uint32_t*)&O[row0 + c] = *(uint32_t*)&h0;
        *(uint32_t*)&O[row1 + c] = *(uint32_t*)&h1;
    }
}

// ---------------- launch ----------------
extern "C" void kernel_launch(void* const* d_in, const int* in_sizes, int n_in,
                              void* d_out, int out_size)
{
    const float* x    = (const float*)d_in[0];
    const float* ln1g = (const float*)d_in[1];
    const float* ln1b = (const float*)d_in[2];
    const float* ln2g = (const float*)d_in[3];
    const float* ln2b = (const float*)d_in[4];
    const float* Wq = (const float*)d_in[5];
    const float* bq = (const float*)d_in[6];
    const float* Wk = (const float*)d_in[7];
    const float* bk = (const float*)d_in[8];
    const float* Wv = (const float*)d_in[9];
    const float* bv = (const float*)d_in[10];
    const float* Wo = (const float*)d_in[11];
    const float* bo = (const float*)d_in[12];
    const float* W1 = (const float*)d_in[13];
    const float* b1 = (const float*)d_in[14];
    const float* W2 = (const float*)d_in[15];
    const float* b2 = (const float*)d_in[16];
    float* out = (float*)d_out;

    __half *xnh, *qkvh, *ctxh, *ffh, *wqkvh, *woh, *w1h, *w2h;
    float *x1, *bqkv;
    cudaGetSymbolAddress((void**)&xnh,   g_xnh);
    cudaGetSymbolAddress((void**)&qkvh,  g_qkvh);
    cudaGetSymbolAddress((void**)&ctxh,  g_ctxh);
    cudaGetSymbolAddress((void**)&x1,    g_x1);
    cudaGetSymbolAddress((void**)&ffh,   g_ffh);
    cudaGetSymbolAddress((void**)&wqkvh, g_wqkvh);
    cudaGetSymbolAddress((void**)&woh,   g_woh);
    cudaGetSymbolAddress((void**)&w1h,   g_w1h);
    cudaGetSymbolAddress((void**)&w2h,   g_w2h);
    cudaGetSymbolAddress((void**)&bqkv,  g_bqkv);

    cudaFuncSetAttribute(attn_h, cudaFuncAttributeMaxDynamicSharedMemorySize, ATT_SMEM);
    cudaFuncSetAttribute(gemm_h<false,false,true>,  cudaFuncAttributeMaxDynamicSharedMemorySize, GSM_TOTAL);
    cudaFuncSetAttribute(gemm_h<false,true,false>,  cudaFuncAttributeMaxDynamicSharedMemorySize, GSM_TOTAL);
    cudaFuncSetAttribute(gemm_h<true,false,true>,   cudaFuncAttributeMaxDynamicSharedMemorySize, GSM_TOTAL);

    // weight converts (f32 -> f16, layout preserved [K,N]) + bias concat
    convert_qkv<<<D_MODEL, 256>>>(Wq, Wk, Wv, wqkvh);
    convert_h<<<(D_MODEL*D_MODEL)/1024, 256>>>(Wo, woh);
    convert_h<<<(D_MODEL*D_FF)/1024, 256>>>(W1, w1h);
    convert_h<<<(D_FF*D_MODEL)/1024, 256>>>(W2, w2h);
    concat_bias_kernel<<<3, 1024>>>(bq, bk, bv, bqkv);

    // 1) xn = LN1(x)  (fp16 out)
    ln_kernel<<<NTOK, 256>>>(x, ln1g, ln1b, xnh);
    // 2) qkv = xn @ [Wq|Wk|Wv] + [bq|bk|bv]   (fused, N=3072, fp16 out)
    gemm_h<false,false,true><<<dim3(3*D_MODEL/128, NTOK/128), 128, GSM_TOTAL>>>(
        xnh, wqkvh, bqkv, nullptr, nullptr, qkvh, NTOK, 3*D_MODEL, D_MODEL);
    // 3) ctx = attention(q,k,v)  (fp16 in/out)
    attn_h<<<dim3(SEQ/128, BATCH*NHEAD), 256, ATT_SMEM>>>(
        qkvh, qkvh + D_MODEL, qkvh + 2*D_MODEL, ctxh, 3*D_MODEL);
    // 4) x1 = x + ctx @ Wo + bo  (f32 out)
    gemm_h<false,true,false><<<dim3(D_MODEL/128, NTOK/128), 128, GSM_TOTAL>>>(
        ctxh, woh, bo, x, x1, nullptr, NTOK, D_MODEL, D_MODEL);
    // 5) xn = LN2(x1)  (fp16 out)
    ln_kernel<<<NTOK, 256>>>(x1, ln2g, ln2b, xnh);
    // 6) ffh = relu(xn @ W1 + b1)  (fp16 out)
    gemm_h<true,false,true><<<dim3(D_FF/128, NTOK/128), 128, GSM_TOTAL>>>(
        xnh, w1h, b1, nullptr, nullptr, ffh, NTOK, D_FF, D_MODEL);
    // 7) out = x1 + ffh @ W2 + b2  (f32 out)
    gemm_h<false,true,false><<<dim3(D_MODEL/128, NTOK/128), 128, GSM_TOTAL>>>(
        ffh, w2h, b2, x1, out, nullptr, NTOK, D_MODEL, D_FF);
}

// round 9
// speedup vs baseline: 8.4680x; 1.0078x over previous
#include <cuda_runtime.h>
#include <cuda_fp16.h>
#include <cstdint>

#define D_MODEL 1024
#define D_FF    4096
#define SEQ     2048
#define BATCH   4
#define NTOK    (BATCH*SEQ)   /* 8192 */
#define NHEAD   16
#define DK      64

// ---------------- scratch (static device globals; no allocation) ----------------
__device__ __half g_xnh  [(size_t)NTOK*D_MODEL];
__device__ __half g_qkvh [(size_t)NTOK*3*D_MODEL];
__device__ __half g_ctxh [(size_t)NTOK*D_MODEL];
__device__ float  g_x1   [(size_t)NTOK*D_MODEL];
__device__ __half g_ffh  [(size_t)NTOK*D_FF];
__device__ __half g_wqkvh[(size_t)D_MODEL*3*D_MODEL];   // [K=1024][N=3072]
__device__ __half g_woh  [(size_t)D_MODEL*D_MODEL];     // [K][N]
__device__ __half g_w1h  [(size_t)D_MODEL*D_FF];        // [1024][4096]
__device__ __half g_w2h  [(size_t)D_FF*D_MODEL];        // [4096][1024]
__device__ float  g_bqkv [3*D_MODEL];

// ---------------- PTX helpers ----------------
__device__ __forceinline__ uint32_t smem_u32(const void* p) {
    uint32_t a;
    asm("{ .reg .u64 t; cvta.to.shared.u64 t, %1; cvt.u32.u64 %0, t; }"
        : "=r"(a) : "l"(p));
    return a;
}

#define LDSM4(r0, r1, r2, r3, a) \
    asm volatile("ldmatrix.sync.aligned.m8n8.x4.shared.b16 {%0,%1,%2,%3}, [%4];" \
        : "=r"(r0), "=r"(r1), "=r"(r2), "=r"(r3) : "r"(a))
#define LDSM4T(r0, r1, r2, r3, a) \
    asm volatile("ldmatrix.sync.aligned.m8n8.x4.trans.shared.b16 {%0,%1,%2,%3}, [%4];" \
        : "=r"(r0), "=r"(r1), "=r"(r2), "=r"(r3) : "r"(a))

#define CP16(dst, src) \
    asm volatile("cp.async.cg.shared.global [%0], [%1], 16;" :: "r"(dst), "l"(src))
#define CP_COMMIT() asm volatile("cp.async.commit_group;" ::: "memory")
#define CP_WAIT1()  asm volatile("cp.async.wait_group 1;" ::: "memory")

// fp16 MMA, fp32 accum: D(16x8) += A(16x16) @ B(16x8)
__device__ __forceinline__ void mma16(float* d, const uint32_t* a, const uint32_t* b) {
    asm volatile(
        "mma.sync.aligned.m16n8k16.row.col.f32.f16.f16.f32 "
        "{%0,%1,%2,%3}, {%4,%5,%6,%7}, {%8,%9}, {%0,%1,%2,%3};"
        : "+f"(d[0]), "+f"(d[1]), "+f"(d[2]), "+f"(d[3])
        : "r"(a[0]), "r"(a[1]), "r"(a[2]), "r"(a[3]), "r"(b[0]), "r"(b[1]));
}

// ---------------- LayerNorm: warp-per-row, MLP=8, f32 in fp16 out ----------------
// block = 256 thr = 8 rows; grid = NTOK/8
__global__ void ln_kernel(const float* __restrict__ x,
                          const float* __restrict__ gamma,
                          const float* __restrict__ beta,
                          __half* __restrict__ y)
{
    const int lane = threadIdx.x & 31;
    const int wrp  = threadIdx.x >> 5;
    const int row  = blockIdx.x * 8 + wrp;

    const float4* xr = (const float4*)(x + (size_t)row * D_MODEL);
    float4 v[8];
    #pragma unroll
    for (int i = 0; i < 8; i++) v[i] = xr[lane + 32 * i];

    float s = 0.f, ss = 0.f;
    #pragma unroll
    for (int i = 0; i < 8; i++) {
        s  += v[i].x + v[i].y + v[i].z + v[i].w;
        ss += v[i].x*v[i].x + v[i].y*v[i].y + v[i].z*v[i].z + v[i].w*v[i].w;
    }
    #pragma unroll
    for (int off = 16; off; off >>= 1) {
        s  += __shfl_xor_sync(0xffffffffu, s,  off);
        ss += __shfl_xor_sync(0xffffffffu, ss, off);
    }
    const float mu   = s * (1.0f / D_MODEL);
    const float var  = ss * (1.0f / D_MODEL) - mu * mu;
    const float rstd = rsqrtf(var + 1e-5f);

    __half* yr = y + (size_t)row * D_MODEL;
    #pragma unroll
    for (int i = 0; i < 8; i++) {
        const int e = lane + 32 * i;
        const float4 g4 = ((const float4*)gamma)[e];
        const float4 b4 = ((const float4*)beta)[e];
        const float ox = (v[i].x - mu) * rstd * g4.x + b4.x;
        const float oy = (v[i].y - mu) * rstd * g4.y + b4.y;
        const float oz = (v[i].z - mu) * rstd * g4.z + b4.z;
        const float ow = (v[i].w - mu) * rstd * g4.w + b4.w;
        __half2 h0 = __floats2half2_rn(ox, oy);
        __half2 h1 = __floats2half2_rn(oz, ow);
        uint2 o; o.x = *(uint32_t*)&h0; o.y = *(uint32_t*)&h1;
        *(uint2*)(yr + e * 4) = o;
    }
}

// ---------------- weight convert: f32 -> f16, 4 float4/thread (MLP=4) ----------------
// grid = elems/4096, block 256
__global__ void convert_h(const float* __restrict__ in, __half* __restrict__ out)
{
    const size_t b0 = (size_t)blockIdx.x * 4096 + threadIdx.x * 4;
    float4 v[4];
    #pragma unroll
    for (int j = 0; j < 4; j++) v[j] = *(const float4*)(in + b0 + j * 1024);
    #pragma unroll
    for (int j = 0; j < 4; j++) {
        __half2 a = __floats2half2_rn(v[j].x, v[j].y);
        __half2 b = __floats2half2_rn(v[j].z, v[j].w);
        uint2 o; o.x = *(uint32_t*)&a; o.y = *(uint32_t*)&b;
        *(uint2*)(out + b0 + j * 1024) = o;
    }
}

// qkv merge-convert: out[k][j*1024 + n] = Wj[k][n]; 2 rows x 3 srcs per block (MLP=6)
__global__ void convert_qkv(const float* __restrict__ Wq, const float* __restrict__ Wk,
                            const float* __restrict__ Wv, float* __restrict__ bqkv,
                            const float* __restrict__ bq, const float* __restrict__ bk,
                            const float* __restrict__ bv, __half* __restrict__ out)
{
    const int k0 = blockIdx.x * 2;            // grid 512
    const int c  = threadIdx.x;               // 0..255 (float4 index within row)
    const int kk = c >> 7;                     // not used for split; each thread does both rows
    (void)kk;
    const float* srcs[3] = { Wq, Wk, Wv };
    float4 v[2][3];
    #pragma unroll
    for (int r = 0; r < 2; r++)
        #pragma unroll
        for (int j = 0; j < 3; j++)
            v[r][j] = ((const float4*)(srcs[j] + (size_t)(k0 + r) * D_MODEL))[c];
    #pragma unroll
    for (int r = 0; r < 2; r++)
        #pragma unroll
        for (int j = 0; j < 3; j++) {
            __half2 a = __floats2half2_rn(v[r][j].x, v[r][j].y);
            __half2 b = __floats2half2_rn(v[r][j].z, v[r][j].w);
            uint2 o; o.x = *(uint32_t*)&a; o.y = *(uint32_t*)&b;
            *(uint2*)(out + (size_t)(k0 + r) * 3 * D_MODEL + j * D_MODEL + c * 4) = o;
        }
    // bias concat: first 3 blocks handle one source each (grid >= 3)
    if (blockIdx.x < 3) {
        const float* src = (blockIdx.x == 0) ? bq : (blockIdx.x == 1) ? bk : bv;
        #pragma unroll
        for (int j = 0; j < 4; j++)
            bqkv[blockIdx.x * 1024 + threadIdx.x + j * 256] = src[threadIdx.x + j * 256];
    }
}

// ---------------- fp16 tensor-core GEMM, 2 CTAs/SM (R8 state, proven) ----------------
#define STG_BYTES 32768
#define GSM_TOTAL (3 * STG_BYTES)     /* 98304 */

template<bool RELU, bool RESID, bool HOUT>
__global__ __launch_bounds__(128, 2)
void gemm_h(const __half* __restrict__ Ah, const __half* __restrict__ Bh,
            const float* __restrict__ bias, const float* __restrict__ R,
            float* __restrict__ Cf, __half* __restrict__ Ch, int M, int N, int K)
{
    extern __shared__ char smem[];
    const uint32_t sb = smem_u32(smem);
    const int tid  = threadIdx.x;        // 0..127
    const int lane = tid & 31;
    const int wid  = tid >> 5;           // 0..3
    const int wm   = wid & 1;
    const int wn   = wid >> 1;           // 0..1
    const int swz  = lane & 7;

    const int m0 = blockIdx.y << 7;
    const int n0 = blockIdx.x << 7;

    const int rlA = lane & 15, clA = lane >> 4;
    const int kV = (lane & 7) + ((lane & 8) ? 8 : 0);
    const int cV = (lane >> 4) & 1;

    float acc[4][8][4];
    #pragma unroll
    for (int mi = 0; mi < 4; mi++)
        #pragma unroll
        for (int ni = 0; ni < 8; ni++)
            #pragma unroll
            for (int c = 0; c < 4; c++) acc[mi][ni][c] = 0.f;

    const int T = K >> 6;

    #define ISSUE_STAGE(s, buf) do { \
        const uint32_t b0_ = sb + (buf) * STG_BYTES; \
        _Pragma("unroll") \
        for (int j = 0; j < 8; j++) { \
            const int c_ = tid + j * 128, row_ = c_ >> 3, ch_ = c_ & 7; \
            CP16(b0_ + row_ * 128 + ((ch_ ^ (row_ & 7)) << 4), \
                 Ah + (size_t)(m0 + row_) * K + (s) * 64 + ch_ * 8); \
        } \
        _Pragma("unroll") \
        for (int j = 0; j < 8; j++) { \
            const int c_ = tid + j * 128, row_ = c_ >> 4, ch_ = c_ & 15; \
            const int ph_ = (ch_ & 8) | ((ch_ & 7) ^ (row_ & 7)); \
            CP16(b0_ + 16384 + row_ * 256 + (ph_ << 4), \
                 Bh + (size_t)((s) * 64 + row_) * N + n0 + ch_ * 8); \
        } \
    } while (0)

    #define LOAD_FRAGS(a_, b_, s_) do { \
        _Pragma("unroll") \
        for (int mi = 0; mi < 4; mi++) { \
            const int row = wm * 64 + mi * 16 + rlA; \
            LDSM4((a_)[mi][0], (a_)[mi][1], (a_)[mi][2], (a_)[mi][3], \
                  sA + row * 128 + (((2 * (s_) + clA) ^ swz) << 4)); \
        } \
        _Pragma("unroll") \
        for (int bb = 0; bb < 4; bb++) { \
            const int c = wn * 8 + 2 * bb + cV; \
            const int ph = (c & 8) | ((c & 7) ^ (kV & 7)); \
            LDSM4T((b_)[2*bb][0], (b_)[2*bb][1], (b_)[2*bb+1][0], (b_)[2*bb+1][1], \
                   sB + (16 * (s_) + kV) * 256 + (ph << 4)); \
        } \
    } while (0)

    ISSUE_STAGE(0, 0); CP_COMMIT();
    if (T > 1) ISSUE_STAGE(1, 1);
    CP_COMMIT();

    uint32_t af[2][4][4], bf[2][8][2];

    int cur = 0;
    for (int kt = 0; kt < T; kt++) {
        CP_WAIT1();
        __syncthreads();
        {
            int nb = cur + 2; if (nb >= 3) nb -= 3;
            if (kt + 2 < T) ISSUE_STAGE(kt + 2, nb);
            CP_COMMIT();
        }
        const uint32_t sA = sb + cur * STG_BYTES;
        const uint32_t sB = sA + 16384;

        LOAD_FRAGS(af[0], bf[0], 0);
        #pragma unroll
        for (int s = 0; s < 4; s++) {
            const int cb = s & 1;
            if (s < 3) LOAD_FRAGS(af[cb ^ 1], bf[cb ^ 1], s + 1);
            #pragma unroll
            for (int mi = 0; mi < 4; mi++)
                #pragma unroll
                for (int ni = 0; ni < 8; ni++)
                    mma16(acc[mi][ni], af[cb][mi], bf[cb][ni]);
        }
        cur = (cur == 2) ? 0 : cur + 1;
    }
    #undef ISSUE_STAGE
    #undef LOAD_FRAGS

    // ---- epilogue ----
    const int g  = lane >> 2;
    const int t2 = lane & 3;
    #pragma unroll
    for (int ni = 0; ni < 8; ni++) {
        const int c = n0 + wn * 64 + ni * 8 + 2 * t2;
        const float2 bi = *(const float2*)&bias[c];
        #pragma unroll
        for (int mi = 0; mi < 4; mi++) {
            const int r0 = m0 + wm * 64 + mi * 16 + g;
            #pragma unroll
            for (int h = 0; h < 2; h++) {
                const int rr = r0 + h * 8;
                float vx = acc[mi][ni][2 * h]     + bi.x;
                float vy = acc[mi][ni][2 * h + 1] + bi.y;
                if (RELU) { vx = fmaxf(vx, 0.f); vy = fmaxf(vy, 0.f); }
                const size_t idx = (size_t)rr * N + c;
                if (RESID) {
                    const float2 rs = *(const float2*)&R[idx];
                    vx += rs.x; vy += rs.y;
                }
                if (HOUT) {
                    __half2 hv = __floats2half2_rn(vx, vy);
                    *(uint32_t*)&Ch[idx] = *(uint32_t*)&hv;
                } else {
                    float2 o; o.x = vx; o.y = vy;
                    *(float2*)&Cf[idx] = o;
                }
            }
        }
    }
}

// ---------------- fp16 flash attention, register-resident P (R5-proven) ----------------
#define ATT_STG  16384
#define ATT_SMEM (16384 + 3 * ATT_STG)   /* 65536 */

__global__ __launch_bounds__(256, 1)
void attn_h(const __half* __restrict__ Qg, const __half* __restrict__ Kg,
            const __half* __restrict__ Vg, __half* __restrict__ O, int ld)
{
    extern __shared__ char smem[];
    const uint32_t sb = smem_u32(smem);
    const int tid  = threadIdx.x;
    const int lane = tid & 31;
    const int wid  = tid >> 5;
    const int g    = lane >> 2;
    const int t    = lane & 3;
    const int swz  = lane & 7;

    const int bh = blockIdx.y;
    const int b  = bh >> 4;
    const int h  = bh & 15;
    const int q0 = blockIdx.x << 7;

    const size_t base  = (size_t)b * SEQ * ld + (size_t)h * DK;
    const size_t obase = (size_t)b * SEQ * D_MODEL + (size_t)h * DK;

    #pragma unroll
    for (int p = 0; p < 4; p++) {
        const int c = tid + p * 256, row = c >> 3, ch = c & 7;
        *(uint4*)(smem + row * 128 + ((ch ^ (row & 7)) << 4)) =
            *(const uint4*)(Qg + base + (size_t)(q0 + row) * ld + ch * 8);
    }
    __syncthreads();

    uint32_t aq[4][4];
    {
        const int rowA = wid * 16 + (lane & 15);
        const int clA  = lane >> 4;
        #pragma unroll
        for (int kb = 0; kb < 4; kb++)
            LDSM4(aq[kb][0], aq[kb][1], aq[kb][2], aq[kb][3],
                  sb + rowA * 128 + (((2 * kb + clA) ^ swz) << 4));
    }

    const int rlB = (lane & 7) + ((lane >> 4) << 3);
    const int clB = (lane >> 3) & 1;
    const int kV  = (lane & 7) + ((lane & 8) ? 8 : 0);
    const int cV  = (lane >> 4) & 1;

    float m0v = -1e30f, m1v = -1e30f, l0 = 0.f, l1 = 0.f;
    float oacc[8][4];
    #pragma unroll
    for (int ni = 0; ni < 8; ni++)
        #pragma unroll
        for (int c = 0; c < 4; c++) oacc[ni][c] = 0.f;

    #define ISSUE_KV(s, buf) do { \
        const uint32_t kb_ = sb + 16384 + (buf) * ATT_STG; \
        _Pragma("unroll") \
        for (int j = 0; j < 2; j++) { \
            const int c_ = tid + j * 256, row_ = c_ >> 3, ch_ = c_ & 7; \
            const uint32_t off_ = row_ * 128 + ((ch_ ^ (row_ & 7)) << 4); \
            const size_t gsrc = base + (size_t)((s) * 64 + row_) * ld + ch_ * 8; \
            CP16(kb_ + off_,        Kg + gsrc); \
            CP16(kb_ + 8192 + off_, Vg + gsrc); \
        } \
    } while (0)

    ISSUE_KV(0, 0); CP_COMMIT();
    ISSUE_KV(1, 1); CP_COMMIT();

    int cur = 0;
    const int T = SEQ / 64;
    for (int kt = 0; kt < T; kt++) {
        CP_WAIT1();
        __syncthreads();
        {
            int nb = cur + 2; if (nb >= 3) nb -= 3;
            if (kt + 2 < T) ISSUE_KV(kt + 2, nb);
            CP_COMMIT();
        }
        const uint32_t kbuf = sb + 16384 + cur * ATT_STG;
        const uint32_t vbuf = kbuf + 8192;

        float sacc[8][4];
        #pragma unroll
        for (int ni = 0; ni < 8; ni++)
            #pragma unroll
            for (int c = 0; c < 4; c++) sacc[ni][c] = 0.f;

        #pragma unroll
        for (int kb = 0; kb < 4; kb++) {
            uint32_t bf[8][2];
            #pragma unroll
            for (int a = 0; a < 4; a++) {
                const int row = 16 * a + rlB;
                LDSM4(bf[2*a][0], bf[2*a][1], bf[2*a+1][0], bf[2*a+1][1],
                      kbuf + row * 128 + (((2 * kb + clB) ^ swz) << 4));
            }
            #pragma unroll
            for (int ni = 0; ni < 8; ni++)
                mma16(sacc[ni], aq[kb], bf[ni]);
        }

        #pragma unroll
        for (int ni = 0; ni < 8; ni++) {
            sacc[ni][0] *= 0.125f; sacc[ni][1] *= 0.125f;
            sacc[ni][2] *= 0.125f; sacc[ni][3] *= 0.125f;
        }
        float mx0 = -1e30f, mx1 = -1e30f;
        #pragma unroll
        for (int ni = 0; ni < 8; ni++) {
            mx0 = fmaxf(mx0, fmaxf(sacc[ni][0], sacc[ni][1]));
            mx1 = fmaxf(mx1, fmaxf(sacc[ni][2], sacc[ni][3]));
        }
        mx0 = fmaxf(mx0, __shfl_xor_sync(0xffffffffu, mx0, 1));
        mx0 = fmaxf(mx0, __shfl_xor_sync(0xffffffffu, mx0, 2));
        mx1 = fmaxf(mx1, __shfl_xor_sync(0xffffffffu, mx1, 1));
        mx1 = fmaxf(mx1, __shfl_xor_sync(0xffffffffu, mx1, 2));

        const float mn0 = fmaxf(m0v, mx0);
        const float mn1 = fmaxf(m1v, mx1);
        const float al0 = __expf(m0v - mn0);
        const float al1 = __expf(m1v - mn1);
        m0v = mn0; m1v = mn1;

        uint32_t pa[8][2];
        float sum0 = 0.f, sum1 = 0.f;
        #pragma unroll
        for (int ni = 0; ni < 8; ni++) {
            const float p0 = __expf(sacc[ni][0] - mn0);
            const float p1 = __expf(sacc[ni][1] - mn0);
            const float p2 = __expf(sacc[ni][2] - mn1);
            const float p3 = __expf(sacc[ni][3] - mn1);
            sum0 += p0 + p1; sum1 += p2 + p3;
            __half2 h0 = __floats2half2_rn(p0, p1);
            __half2 h1 = __floats2half2_rn(p2, p3);
            pa[ni][0] = *(uint32_t*)&h0;
            pa[ni][1] = *(uint32_t*)&h1;
        }
        sum0 += __shfl_xor_sync(0xffffffffu, sum0, 1);
        sum0 += __shfl_xor_sync(0xffffffffu, sum0, 2);
        sum1 += __shfl_xor_sync(0xffffffffu, sum1, 1);
        sum1 += __shfl_xor_sync(0xffffffffu, sum1, 2);
        l0 = l0 * al0 + sum0;
        l1 = l1 * al1 + sum1;

        #pragma unroll
        for (int ni = 0; ni < 8; ni++) {
            oacc[ni][0] *= al0; oacc[ni][1] *= al0;
            oacc[ni][2] *= al1; oacc[ni][3] *= al1;
        }

        #pragma unroll
        for (int kk = 0; kk < 4; kk++) {
            uint32_t bv[8][2];
            #pragma unroll
            for (int bb = 0; bb < 4; bb++) {
                const int key = 16 * kk + kV;
                LDSM4T(bv[2*bb][0], bv[2*bb][1], bv[2*bb+1][0], bv[2*bb+1][1],
                       vbuf + key * 128 + (((2 * bb + cV) ^ swz) << 4));
            }
            uint32_t ap[4] = { pa[2*kk][0], pa[2*kk][1], pa[2*kk+1][0], pa[2*kk+1][1] };
            #pragma unroll
            for (int ni = 0; ni < 8; ni++)
                mma16(oacc[ni], ap, bv[ni]);
        }

        cur = (cur == 2) ? 0 : cur + 1;
    }
    #undef ISSUE_KV

    const float inv0 = 1.f / l0;
    const float inv1 = 1.f / l1;
    const size_t row0 = obase + (size_t)(q0 + wid * 16 + g) * D_MODEL;
    const size_t row1 = row0 + (size_t)8 * D_MODEL;
    #pragma unroll
    for (int ni = 0; ni < 8; ni++) {
        const int c = ni * 8 + 2 * t;
        __half2 h0 = __floats2half2_rn(oacc[ni][0] * inv0, oacc[ni][1] * inv0);
        __half2 h1 = __floats2half2_rn(oacc[ni][2] * inv1, oacc[ni][3] * inv1);
        *(uint32_t*)&O[row0 + c] = *(uint32_t*)&h0;
        *(uint32_t*)&O[row1 + c] = *(uint32_t*)&h1;
    }
}

// ---------------- launch ----------------
extern "C" void kernel_launch(void* const* d_in, const int* in_sizes, int n_in,
                              void* d_out, int out_size)
{
    const float* x    = (const float*)d_in[0];
    const float* ln1g = (const float*)d_in[1];
    const float* ln1b = (const float*)d_in[2];
    const float* ln2g = (const float*)d_in[3];
    const float* ln2b = (const float*)d_in[4];
    const float* Wq = (const float*)d_in[5];
    const float* bq = (const float*)d_in[6];
    const float* Wk = (const float*)d_in[7];
    const float* bk = (const float*)d_in[8];
    const float* Wv = (const float*)d_in[9];
    const float* bv = (const float*)d_in[10];
    const float* Wo = (const float*)d_in[11];
    const float* bo = (const float*)d_in[12];
    const float* W1 = (const float*)d_in[13];
    const float* b1 = (const float*)d_in[14];
    const float* W2 = (const float*)d_in[15];
    const float* b2 = (const float*)d_in[16];
    float* out = (float*)d_out;

    __half *xnh, *qkvh, *ctxh, *ffh, *wqkvh, *woh, *w1h, *w2h;
    float *x1, *bqkv;
    cudaGetSymbolAddress((void**)&xnh,   g_xnh);
    cudaGetSymbolAddress((void**)&qkvh,  g_qkvh);
    cudaGetSymbolAddress((void**)&ctxh,  g_ctxh);
    cudaGetSymbolAddress((void**)&x1,    g_x1);
    cudaGetSymbolAddress((void**)&ffh,   g_ffh);
    cudaGetSymbolAddress((void**)&wqkvh, g_wqkvh);
    cudaGetSymbolAddress((void**)&woh,   g_woh);
    cudaGetSymbolAddress((void**)&w1h,   g_w1h);
    cudaGetSymbolAddress((void**)&w2h,   g_w2h);
    cudaGetSymbolAddress((void**)&bqkv,  g_bqkv);

    cudaFuncSetAttribute(attn_h, cudaFuncAttributeMaxDynamicSharedMemorySize, ATT_SMEM);
    cudaFuncSetAttribute(gemm_h<false,false,true>,  cudaFuncAttributeMaxDynamicSharedMemorySize, GSM_TOTAL);
    cudaFuncSetAttribute(gemm_h<false,true,false>,  cudaFuncAttributeMaxDynamicSharedMemorySize, GSM_TOTAL);
    cudaFuncSetAttribute(gemm_h<true,false,true>,   cudaFuncAttributeMaxDynamicSharedMemorySize, GSM_TOTAL);

    // weight converts (f32 -> f16, layout preserved [K,N]) + fused bias concat
    convert_qkv<<<512, 256>>>(Wq, Wk, Wv, bqkv, bq, bk, bv, wqkvh);
    convert_h<<<(D_MODEL*D_MODEL)/4096, 256>>>(Wo, woh);
    convert_h<<<(D_MODEL*D_FF)/4096, 256>>>(W1, w1h);
    convert_h<<<(D_FF*D_MODEL)/4096, 256>>>(W2, w2h);

    // 1) xn = LN1(x)  (fp16 out)
    ln_kernel<<<NTOK/8, 256>>>(x, ln1g, ln1b, xnh);
    // 2) qkv = xn @ [Wq|Wk|Wv] + [bq|bk|bv]   (fused, N=3072, fp16 out)
    gemm_h<false,false,true><<<dim3(3*D_MODEL/128, NTOK/128), 128, GSM_TOTAL>>>(
        xnh, wqkvh, bqkv, nullptr, nullptr, qkvh, NTOK, 3*D_MODEL, D_MODEL);
    // 3) ctx = attention(q,k,v)  (fp16 in/out)
    attn_h<<<dim3(SEQ/128, BATCH*NHEAD), 256, ATT_SMEM>>>(
        qkvh, qkvh + D_MODEL, qkvh + 2*D_MODEL, ctxh, 3*D_MODEL);
    // 4) x1 = x + ctx @ Wo + bo  (f32 out)
    gemm_h<false,true,false><<<dim3(D_MODEL/128, NTOK/128), 128, GSM_TOTAL>>>(
        ctxh, woh, bo, x, x1, nullptr, NTOK, D_MODEL, D_MODEL);
    // 5) xn = LN2(x1)  (fp16 out)
    ln_kernel<<<NTOK/8, 256>>>(x1, ln2g, ln2b, xnh);
    // 6) ffh = relu(xn @ W1 + b1)  (fp16 out)
    gemm_h<true,false,true><<<dim3(D_FF/128, NTOK/128), 128, GSM_TOTAL>>>(
        xnh, w1h, b1, nullptr, nullptr, ffh, NTOK, D_FF, D_MODEL);
    // 7) out = x1 + ffh @ W2 + b2  (f32 out)
    gemm_h<false,true,false><<<dim3(D_MODEL/128, NTOK/128), 128, GSM_TOTAL>>>(
        ffh, w2h, b2, x1, out, nullptr, NTOK, D_MODEL, D_FF);
}

// round 10
// speedup vs baseline: 8.5544x; 1.0102x over previous
#include <cuda_runtime.h>
#include <cuda_fp16.h>
#include <cstdint>

#define D_MODEL 1024
#define D_FF    4096
#define SEQ     2048
#define BATCH   4
#define NTOK    (BATCH*SEQ)   /* 8192 */
#define NHEAD   16
#define DK      64

// ---------------- scratch (static device globals; no allocation) ----------------
__device__ __half g_xnh  [(size_t)NTOK*D_MODEL];
__device__ __half g_qkvh [(size_t)NTOK*3*D_MODEL];
__device__ __half g_ctxh [(size_t)NTOK*D_MODEL];
__device__ float  g_x1   [(size_t)NTOK*D_MODEL];
__device__ __half g_ffh  [(size_t)NTOK*D_FF];
__device__ __half g_wqkvh[(size_t)D_MODEL*3*D_MODEL];   // [K=1024][N=3072]
__device__ __half g_woh  [(size_t)D_MODEL*D_MODEL];     // [K][N]
__device__ __half g_w1h  [(size_t)D_MODEL*D_FF];        // [1024][4096]
__device__ __half g_w2h  [(size_t)D_FF*D_MODEL];        // [4096][1024]
__device__ float  g_bqkv [3*D_MODEL];

// ---------------- PTX helpers ----------------
__device__ __forceinline__ uint32_t smem_u32(const void* p) {
    uint32_t a;
    asm("{ .reg .u64 t; cvta.to.shared.u64 t, %1; cvt.u32.u64 %0, t; }"
        : "=r"(a) : "l"(p));
    return a;
}

#define LDSM4(r0, r1, r2, r3, a) \
    asm volatile("ldmatrix.sync.aligned.m8n8.x4.shared.b16 {%0,%1,%2,%3}, [%4];" \
        : "=r"(r0), "=r"(r1), "=r"(r2), "=r"(r3) : "r"(a))
#define LDSM4T(r0, r1, r2, r3, a) \
    asm volatile("ldmatrix.sync.aligned.m8n8.x4.trans.shared.b16 {%0,%1,%2,%3}, [%4];" \
        : "=r"(r0), "=r"(r1), "=r"(r2), "=r"(r3) : "r"(a))

#define CP16(dst, src) \
    asm volatile("cp.async.cg.shared.global [%0], [%1], 16;" :: "r"(dst), "l"(src))
#define CP_COMMIT() asm volatile("cp.async.commit_group;" ::: "memory")
#define CP_WAIT1()  asm volatile("cp.async.wait_group 1;" ::: "memory")
#define CP_WAIT4()  asm volatile("cp.async.wait_group 4;" ::: "memory")

// fp16 MMA, fp32 accum: D(16x8) += A(16x16) @ B(16x8)
__device__ __forceinline__ void mma16(float* d, const uint32_t* a, const uint32_t* b) {
    asm volatile(
        "mma.sync.aligned.m16n8k16.row.col.f32.f16.f16.f32 "
        "{%0,%1,%2,%3}, {%4,%5,%6,%7}, {%8,%9}, {%0,%1,%2,%3};"
        : "+f"(d[0]), "+f"(d[1]), "+f"(d[2]), "+f"(d[3])
        : "r"(a[0]), "r"(a[1]), "r"(a[2]), "r"(a[3]), "r"(b[0]), "r"(b[1]));
}

// ---------------- LayerNorm: warp-per-row, MLP=8, f32 in fp16 out ----------------
__global__ void ln_kernel(const float* __restrict__ x,
                          const float* __restrict__ gamma,
                          const float* __restrict__ beta,
                          __half* __restrict__ y)
{
    const int lane = threadIdx.x & 31;
    const int wrp  = threadIdx.x >> 5;
    const int row  = blockIdx.x * 8 + wrp;

    const float4* xr = (const float4*)(x + (size_t)row * D_MODEL);
    float4 v[8];
    #pragma unroll
    for (int i = 0; i < 8; i++) v[i] = xr[lane + 32 * i];

    float s = 0.f, ss = 0.f;
    #pragma unroll
    for (int i = 0; i < 8; i++) {
        s  += v[i].x + v[i].y + v[i].z + v[i].w;
        ss += v[i].x*v[i].x + v[i].y*v[i].y + v[i].z*v[i].z + v[i].w*v[i].w;
    }
    #pragma unroll
    for (int off = 16; off; off >>= 1) {
        s  += __shfl_xor_sync(0xffffffffu, s,  off);
        ss += __shfl_xor_sync(0xffffffffu, ss, off);
    }
    const float mu   = s * (1.0f / D_MODEL);
    const float var  = ss * (1.0f / D_MODEL) - mu * mu;
    const float rstd = rsqrtf(var + 1e-5f);

    __half* yr = y + (size_t)row * D_MODEL;
    #pragma unroll
    for (int i = 0; i < 8; i++) {
        const int e = lane + 32 * i;
        const float4 g4 = ((const float4*)gamma)[e];
        const float4 b4 = ((const float4*)beta)[e];
        const float ox = (v[i].x - mu) * rstd * g4.x + b4.x;
        const float oy = (v[i].y - mu) * rstd * g4.y + b4.y;
        const float oz = (v[i].z - mu) * rstd * g4.z + b4.z;
        const float ow = (v[i].w - mu) * rstd * g4.w + b4.w;
        __half2 h0 = __floats2half2_rn(ox, oy);
        __half2 h1 = __floats2half2_rn(oz, ow);
        uint2 o; o.x = *(uint32_t*)&h0; o.y = *(uint32_t*)&h1;
        *(uint2*)(yr + e * 4) = o;
    }
}

// ---------------- weight convert: f32 -> f16, 4 float4/thread (MLP=4) ----------------
__global__ void convert_h(const float* __restrict__ in, __half* __restrict__ out)
{
    const size_t b0 = (size_t)blockIdx.x * 4096 + threadIdx.x * 4;
    float4 v[4];
    #pragma unroll
    for (int j = 0; j < 4; j++) v[j] = *(const float4*)(in + b0 + j * 1024);
    #pragma unroll
    for (int j = 0; j < 4; j++) {
        __half2 a = __floats2half2_rn(v[j].x, v[j].y);
        __half2 b = __floats2half2_rn(v[j].z, v[j].w);
        uint2 o; o.x = *(uint32_t*)&a; o.y = *(uint32_t*)&b;
        *(uint2*)(out + b0 + j * 1024) = o;
    }
}

// qkv merge-convert + bias concat
__global__ void convert_qkv(const float* __restrict__ Wq, const float* __restrict__ Wk,
                            const float* __restrict__ Wv, float* __restrict__ bqkv,
                            const float* __restrict__ bq, const float* __restrict__ bk,
                            const float* __restrict__ bv, __half* __restrict__ out)
{
    const int k0 = blockIdx.x * 2;            // grid 512
    const int c  = threadIdx.x;               // 0..255
    const float* srcs[3] = { Wq, Wk, Wv };
    float4 v[2][3];
    #pragma unroll
    for (int r = 0; r < 2; r++)
        #pragma unroll
        for (int j = 0; j < 3; j++)
            v[r][j] = ((const float4*)(srcs[j] + (size_t)(k0 + r) * D_MODEL))[c];
    #pragma unroll
    for (int r = 0; r < 2; r++)
        #pragma unroll
        for (int j = 0; j < 3; j++) {
            __half2 a = __floats2half2_rn(v[r][j].x, v[r][j].y);
            __half2 b = __floats2half2_rn(v[r][j].z, v[r][j].w);
            uint2 o; o.x = *(uint32_t*)&a; o.y = *(uint32_t*)&b;
            *(uint2*)(out + (size_t)(k0 + r) * 3 * D_MODEL + j * D_MODEL + c * 4) = o;
        }
    if (blockIdx.x < 3) {
        const float* src = (blockIdx.x == 0) ? bq : (blockIdx.x == 1) ? bk : bv;
        #pragma unroll
        for (int j = 0; j < 4; j++)
            bqkv[blockIdx.x * 1024 + threadIdx.x + j * 256] = src[threadIdx.x + j * 256];
    }
}

// ---------------- fp16 tensor-core GEMM, 2 CTAs/SM, 6-stage k32 pipeline ----------------
// C[M,N] = Ah[M,K](f16) @ Bh[K,N](f16) + bias (+relu) (+R).
// CTA 128x128, 4 warps (2m x 2n), warp tile 64x64, k-stage 32, 6-stage cp.async.
// smem/stage 16KB: A [128m][32k] 64B rows (swz (row>>1)&3, R4-proven) +
//                  B [32k][128n] 256B rows (trans swz, R7-proven).
#define STG_BYTES 16384
#define GSM_TOTAL (6 * STG_BYTES)     /* 98304 */

template<bool RELU, bool RESID, bool HOUT>
__global__ __launch_bounds__(128, 2)
void gemm_h(const __half* __restrict__ Ah, const __half* __restrict__ Bh,
            const float* __restrict__ bias, const float* __restrict__ R,
            float* __restrict__ Cf, __half* __restrict__ Ch, int M, int N, int K)
{
    extern __shared__ char smem[];
    const uint32_t sb = smem_u32(smem);
    const int tid  = threadIdx.x;        // 0..127
    const int lane = tid & 31;
    const int wid  = tid >> 5;           // 0..3
    const int wm   = wid & 1;
    const int wn   = wid >> 1;           // 0..1

    const int m0 = blockIdx.y << 7;
    const int n0 = blockIdx.x << 7;

    const int rlA = lane & 15, clA = lane >> 4;
    const int kV = (lane & 7) + ((lane & 8) ? 8 : 0);
    const int cV = (lane >> 4) & 1;

    float acc[4][8][4];
    #pragma unroll
    for (int mi = 0; mi < 4; mi++)
        #pragma unroll
        for (int ni = 0; ni < 8; ni++)
            #pragma unroll
            for (int c = 0; c < 4; c++) acc[mi][ni][c] = 0.f;

    const int T = K >> 5;

    // stage = 16KB: A 8KB (128 rows x 64B) + B 8KB (32 rows x 256B)
    #define ISSUE_STAGE(s, buf) do { \
        const uint32_t b0_ = sb + (buf) * STG_BYTES; \
        _Pragma("unroll") \
        for (int j = 0; j < 4; j++) { \
            const int c_ = tid + j * 128, row_ = c_ >> 2, ch_ = c_ & 3; \
            CP16(b0_ + row_ * 64 + ((ch_ ^ ((row_ >> 1) & 3)) << 4), \
                 Ah + (size_t)(m0 + row_) * K + (s) * 32 + ch_ * 8); \
        } \
        _Pragma("unroll") \
        for (int j = 0; j < 4; j++) { \
            const int c_ = tid + j * 128, row_ = c_ >> 4, ch_ = c_ & 15; \
            const int ph_ = (ch_ & 8) | ((ch_ & 7) ^ (row_ & 7)); \
            CP16(b0_ + 8192 + row_ * 256 + (ph_ << 4), \
                 Bh + (size_t)((s) * 32 + row_) * N + n0 + ch_ * 8); \
        } \
    } while (0)

    // fragments for k16-step s_ (0 or 1) of current stage
    #define LOAD_FRAGS(a_, b_, s_) do { \
        _Pragma("unroll") \
        for (int mi = 0; mi < 4; mi++) { \
            const int row = wm * 64 + mi * 16 + rlA; \
            LDSM4((a_)[mi][0], (a_)[mi][1], (a_)[mi][2], (a_)[mi][3], \
                  sA + row * 64 + (((2 * (s_) + clA) ^ ((row >> 1) & 3)) << 4)); \
        } \
        _Pragma("unroll") \
        for (int bb = 0; bb < 4; bb++) { \
            const int c = wn * 8 + 2 * bb + cV; \
            const int ph = (c & 8) | ((c & 7) ^ (kV & 7)); \
            LDSM4T((b_)[2*bb][0], (b_)[2*bb][1], (b_)[2*bb+1][0], (b_)[2*bb+1][1], \
                   sB + (16 * (s_) + kV) * 256 + (ph << 4)); \
        } \
    } while (0)

    // prologue: prefetch 5 stages
    #pragma unroll
    for (int i = 0; i < 5; i++) {
        if (i < T) ISSUE_STAGE(i, i);
        CP_COMMIT();
    }

    uint32_t af[2][4][4], bf[2][8][2];

    int cur = 0;
    for (int kt = 0; kt < T; kt++) {
        CP_WAIT4();
        __syncthreads();
        {
            int nb = cur + 5; if (nb >= 6) nb -= 6;
            if (kt + 5 < T) ISSUE_STAGE(kt + 5, nb);
            CP_COMMIT();
        }
        const uint32_t sA = sb + cur * STG_BYTES;
        const uint32_t sB = sA + 8192;

        LOAD_FRAGS(af[0], bf[0], 0);
        LOAD_FRAGS(af[1], bf[1], 1);
        #pragma unroll
        for (int s = 0; s < 2; s++) {
            #pragma unroll
            for (int mi = 0; mi < 4; mi++)
                #pragma unroll
                for (int ni = 0; ni < 8; ni++)
                    mma16(acc[mi][ni], af[s][mi], bf[s][ni]);
        }
        cur = (cur == 5) ? 0 : cur + 1;
    }
    #undef ISSUE_STAGE
    #undef LOAD_FRAGS

    // ---- epilogue ----
    const int g  = lane >> 2;
    const int t2 = lane & 3;
    #pragma unroll
    for (int ni = 0; ni < 8; ni++) {
        const int c = n0 + wn * 64 + ni * 8 + 2 * t2;
        const float2 bi = *(const float2*)&bias[c];
        #pragma unroll
        for (int mi = 0; mi < 4; mi++) {
            const int r0 = m0 + wm * 64 + mi * 16 + g;
            #pragma unroll
            for (int h = 0; h < 2; h++) {
                const int rr = r0 + h * 8;
                float vx = acc[mi][ni][2 * h]     + bi.x;
                float vy = acc[mi][ni][2 * h + 1] + bi.y;
                if (RELU) { vx = fmaxf(vx, 0.f); vy = fmaxf(vy, 0.f); }
                const size_t idx = (size_t)rr * N + c;
                if (RESID) {
                    const float2 rs = *(const float2*)&R[idx];
                    vx += rs.x; vy += rs.y;
                }
                if (HOUT) {
                    __half2 hv = __floats2half2_rn(vx, vy);
                    *(uint32_t*)&Ch[idx] = *(uint32_t*)&hv;
                } else {
                    float2 o; o.x = vx; o.y = vy;
                    *(float2*)&Cf[idx] = o;
                }
            }
        }
    }
}

// ---------------- fp16 flash attention, register-resident P (R5-proven) ----------------
#define ATT_STG  16384
#define ATT_SMEM (16384 + 3 * ATT_STG)   /* 65536 */

__global__ __launch_bounds__(256, 1)
void attn_h(const __half* __restrict__ Qg, const __half* __restrict__ Kg,
            const __half* __restrict__ Vg, __half* __restrict__ O, int ld)
{
    extern __shared__ char smem[];
    const uint32_t sb = smem_u32(smem);
    const int tid  = threadIdx.x;
    const int lane = tid & 31;
    const int wid  = tid >> 5;
    const int g    = lane >> 2;
    const int t    = lane & 3;
    const int swz  = lane & 7;

    const int bh = blockIdx.y;
    const int b  = bh >> 4;
    const int h  = bh & 15;
    const int q0 = blockIdx.x << 7;

    const size_t base  = (size_t)b * SEQ * ld + (size_t)h * DK;
    const size_t obase = (size_t)b * SEQ * D_MODEL + (size_t)h * DK;

    #pragma unroll
    for (int p = 0; p < 4; p++) {
        const int c = tid + p * 256, row = c >> 3, ch = c & 7;
        *(uint4*)(smem + row * 128 + ((ch ^ (row & 7)) << 4)) =
            *(const uint4*)(Qg + base + (size_t)(q0 + row) * ld + ch * 8);
    }
    __syncthreads();

    uint32_t aq[4][4];
    {
        const int rowA = wid * 16 + (lane & 15);
        const int clA  = lane >> 4;
        #pragma unroll
        for (int kb = 0; kb < 4; kb++)
            LDSM4(aq[kb][0], aq[kb][1], aq[kb][2], aq[kb][3],
                  sb + rowA * 128 + (((2 * kb + clA) ^ swz) << 4));
    }

    const int rlB = (lane & 7) + ((lane >> 4) << 3);
    const int clB = (lane >> 3) & 1;
    const int kV  = (lane & 7) + ((lane & 8) ? 8 : 0);
    const int cV  = (lane >> 4) & 1;

    float m0v = -1e30f, m1v = -1e30f, l0 = 0.f, l1 = 0.f;
    float oacc[8][4];
    #pragma unroll
    for (int ni = 0; ni < 8; ni++)
        #pragma unroll
        for (int c = 0; c < 4; c++) oacc[ni][c] = 0.f;

    #define ISSUE_KV(s, buf) do { \
        const uint32_t kb_ = sb + 16384 + (buf) * ATT_STG; \
        _Pragma("unroll") \
        for (int j = 0; j < 2; j++) { \
            const int c_ = tid + j * 256, row_ = c_ >> 3, ch_ = c_ & 7; \
            const uint32_t off_ = row_ * 128 + ((ch_ ^ (row_ & 7)) << 4); \
            const size_t gsrc = base + (size_t)((s) * 64 + row_) * ld + ch_ * 8; \
            CP16(kb_ + off_,        Kg + gsrc); \
            CP16(kb_ + 8192 + off_, Vg + gsrc); \
        } \
    } while (0)

    ISSUE_KV(0, 0); CP_COMMIT();
    ISSUE_KV(1, 1); CP_COMMIT();

    int cur = 0;
    const int T = SEQ / 64;
    for (int kt = 0; kt < T; kt++) {
        CP_WAIT1();
        __syncthreads();
        {
            int nb = cur + 2; if (nb >= 3) nb -= 3;
            if (kt + 2 < T) ISSUE_KV(kt + 2, nb);
            CP_COMMIT();
        }
        const uint32_t kbuf = sb + 16384 + cur * ATT_STG;
        const uint32_t vbuf = kbuf + 8192;

        float sacc[8][4];
        #pragma unroll
        for (int ni = 0; ni < 8; ni++)
            #pragma unroll
            for (int c = 0; c < 4; c++) sacc[ni][c] = 0.f;

        #pragma unroll
        for (int kb = 0; kb < 4; kb++) {
            uint32_t bf[8][2];
            #pragma unroll
            for (int a = 0; a < 4; a++) {
                const int row = 16 * a + rlB;
                LDSM4(bf[2*a][0], bf[2*a][1], bf[2*a+1][0], bf[2*a+1][1],
                      kbuf + row * 128 + (((2 * kb + clB) ^ swz) << 4));
            }
            #pragma unroll
            for (int ni = 0; ni < 8; ni++)
                mma16(sacc[ni], aq[kb], bf[ni]);
        }

        #pragma unroll
        for (int ni = 0; ni < 8; ni++) {
            sacc[ni][0] *= 0.125f; sacc[ni][1] *= 0.125f;
            sacc[ni][2] *= 0.125f; sacc[ni][3] *= 0.125f;
        }
        float mx0 = -1e30f, mx1 = -1e30f;
        #pragma unroll
        for (int ni = 0; ni < 8; ni++) {
            mx0 = fmaxf(mx0, fmaxf(sacc[ni][0], sacc[ni][1]));
            mx1 = fmaxf(mx1, fmaxf(sacc[ni][2], sacc[ni][3]));
        }
        mx0 = fmaxf(mx0, __shfl_xor_sync(0xffffffffu, mx0, 1));
        mx0 = fmaxf(mx0, __shfl_xor_sync(0xffffffffu, mx0, 2));
        mx1 = fmaxf(mx1, __shfl_xor_sync(0xffffffffu, mx1, 1));
        mx1 = fmaxf(mx1, __shfl_xor_sync(0xffffffffu, mx1, 2));

        const float mn0 = fmaxf(m0v, mx0);
        const float mn1 = fmaxf(m1v, mx1);
        const float al0 = __expf(m0v - mn0);
        const float al1 = __expf(m1v - mn1);
        m0v = mn0; m1v = mn1;

        uint32_t pa[8][2];
        float sum0 = 0.f, sum1 = 0.f;
        #pragma unroll
        for (int ni = 0; ni < 8; ni++) {
            const float p0 = __expf(sacc[ni][0] - mn0);
            const float p1 = __expf(sacc[ni][1] - mn0);
            const float p2 = __expf(sacc[ni][2] - mn1);
            const float p3 = __expf(sacc[ni][3] - mn1);
            sum0 += p0 + p1; sum1 += p2 + p3;
            __half2 h0 = __floats2half2_rn(p0, p1);
            __half2 h1 = __floats2half2_rn(p2, p3);
            pa[ni][0] = *(uint32_t*)&h0;
            pa[ni][1] = *(uint32_t*)&h1;
        }
        sum0 += __shfl_xor_sync(0xffffffffu, sum0, 1);
        sum0 += __shfl_xor_sync(0xffffffffu, sum0, 2);
        sum1 += __shfl_xor_sync(0xffffffffu, sum1, 1);
        sum1 += __shfl_xor_sync(0xffffffffu, sum1, 2);
        l0 = l0 * al0 + sum0;
        l1 = l1 * al1 + sum1;

        #pragma unroll
        for (int ni = 0; ni < 8; ni++) {
            oacc[ni][0] *= al0; oacc[ni][1] *= al0;
            oacc[ni][2] *= al1; oacc[ni][3] *= al1;
        }

        #pragma unroll
        for (int kk = 0; kk < 4; kk++) {
            uint32_t bv[8][2];
            #pragma unroll
            for (int bb = 0; bb < 4; bb++) {
                const int key = 16 * kk + kV;
                LDSM4T(bv[2*bb][0], bv[2*bb][1], bv[2*bb+1][0], bv[2*bb+1][1],
                       vbuf + key * 128 + (((2 * bb + cV) ^ swz) << 4));
            }
            uint32_t ap[4] = { pa[2*kk][0], pa[2*kk][1], pa[2*kk+1][0], pa[2*kk+1][1] };
            #pragma unroll
            for (int ni = 0; ni < 8; ni++)
                mma16(oacc[ni], ap, bv[ni]);
        }

        cur = (cur == 2) ? 0 : cur + 1;
    }
    #undef ISSUE_KV

    const float inv0 = 1.f / l0;
    const float inv1 = 1.f / l1;
    const size_t row0 = obase + (size_t)(q0 + wid * 16 + g) * D_MODEL;
    const size_t row1 = row0 + (size_t)8 * D_MODEL;
    #pragma unroll
    for (int ni = 0; ni < 8; ni++) {
        const int c = ni * 8 + 2 * t;
        __half2 h0 = __floats2half2_rn(oacc[ni][0] * inv0, oacc[ni][1] * inv0);
        __half2 h1 = __floats2half2_rn(oacc[ni][2] * inv1, oacc[ni][3] * inv1);
        *(uint32_t*)&O[row0 + c] = *(uint32_t*)&h0;
        *(uint32_t*)&O[row1 + c] = *(uint32_t*)&h1;
    }
}

// ---------------- launch ----------------
extern "C" void kernel_launch(void* const* d_in, const int* in_sizes, int n_in,
                              void* d_out, int out_size)
{
    const float* x    = (const float*)d_in[0];
    const float* ln1g = (const float*)d_in[1];
    const float* ln1b = (const float*)d_in[2];
    const float* ln2g = (const float*)d_in[3];
    const float* ln2b = (const float*)d_in[4];
    const float* Wq = (const float*)d_in[5];
    const float* bq = (const float*)d_in[6];
    const float* Wk = (const float*)d_in[7];
    const float* bk = (const float*)d_in[8];
    const float* Wv = (const float*)d_in[9];
    const float* bv = (const float*)d_in[10];
    const float* Wo = (const float*)d_in[11];
    const float* bo = (const float*)d_in[12];
    const float* W1 = (const float*)d_in[13];
    const float* b1 = (const float*)d_in[14];
    const float* W2 = (const float*)d_in[15];
    const float* b2 = (const float*)d_in[16];
    float* out = (float*)d_out;

    __half *xnh, *qkvh, *ctxh, *ffh, *wqkvh, *woh, *w1h, *w2h;
    float *x1, *bqkv;
    cudaGetSymbolAddress((void**)&xnh,   g_xnh);
    cudaGetSymbolAddress((void**)&qkvh,  g_qkvh);
    cudaGetSymbolAddress((void**)&ctxh,  g_ctxh);
    cudaGetSymbolAddress((void**)&x1,    g_x1);
    cudaGetSymbolAddress((void**)&ffh,   g_ffh);
    cudaGetSymbolAddress((void**)&wqkvh, g_wqkvh);
    cudaGetSymbolAddress((void**)&woh,   g_woh);
    cudaGetSymbolAddress((void**)&w1h,   g_w1h);
    cudaGetSymbolAddress((void**)&w2h,   g_w2h);
    cudaGetSymbolAddress((void**)&bqkv,  g_bqkv);

    cudaFuncSetAttribute(attn_h, cudaFuncAttributeMaxDynamicSharedMemorySize, ATT_SMEM);
    cudaFuncSetAttribute(gemm_h<false,false,true>,  cudaFuncAttributeMaxDynamicSharedMemorySize, GSM_TOTAL);
    cudaFuncSetAttribute(gemm_h<false,true,false>,  cudaFuncAttributeMaxDynamicSharedMemorySize, GSM_TOTAL);
    cudaFuncSetAttribute(gemm_h<true,false,true>,   cudaFuncAttributeMaxDynamicSharedMemorySize, GSM_TOTAL);

    // weight converts (f32 -> f16, layout preserved [K,N]) + fused bias concat
    convert_qkv<<<512, 256>>>(Wq, Wk, Wv, bqkv, bq, bk, bv, wqkvh);
    convert_h<<<(D_MODEL*D_MODEL)/4096, 256>>>(Wo, woh);
    convert_h<<<(D_MODEL*D_FF)/4096, 256>>>(W1, w1h);
    convert_h<<<(D_FF*D_MODEL)/4096, 256>>>(W2, w2h);

    // 1) xn = LN1(x)  (fp16 out)
    ln_kernel<<<NTOK/8, 256>>>(x, ln1g, ln1b, xnh);
    // 2) qkv = xn @ [Wq|Wk|Wv] + [bq|bk|bv]   (fused, N=3072, fp16 out)
    gemm_h<false,false,true><<<dim3(3*D_MODEL/128, NTOK/128), 128, GSM_TOTAL>>>(
        xnh, wqkvh, bqkv, nullptr, nullptr, qkvh, NTOK, 3*D_MODEL, D_MODEL);
    // 3) ctx = attention(q,k,v)  (fp16 in/out)
    attn_h<<<dim3(SEQ/128, BATCH*NHEAD), 256, ATT_SMEM>>>(
        qkvh, qkvh + D_MODEL, qkvh + 2*D_MODEL, ctxh, 3*D_MODEL);
    // 4) x1 = x + ctx @ Wo + bo  (f32 out)
    gemm_h<false,true,false><<<dim3(D_MODEL/128, NTOK/128), 128, GSM_TOTAL>>>(
        ctxh, woh, bo, x, x1, nullptr, NTOK, D_MODEL, D_MODEL);
    // 5) xn = LN2(x1)  (fp16 out)
    ln_kernel<<<NTOK/8, 256>>>(x1, ln2g, ln2b, xnh);
    // 6) ffh = relu(xn @ W1 + b1)  (fp16 out)
    gemm_h<true,false,true><<<dim3(D_FF/128, NTOK/128), 128, GSM_TOTAL>>>(
        xnh, w1h, b1, nullptr, nullptr, ffh, NTOK, D_FF, D_MODEL);
    // 7) out = x1 + ffh @ W2 + b2  (f32 out)
    gemm_h<false,true,false><<<dim3(D_MODEL/128, NTOK/128), 128, GSM_TOTAL>>>(
        ffh, w2h, b2, x1, out, nullptr, NTOK, D_MODEL, D_FF);
}

// round 11
// speedup vs baseline: 8.9396x; 1.0450x over previous
#include <cuda_runtime.h>
#include <cuda_fp16.h>
#include <cstdint>

#define D_MODEL 1024
#define D_FF    4096
#define SEQ     2048
#define BATCH   4
#define NTOK    (BATCH*SEQ)   /* 8192 */
#define NHEAD   16
#define DK      64

// ---------------- scratch (static device globals; no allocation) ----------------
__device__ __half g_xnh  [(size_t)NTOK*D_MODEL];
__device__ __half g_qkvh [(size_t)NTOK*3*D_MODEL];
__device__ __half g_ctxh [(size_t)NTOK*D_MODEL];
__device__ float  g_x1   [(size_t)NTOK*D_MODEL];
__device__ __half g_ffh  [(size_t)NTOK*D_FF];
__device__ __half g_wqkvh[(size_t)D_MODEL*3*D_MODEL];   // [K=1024][N=3072]
__device__ __half g_woh  [(size_t)D_MODEL*D_MODEL];     // [K][N]
__device__ __half g_w1h  [(size_t)D_MODEL*D_FF];        // [1024][4096]
__device__ __half g_w2h  [(size_t)D_FF*D_MODEL];        // [4096][1024]
__device__ float  g_bqkv [3*D_MODEL];

// ---------------- PTX helpers ----------------
__device__ __forceinline__ uint32_t smem_u32(const void* p) {
    uint32_t a;
    asm("{ .reg .u64 t; cvta.to.shared.u64 t, %1; cvt.u32.u64 %0, t; }"
        : "=r"(a) : "l"(p));
    return a;
}

#define LDSM4(r0, r1, r2, r3, a) \
    asm volatile("ldmatrix.sync.aligned.m8n8.x4.shared.b16 {%0,%1,%2,%3}, [%4];" \
        : "=r"(r0), "=r"(r1), "=r"(r2), "=r"(r3) : "r"(a))
#define LDSM4T(r0, r1, r2, r3, a) \
    asm volatile("ldmatrix.sync.aligned.m8n8.x4.trans.shared.b16 {%0,%1,%2,%3}, [%4];" \
        : "=r"(r0), "=r"(r1), "=r"(r2), "=r"(r3) : "r"(a))

#define CP16(dst, src) \
    asm volatile("cp.async.cg.shared.global [%0], [%1], 16;" :: "r"(dst), "l"(src))
#define CP_COMMIT() asm volatile("cp.async.commit_group;" ::: "memory")
#define CP_WAIT1()  asm volatile("cp.async.wait_group 1;" ::: "memory")
#define CP_WAIT4()  asm volatile("cp.async.wait_group 4;" ::: "memory")

// fp16 MMA, fp32 accum: D(16x8) += A(16x16) @ B(16x8)
__device__ __forceinline__ void mma16(float* d, const uint32_t* a, const uint32_t* b) {
    asm volatile(
        "mma.sync.aligned.m16n8k16.row.col.f32.f16.f16.f32 "
        "{%0,%1,%2,%3}, {%4,%5,%6,%7}, {%8,%9}, {%0,%1,%2,%3};"
        : "+f"(d[0]), "+f"(d[1]), "+f"(d[2]), "+f"(d[3])
        : "r"(a[0]), "r"(a[1]), "r"(a[2]), "r"(a[3]), "r"(b[0]), "r"(b[1]));
}

// ---------------- LayerNorm: warp-per-row, MLP=8, f32 in fp16 out ----------------
__global__ void ln_kernel(const float* __restrict__ x,
                          const float* __restrict__ gamma,
                          const float* __restrict__ beta,
                          __half* __restrict__ y)
{
    const int lane = threadIdx.x & 31;
    const int wrp  = threadIdx.x >> 5;
    const int row  = blockIdx.x * 8 + wrp;

    const float4* xr = (const float4*)(x + (size_t)row * D_MODEL);
    float4 v[8];
    #pragma unroll
    for (int i = 0; i < 8; i++) v[i] = xr[lane + 32 * i];

    float s = 0.f, ss = 0.f;
    #pragma unroll
    for (int i = 0; i < 8; i++) {
        s  += v[i].x + v[i].y + v[i].z + v[i].w;
        ss += v[i].x*v[i].x + v[i].y*v[i].y + v[i].z*v[i].z + v[i].w*v[i].w;
    }
    #pragma unroll
    for (int off = 16; off; off >>= 1) {
        s  += __shfl_xor_sync(0xffffffffu, s,  off);
        ss += __shfl_xor_sync(0xffffffffu, ss, off);
    }
    const float mu   = s * (1.0f / D_MODEL);
    const float var  = ss * (1.0f / D_MODEL) - mu * mu;
    const float rstd = rsqrtf(var + 1e-5f);

    __half* yr = y + (size_t)row * D_MODEL;
    #pragma unroll
    for (int i = 0; i < 8; i++) {
        const int e = lane + 32 * i;
        const float4 g4 = ((const float4*)gamma)[e];
        const float4 b4 = ((const float4*)beta)[e];
        const float ox = (v[i].x - mu) * rstd * g4.x + b4.x;
        const float oy = (v[i].y - mu) * rstd * g4.y + b4.y;
        const float oz = (v[i].z - mu) * rstd * g4.z + b4.z;
        const float ow = (v[i].w - mu) * rstd * g4.w + b4.w;
        __half2 h0 = __floats2half2_rn(ox, oy);
        __half2 h1 = __floats2half2_rn(oz, ow);
        uint2 o; o.x = *(uint32_t*)&h0; o.y = *(uint32_t*)&h1;
        *(uint2*)(yr + e * 4) = o;
    }
}

// ---------------- weight convert: f32 -> f16, 4 float4/thread (MLP=4) ----------------
__global__ void convert_h(const float* __restrict__ in, __half* __restrict__ out)
{
    const size_t b0 = (size_t)blockIdx.x * 4096 + threadIdx.x * 4;
    float4 v[4];
    #pragma unroll
    for (int j = 0; j < 4; j++) v[j] = *(const float4*)(in + b0 + j * 1024);
    #pragma unroll
    for (int j = 0; j < 4; j++) {
        __half2 a = __floats2half2_rn(v[j].x, v[j].y);
        __half2 b = __floats2half2_rn(v[j].z, v[j].w);
        uint2 o; o.x = *(uint32_t*)&a; o.y = *(uint32_t*)&b;
        *(uint2*)(out + b0 + j * 1024) = o;
    }
}

// qkv merge-convert + bias concat
__global__ void convert_qkv(const float* __restrict__ Wq, const float* __restrict__ Wk,
                            const float* __restrict__ Wv, float* __restrict__ bqkv,
                            const float* __restrict__ bq, const float* __restrict__ bk,
                            const float* __restrict__ bv, __half* __restrict__ out)
{
    const int k0 = blockIdx.x * 2;            // grid 512
    const int c  = threadIdx.x;               // 0..255
    const float* srcs[3] = { Wq, Wk, Wv };
    float4 v[2][3];
    #pragma unroll
    for (int r = 0; r < 2; r++)
        #pragma unroll
        for (int j = 0; j < 3; j++)
            v[r][j] = ((const float4*)(srcs[j] + (size_t)(k0 + r) * D_MODEL))[c];
    #pragma unroll
    for (int r = 0; r < 2; r++)
        #pragma unroll
        for (int j = 0; j < 3; j++) {
            __half2 a = __floats2half2_rn(v[r][j].x, v[r][j].y);
            __half2 b = __floats2half2_rn(v[r][j].z, v[r][j].w);
            uint2 o; o.x = *(uint32_t*)&a; o.y = *(uint32_t*)&b;
            *(uint2*)(out + (size_t)(k0 + r) * 3 * D_MODEL + j * D_MODEL + c * 4) = o;
        }
    if (blockIdx.x < 3) {
        const float* src = (blockIdx.x == 0) ? bq : (blockIdx.x == 1) ? bk : bv;
        #pragma unroll
        for (int j = 0; j < 4; j++)
            bqkv[blockIdx.x * 1024 + threadIdx.x + j * 256] = src[threadIdx.x + j * 256];
    }
}

// ---------------- fp16 tensor-core GEMM, 2 CTAs/SM, 6-stage k32 pipeline (R10) ----------------
#define STG_BYTES 16384
#define GSM_TOTAL (6 * STG_BYTES)     /* 98304 */

template<bool RELU, bool RESID, bool HOUT>
__global__ __launch_bounds__(128, 2)
void gemm_h(const __half* __restrict__ Ah, const __half* __restrict__ Bh,
            const float* __restrict__ bias, const float* __restrict__ R,
            float* __restrict__ Cf, __half* __restrict__ Ch, int M, int N, int K)
{
    extern __shared__ char smem[];
    const uint32_t sb = smem_u32(smem);
    const int tid  = threadIdx.x;        // 0..127
    const int lane = tid & 31;
    const int wid  = tid >> 5;           // 0..3
    const int wm   = wid & 1;
    const int wn   = wid >> 1;           // 0..1

    const int m0 = blockIdx.y << 7;
    const int n0 = blockIdx.x << 7;

    const int rlA = lane & 15, clA = lane >> 4;
    const int kV = (lane & 7) + ((lane & 8) ? 8 : 0);
    const int cV = (lane >> 4) & 1;

    float acc[4][8][4];
    #pragma unroll
    for (int mi = 0; mi < 4; mi++)
        #pragma unroll
        for (int ni = 0; ni < 8; ni++)
            #pragma unroll
            for (int c = 0; c < 4; c++) acc[mi][ni][c] = 0.f;

    const int T = K >> 5;

    #define ISSUE_STAGE(s, buf) do { \
        const uint32_t b0_ = sb + (buf) * STG_BYTES; \
        _Pragma("unroll") \
        for (int j = 0; j < 4; j++) { \
            const int c_ = tid + j * 128, row_ = c_ >> 2, ch_ = c_ & 3; \
            CP16(b0_ + row_ * 64 + ((ch_ ^ ((row_ >> 1) & 3)) << 4), \
                 Ah + (size_t)(m0 + row_) * K + (s) * 32 + ch_ * 8); \
        } \
        _Pragma("unroll") \
        for (int j = 0; j < 4; j++) { \
            const int c_ = tid + j * 128, row_ = c_ >> 4, ch_ = c_ & 15; \
            const int ph_ = (ch_ & 8) | ((ch_ & 7) ^ (row_ & 7)); \
            CP16(b0_ + 8192 + row_ * 256 + (ph_ << 4), \
                 Bh + (size_t)((s) * 32 + row_) * N + n0 + ch_ * 8); \
        } \
    } while (0)

    #define LOAD_FRAGS(a_, b_, s_) do { \
        _Pragma("unroll") \
        for (int mi = 0; mi < 4; mi++) { \
            const int row = wm * 64 + mi * 16 + rlA; \
            LDSM4((a_)[mi][0], (a_)[mi][1], (a_)[mi][2], (a_)[mi][3], \
                  sA + row * 64 + (((2 * (s_) + clA) ^ ((row >> 1) & 3)) << 4)); \
        } \
        _Pragma("unroll") \
        for (int bb = 0; bb < 4; bb++) { \
            const int c = wn * 8 + 2 * bb + cV; \
            const int ph = (c & 8) | ((c & 7) ^ (kV & 7)); \
            LDSM4T((b_)[2*bb][0], (b_)[2*bb][1], (b_)[2*bb+1][0], (b_)[2*bb+1][1], \
                   sB + (16 * (s_) + kV) * 256 + (ph << 4)); \
        } \
    } while (0)

    #pragma unroll
    for (int i = 0; i < 5; i++) {
        if (i < T) ISSUE_STAGE(i, i);
        CP_COMMIT();
    }

    uint32_t af[2][4][4], bf[2][8][2];

    int cur = 0;
    for (int kt = 0; kt < T; kt++) {
        CP_WAIT4();
        __syncthreads();
        {
            int nb = cur + 5; if (nb >= 6) nb -= 6;
            if (kt + 5 < T) ISSUE_STAGE(kt + 5, nb);
            CP_COMMIT();
        }
        const uint32_t sA = sb + cur * STG_BYTES;
        const uint32_t sB = sA + 8192;

        LOAD_FRAGS(af[0], bf[0], 0);
        LOAD_FRAGS(af[1], bf[1], 1);
        #pragma unroll
        for (int s = 0; s < 2; s++) {
            #pragma unroll
            for (int mi = 0; mi < 4; mi++)
                #pragma unroll
                for (int ni = 0; ni < 8; ni++)
                    mma16(acc[mi][ni], af[s][mi], bf[s][ni]);
        }
        cur = (cur == 5) ? 0 : cur + 1;
    }
    #undef ISSUE_STAGE
    #undef LOAD_FRAGS

    // ---- epilogue ----
    const int g  = lane >> 2;
    const int t2 = lane & 3;
    #pragma unroll
    for (int ni = 0; ni < 8; ni++) {
        const int c = n0 + wn * 64 + ni * 8 + 2 * t2;
        const float2 bi = *(const float2*)&bias[c];
        #pragma unroll
        for (int mi = 0; mi < 4; mi++) {
            const int r0 = m0 + wm * 64 + mi * 16 + g;
            #pragma unroll
            for (int h = 0; h < 2; h++) {
                const int rr = r0 + h * 8;
                float vx = acc[mi][ni][2 * h]     + bi.x;
                float vy = acc[mi][ni][2 * h + 1] + bi.y;
                if (RELU) { vx = fmaxf(vx, 0.f); vy = fmaxf(vy, 0.f); }
                const size_t idx = (size_t)rr * N + c;
                if (RESID) {
                    const float2 rs = *(const float2*)&R[idx];
                    vx += rs.x; vy += rs.y;
                }
                if (HOUT) {
                    __half2 hv = __floats2half2_rn(vx, vy);
                    *(uint32_t*)&Ch[idx] = *(uint32_t*)&hv;
                } else {
                    float2 o; o.x = vx; o.y = vy;
                    *(float2*)&Cf[idx] = o;
                }
            }
        }
    }
}

// ---------------- fp16 flash attention, register-resident P, 2 CTAs/SM ----------------
#define ATT_STG  16384
#define ATT_SMEM (16384 + 3 * ATT_STG)   /* 65536 */

__global__ __launch_bounds__(256, 2)
void attn_h(const __half* __restrict__ Qg, const __half* __restrict__ Kg,
            const __half* __restrict__ Vg, __half* __restrict__ O, int ld)
{
    extern __shared__ char smem[];
    const uint32_t sb = smem_u32(smem);
    const int tid  = threadIdx.x;
    const int lane = tid & 31;
    const int wid  = tid >> 5;
    const int g    = lane >> 2;
    const int t    = lane & 3;
    const int swz  = lane & 7;

    const int bh = blockIdx.y;
    const int b  = bh >> 4;
    const int h  = bh & 15;
    const int q0 = blockIdx.x << 7;

    const size_t base  = (size_t)b * SEQ * ld + (size_t)h * DK;
    const size_t obase = (size_t)b * SEQ * D_MODEL + (size_t)h * DK;

    #pragma unroll
    for (int p = 0; p < 4; p++) {
        const int c = tid + p * 256, row = c >> 3, ch = c & 7;
        *(uint4*)(smem + row * 128 + ((ch ^ (row & 7)) << 4)) =
            *(const uint4*)(Qg + base + (size_t)(q0 + row) * ld + ch * 8);
    }
    __syncthreads();

    uint32_t aq[4][4];
    {
        const int rowA = wid * 16 + (lane & 15);
        const int clA  = lane >> 4;
        #pragma unroll
        for (int kb = 0; kb < 4; kb++)
            LDSM4(aq[kb][0], aq[kb][1], aq[kb][2], aq[kb][3],
                  sb + rowA * 128 + (((2 * kb + clA) ^ swz) << 4));
    }

    const int rlB = (lane & 7) + ((lane >> 4) << 3);
    const int clB = (lane >> 3) & 1;
    const int kV  = (lane & 7) + ((lane & 8) ? 8 : 0);
    const int cV  = (lane >> 4) & 1;

    float m0v = -1e30f, m1v = -1e30f, l0 = 0.f, l1 = 0.f;
    float oacc[8][4];
    #pragma unroll
    for (int ni = 0; ni < 8; ni++)
        #pragma unroll
        for (int c = 0; c < 4; c++) oacc[ni][c] = 0.f;

    #define ISSUE_KV(s, buf) do { \
        const uint32_t kb_ = sb + 16384 + (buf) * ATT_STG; \
        _Pragma("unroll") \
        for (int j = 0; j < 2; j++) { \
            const int c_ = tid + j * 256, row_ = c_ >> 3, ch_ = c_ & 7; \
            const uint32_t off_ = row_ * 128 + ((ch_ ^ (row_ & 7)) << 4); \
            const size_t gsrc = base + (size_t)((s) * 64 + row_) * ld + ch_ * 8; \
            CP16(kb_ + off_,        Kg + gsrc); \
            CP16(kb_ + 8192 + off_, Vg + gsrc); \
        } \
    } while (0)

    ISSUE_KV(0, 0); CP_COMMIT();
    ISSUE_KV(1, 1); CP_COMMIT();

    int cur = 0;
    const int T = SEQ / 64;
    for (int kt = 0; kt < T; kt++) {
        CP_WAIT1();
        __syncthreads();
        {
            int nb = cur + 2; if (nb >= 3) nb -= 3;
            if (kt + 2 < T) ISSUE_KV(kt + 2, nb);
            CP_COMMIT();
        }
        const uint32_t kbuf = sb + 16384 + cur * ATT_STG;
        const uint32_t vbuf = kbuf + 8192;

        float sacc[8][4];
        #pragma unroll
        for (int ni = 0; ni < 8; ni++)
            #pragma unroll
            for (int c = 0; c < 4; c++) sacc[ni][c] = 0.f;

        #pragma unroll
        for (int kb = 0; kb < 4; kb++) {
            uint32_t bf[8][2];
            #pragma unroll
            for (int a = 0; a < 4; a++) {
                const int row = 16 * a + rlB;
                LDSM4(bf[2*a][0], bf[2*a][1], bf[2*a+1][0], bf[2*a+1][1],
                      kbuf + row * 128 + (((2 * kb + clB) ^ swz) << 4));
            }
            #pragma unroll
            for (int ni = 0; ni < 8; ni++)
                mma16(sacc[ni], aq[kb], bf[ni]);
        }

        #pragma unroll
        for (int ni = 0; ni < 8; ni++) {
            sacc[ni][0] *= 0.125f; sacc[ni][1] *= 0.125f;
            sacc[ni][2] *= 0.125f; sacc[ni][3] *= 0.125f;
        }
        float mx0 = -1e30f, mx1 = -1e30f;
        #pragma unroll
        for (int ni = 0; ni < 8; ni++) {
            mx0 = fmaxf(mx0, fmaxf(sacc[ni][0], sacc[ni][1]));
            mx1 = fmaxf(mx1, fmaxf(sacc[ni][2], sacc[ni][3]));
        }
        mx0 = fmaxf(mx0, __shfl_xor_sync(0xffffffffu, mx0, 1));
        mx0 = fmaxf(mx0, __shfl_xor_sync(0xffffffffu, mx0, 2));
        mx1 = fmaxf(mx1, __shfl_xor_sync(0xffffffffu, mx1, 1));
        mx1 = fmaxf(mx1, __shfl_xor_sync(0xffffffffu, mx1, 2));

        const float mn0 = fmaxf(m0v, mx0);
        const float mn1 = fmaxf(m1v, mx1);
        const float al0 = __expf(m0v - mn0);
        const float al1 = __expf(m1v - mn1);
        m0v = mn0; m1v = mn1;

        uint32_t pa[8][2];
        float sum0 = 0.f, sum1 = 0.f;
        #pragma unroll
        for (int ni = 0; ni < 8; ni++) {
            const float p0 = __expf(sacc[ni][0] - mn0);
            const float p1 = __expf(sacc[ni][1] - mn0);
            const float p2 = __expf(sacc[ni][2] - mn1);
            const float p3 = __expf(sacc[ni][3] - mn1);
            sum0 += p0 + p1; sum1 += p2 + p3;
            __half2 h0 = __floats2half2_rn(p0, p1);
            __half2 h1 = __floats2half2_rn(p2, p3);
            pa[ni][0] = *(uint32_t*)&h0;
            pa[ni][1] = *(uint32_t*)&h1;
        }
        sum0 += __shfl_xor_sync(0xffffffffu, sum0, 1);
        sum0 += __shfl_xor_sync(0xffffffffu, sum0, 2);
        sum1 += __shfl_xor_sync(0xffffffffu, sum1, 1);
        sum1 += __shfl_xor_sync(0xffffffffu, sum1, 2);
        l0 = l0 * al0 + sum0;
        l1 = l1 * al1 + sum1;

        #pragma unroll
        for (int ni = 0; ni < 8; ni++) {
            oacc[ni][0] *= al0; oacc[ni][1] *= al0;
            oacc[ni][2] *= al1; oacc[ni][3] *= al1;
        }

        #pragma unroll
        for (int kk = 0; kk < 4; kk++) {
            uint32_t bv[8][2];
            #pragma unroll
            for (int bb = 0; bb < 4; bb++) {
                const int key = 16 * kk + kV;
                LDSM4T(bv[2*bb][0], bv[2*bb][1], bv[2*bb+1][0], bv[2*bb+1][1],
                       vbuf + key * 128 + (((2 * bb + cV) ^ swz) << 4));
            }
            uint32_t ap[4] = { pa[2*kk][0], pa[2*kk][1], pa[2*kk+1][0], pa[2*kk+1][1] };
            #pragma unroll
            for (int ni = 0; ni < 8; ni++)
                mma16(oacc[ni], ap, bv[ni]);
        }

        cur = (cur == 2) ? 0 : cur + 1;
    }
    #undef ISSUE_KV

    const float inv0 = 1.f / l0;
    const float inv1 = 1.f / l1;
    const size_t row0 = obase + (size_t)(q0 + wid * 16 + g) * D_MODEL;
    const size_t row1 = row0 + (size_t)8 * D_MODEL;
    #pragma unroll
    for (int ni = 0; ni < 8; ni++) {
        const int c = ni * 8 + 2 * t;
        __half2 h0 = __floats2half2_rn(oacc[ni][0] * inv0, oacc[ni][1] * inv0);
        __half2 h1 = __floats2half2_rn(oacc[ni][2] * inv1, oacc[ni][3] * inv1);
        *(uint32_t*)&O[row0 + c] = *(uint32_t*)&h0;
        *(uint32_t*)&O[row1 + c] = *(uint32_t*)&h1;
    }
}

// ---------------- launch ----------------
extern "C" void kernel_launch(void* const* d_in, const int* in_sizes, int n_in,
                              void* d_out, int out_size)
{
    const float* x    = (const float*)d_in[0];
    const float* ln1g = (const float*)d_in[1];
    const float* ln1b = (const float*)d_in[2];
    const float* ln2g = (const float*)d_in[3];
    const float* ln2b = (const float*)d_in[4];
    const float* Wq = (const float*)d_in[5];
    const float* bq = (const float*)d_in[6];
    const float* Wk = (const float*)d_in[7];
    const float* bk = (const float*)d_in[8];
    const float* Wv = (const float*)d_in[9];
    const float* bv = (const float*)d_in[10];
    const float* Wo = (const float*)d_in[11];
    const float* bo = (const float*)d_in[12];
    const float* W1 = (const float*)d_in[13];
    const float* b1 = (const float*)d_in[14];
    const float* W2 = (const float*)d_in[15];
    const float* b2 = (const float*)d_in[16];
    float* out = (float*)d_out;

    __half *xnh, *qkvh, *ctxh, *ffh, *wqkvh, *woh, *w1h, *w2h;
    float *x1, *bqkv;
    cudaGetSymbolAddress((void**)&xnh,   g_xnh);
    cudaGetSymbolAddress((void**)&qkvh,  g_qkvh);
    cudaGetSymbolAddress((void**)&ctxh,  g_ctxh);
    cudaGetSymbolAddress((void**)&x1,    g_x1);
    cudaGetSymbolAddress((void**)&ffh,   g_ffh);
    cudaGetSymbolAddress((void**)&wqkvh, g_wqkvh);
    cudaGetSymbolAddress((void**)&woh,   g_woh);
    cudaGetSymbolAddress((void**)&w1h,   g_w1h);
    cudaGetSymbolAddress((void**)&w2h,   g_w2h);
    cudaGetSymbolAddress((void**)&bqkv,  g_bqkv);

    cudaFuncSetAttribute(attn_h, cudaFuncAttributeMaxDynamicSharedMemorySize, ATT_SMEM);
    cudaFuncSetAttribute(gemm_h<false,false,true>,  cudaFuncAttributeMaxDynamicSharedMemorySize, GSM_TOTAL);
    cudaFuncSetAttribute(gemm_h<false,true,false>,  cudaFuncAttributeMaxDynamicSharedMemorySize, GSM_TOTAL);
    cudaFuncSetAttribute(gemm_h<true,false,true>,   cudaFuncAttributeMaxDynamicSharedMemorySize, GSM_TOTAL);

    // weight converts (f32 -> f16, layout preserved [K,N]) + fused bias concat
    convert_qkv<<<512, 256>>>(Wq, Wk, Wv, bqkv, bq, bk, bv, wqkvh);
    convert_h<<<(D_MODEL*D_MODEL)/4096, 256>>>(Wo, woh);
    convert_h<<<(D_MODEL*D_FF)/4096, 256>>>(W1, w1h);
    convert_h<<<(D_FF*D_MODEL)/4096, 256>>>(W2, w2h);

    // 1) xn = LN1(x)  (fp16 out)
    ln_kernel<<<NTOK/8, 256>>>(x, ln1g, ln1b, xnh);
    // 2) qkv = xn @ [Wq|Wk|Wv] + [bq|bk|bv]   (fused, N=3072, fp16 out)
    gemm_h<false,false,true><<<dim3(3*D_MODEL/128, NTOK/128), 128, GSM_TOTAL>>>(
        xnh, wqkvh, bqkv, nullptr, nullptr, qkvh, NTOK, 3*D_MODEL, D_MODEL);
    // 3) ctx = attention(q,k,v)  (fp16 in/out)
    attn_h<<<dim3(SEQ/128, BATCH*NHEAD), 256, ATT_SMEM>>>(
        qkvh, qkvh + D_MODEL, qkvh + 2*D_MODEL, ctxh, 3*D_MODEL);
    // 4) x1 = x + ctx @ Wo + bo  (f32 out)
    gemm_h<false,true,false><<<dim3(D_MODEL/128, NTOK/128), 128, GSM_TOTAL>>>(
        ctxh, woh, bo, x, x1, nullptr, NTOK, D_MODEL, D_MODEL);
    // 5) xn = LN2(x1)  (fp16 out)
    ln_kernel<<<NTOK/8, 256>>>(x1, ln2g, ln2b, xnh);
    // 6) ffh = relu(xn @ W1 + b1)  (fp16 out)
    gemm_h<true,false,true><<<dim3(D_FF/128, NTOK/128), 128, GSM_TOTAL>>>(
        xnh, w1h, b1, nullptr, nullptr, ffh, NTOK, D_FF, D_MODEL);
    // 7) out = x1 + ffh @ W2 + b2  (f32 out)
    gemm_h<false,true,false><<<dim3(D_MODEL/128, NTOK/128), 128, GSM_TOTAL>>>(
        ffh, w2h, b2, x1, out, nullptr, NTOK, D_MODEL, D_FF);
}